// round 1
// baseline (speedup 1.0000x reference)
#include <cuda_runtime.h>
#include <cuda_bf16.h>
#include <math.h>

// Problem constants
#define BB 2
#define SS 2048
#define EE 2048
#define HH 16
#define NOPE 128
#define ROPE_D 64
#define QHD 192          // NOPE + ROPE
#define LORA 512
#define VD 128
#define RWS (BB*SS)      // 4096 rows

// Scratch (device globals; no allocation allowed)
__device__ float g_q[(size_t)RWS * (HH * QHD)];        // 4096 x 3072
__device__ float g_kva[(size_t)RWS * (LORA + ROPE_D)]; // 4096 x 576
__device__ float g_ckv[(size_t)RWS * LORA];            // 4096 x 512
__device__ float g_kv[(size_t)RWS * (HH * (NOPE + VD))]; // 4096 x 4096
__device__ float g_ao[(size_t)RWS * (HH * VD)];        // 4096 x 2048

// ---------------------------------------------------------------------------
// Generic SGEMM: C[M,N] = A[M,K] @ B[K,N], row-major.
// 128x128 tile, BK=8, 256 threads, 8x8 per-thread microtile.
// Assumes: M % 128 == 0, K % 8 == 0, N % 4 == 0 (N guarded).
// ---------------------------------------------------------------------------
__global__ void __launch_bounds__(256) sgemm128(const float* __restrict__ A,
                                                const float* __restrict__ B,
                                                float* __restrict__ C,
                                                int M, int N, int K) {
    __shared__ float As[8][128];
    __shared__ float Bs[8][128];

    int tid = threadIdx.x;
    int bm = blockIdx.y * 128;
    int bn = blockIdx.x * 128;
    int tx = tid & 15;
    int ty = tid >> 4;

    int aRow  = bm + (tid >> 1);
    int aCol  = (tid & 1) * 4;
    int bColL = (tid & 31) * 4;
    int bRowL = tid >> 5;
    int bCol  = bn + bColL;

    float acc[8][8] = {};

    for (int k0 = 0; k0 < K; k0 += 8) {
        // Load A tile (transposed into smem)
        float4 av = *(const float4*)(A + (size_t)aRow * K + k0 + aCol);
        As[aCol + 0][tid >> 1] = av.x;
        As[aCol + 1][tid >> 1] = av.y;
        As[aCol + 2][tid >> 1] = av.z;
        As[aCol + 3][tid >> 1] = av.w;
        // Load B tile
        float4 bv = make_float4(0.f, 0.f, 0.f, 0.f);
        if (bCol < N)
            bv = *(const float4*)(B + (size_t)(k0 + bRowL) * N + bCol);
        *(float4*)&Bs[bRowL][bColL] = bv;
        __syncthreads();

        #pragma unroll
        for (int k = 0; k < 8; k++) {
            float af[8], bf[8];
            *(float4*)(af)     = *(const float4*)&As[k][ty * 8];
            *(float4*)(af + 4) = *(const float4*)&As[k][ty * 8 + 4];
            *(float4*)(bf)     = *(const float4*)&Bs[k][tx * 8];
            *(float4*)(bf + 4) = *(const float4*)&Bs[k][tx * 8 + 4];
            #pragma unroll
            for (int i = 0; i < 8; i++)
                #pragma unroll
                for (int j = 0; j < 8; j++)
                    acc[i][j] = fmaf(af[i], bf[j], acc[i][j]);
        }
        __syncthreads();
    }

    #pragma unroll
    for (int i = 0; i < 8; i++) {
        int row = bm + ty * 8 + i;
        #pragma unroll
        for (int j = 0; j < 8; j += 4) {
            int col = bn + tx * 8 + j;
            if (col < N) {
                *(float4*)(C + (size_t)row * N + col) =
                    make_float4(acc[i][j], acc[i][j+1], acc[i][j+2], acc[i][j+3]);
            }
        }
    }
}

// ---------------------------------------------------------------------------
// RMSNorm over first LORA cols of kva -> ckv, scaled by kv_norm_scale.
// One block (128 threads) per row.
// ---------------------------------------------------------------------------
__global__ void __launch_bounds__(128) rmsnorm_kernel(const float* __restrict__ kva,
                                                      const float* __restrict__ kvs,
                                                      float* __restrict__ ckv) {
    int r = blockIdx.x;
    int tid = threadIdx.x;
    const float* row = kva + (size_t)r * (LORA + ROPE_D);

    float x[4];
    float ss = 0.f;
    #pragma unroll
    for (int j = 0; j < 4; j++) {
        x[j] = row[tid + 128 * j];
        ss += x[j] * x[j];
    }
    #pragma unroll
    for (int o = 16; o > 0; o >>= 1)
        ss += __shfl_xor_sync(0xffffffffu, ss, o);

    __shared__ float wsum[4];
    if ((tid & 31) == 0) wsum[tid >> 5] = ss;
    __syncthreads();
    float tot = wsum[0] + wsum[1] + wsum[2] + wsum[3];
    float rms = rsqrtf(tot / (float)LORA + 1e-6f);

    float* orow = ckv + (size_t)r * LORA;
    #pragma unroll
    for (int j = 0; j < 4; j++) {
        int c = tid + 128 * j;
        orow[c] = x[j] * rms * kvs[c];
    }
}

// ---------------------------------------------------------------------------
// RoPE: apply to q_pe (16 heads) and k_pe (in kva), in place.
// grid = RWS blocks, block = (32, 17): y<16 -> q head y, y==16 -> k_pe.
// ---------------------------------------------------------------------------
__global__ void rope_kernel(float* __restrict__ q, float* __restrict__ kva) {
    int r = blockIdx.x;
    int s = r % SS;
    int i = threadIdx.x;        // 0..31
    int hy = threadIdx.y;       // 0..16

    float inv = powf(10000.f, -(float)i / 32.f);
    float ang = (float)s * inv;
    float sn, cs;
    sincosf(ang, &sn, &cs);

    float* base;
    if (hy < HH) {
        base = q + (size_t)r * (HH * QHD) + hy * QHD + NOPE;
    } else {
        base = kva + (size_t)r * (LORA + ROPE_D) + LORA;
    }
    float x1 = base[i];
    float x2 = base[i + 32];
    base[i]      = x1 * cs - x2 * sn;
    base[i + 32] = x2 * cs + x1 * sn;
}

// ---------------------------------------------------------------------------
// Flash attention (causal), fp32.
// BM=BN=64, 256 threads. Each thread: rows {rg, rg+32}, score cols part+8t,
// output cols part+8j (j<16). Online softmax.
// ---------------------------------------------------------------------------
#define FBM 64
#define FBN 64
#define KPAD 193
#define VPAD 129
#define SPAD 65
#define FSMEM ((2 * FBM * KPAD + FBN * VPAD + FBM * SPAD) * sizeof(float))

__global__ void __launch_bounds__(256) flash_kernel(const float* __restrict__ q,
                                                    const float* __restrict__ kv,
                                                    const float* __restrict__ kva,
                                                    float* __restrict__ ao) {
    extern __shared__ float sm[];
    float* sQ = sm;                       // FBM x KPAD
    float* sK = sQ + FBM * KPAD;          // FBN x KPAD
    float* sV = sK + FBN * KPAD;          // FBN x VPAD
    float* sS = sV + FBN * VPAD;          // FBM x SPAD

    int qt = blockIdx.x;
    int h  = blockIdx.y;
    int b  = blockIdx.z;
    int tid = threadIdx.x;
    int qbase = qt * FBM;

    // Load Q tile (nope + roped pe are contiguous 192 floats)
    for (int i = tid; i < FBM * QHD; i += 256) {
        int row = i / QHD, d = i % QHD;
        int r = b * SS + qbase + row;
        sQ[row * KPAD + d] = q[(size_t)r * (HH * QHD) + h * QHD + d];
    }

    int rg = tid >> 3;     // 0..31
    int part = tid & 7;    // 0..7

    const float NEG = -1e30f;
    float m0 = NEG, m1 = NEG, l0 = 0.f, l1 = 0.f;
    float acc0[16] = {}, acc1[16] = {};
    const float scale = 0.07216878364870323f;  // 192^-0.5

    __syncthreads();

    for (int kt = 0; kt <= qt; kt++) {
        int kbase = kt * FBN;
        // Load K tile: 128 nope from kv + 64 roped pe from kva
        for (int i = tid; i < FBN * QHD; i += 256) {
            int row = i / QHD, d = i % QHD;
            int r = b * SS + kbase + row;
            float val;
            if (d < NOPE)
                val = kv[(size_t)r * (HH * (NOPE + VD)) + h * (NOPE + VD) + d];
            else
                val = kva[(size_t)r * (LORA + ROPE_D) + LORA + (d - NOPE)];
            sK[row * KPAD + d] = val;
        }
        // Load V tile
        for (int i = tid; i < FBN * VD; i += 256) {
            int row = i / VD, c = i % VD;
            int r = b * SS + kbase + row;
            sV[row * VPAD + c] = kv[(size_t)r * (HH * (NOPE + VD)) + h * (NOPE + VD) + NOPE + c];
        }
        __syncthreads();

        // Scores
        float sc0[8] = {}, sc1[8] = {};
        const float* q0p = sQ + rg * KPAD;
        const float* q1p = sQ + (rg + 32) * KPAD;
        #pragma unroll 4
        for (int k = 0; k < QHD; k++) {
            float qv0 = q0p[k];
            float qv1 = q1p[k];
            #pragma unroll
            for (int t = 0; t < 8; t++) {
                float kvl = sK[(part + 8 * t) * KPAD + k];
                sc0[t] = fmaf(qv0, kvl, sc0[t]);
                sc1[t] = fmaf(qv1, kvl, sc1[t]);
            }
        }

        // Mask + scale, local max
        int q0g = qbase + rg;
        int q1g = qbase + rg + 32;
        float tm0 = NEG, tm1 = NEG;
        #pragma unroll
        for (int t = 0; t < 8; t++) {
            int kg = kbase + part + 8 * t;
            sc0[t] = (kg <= q0g) ? sc0[t] * scale : NEG;
            sc1[t] = (kg <= q1g) ? sc1[t] * scale : NEG;
            tm0 = fmaxf(tm0, sc0[t]);
            tm1 = fmaxf(tm1, sc1[t]);
        }
        // reduce over 8-lane row group
        #pragma unroll
        for (int o = 1; o < 8; o <<= 1) {
            tm0 = fmaxf(tm0, __shfl_xor_sync(0xffffffffu, tm0, o));
            tm1 = fmaxf(tm1, __shfl_xor_sync(0xffffffffu, tm1, o));
        }
        float mn0 = fmaxf(m0, tm0);
        float mn1 = fmaxf(m1, tm1);
        float c0 = __expf(m0 - mn0);
        float c1 = __expf(m1 - mn1);
        m0 = mn0; m1 = mn1;

        float rs0 = 0.f, rs1 = 0.f;
        #pragma unroll
        for (int t = 0; t < 8; t++) {
            float p0 = __expf(sc0[t] - mn0);
            float p1 = __expf(sc1[t] - mn1);
            rs0 += p0; rs1 += p1;
            sS[rg * SPAD + part + 8 * t] = p0;
            sS[(rg + 32) * SPAD + part + 8 * t] = p1;
        }
        #pragma unroll
        for (int o = 1; o < 8; o <<= 1) {
            rs0 += __shfl_xor_sync(0xffffffffu, rs0, o);
            rs1 += __shfl_xor_sync(0xffffffffu, rs1, o);
        }
        l0 = l0 * c0 + rs0;
        l1 = l1 * c1 + rs1;
        #pragma unroll
        for (int j = 0; j < 16; j++) { acc0[j] *= c0; acc1[j] *= c1; }

        __syncthreads();

        // PV
        #pragma unroll 2
        for (int kc = 0; kc < FBN; kc++) {
            float p0 = sS[rg * SPAD + kc];
            float p1 = sS[(rg + 32) * SPAD + kc];
            const float* vrow = sV + kc * VPAD;
            #pragma unroll
            for (int j = 0; j < 16; j++) {
                float vv = vrow[part + 8 * j];
                acc0[j] = fmaf(p0, vv, acc0[j]);
                acc1[j] = fmaf(p1, vv, acc1[j]);
            }
        }
        __syncthreads();
    }

    float inv0 = 1.f / l0;
    float inv1 = 1.f / l1;
    size_t orow0 = (size_t)(b * SS + qbase + rg) * (HH * VD) + h * VD;
    size_t orow1 = (size_t)(b * SS + qbase + rg + 32) * (HH * VD) + h * VD;
    #pragma unroll
    for (int j = 0; j < 16; j++) {
        int c = part + 8 * j;
        ao[orow0 + c] = acc0[j] * inv0;
        ao[orow1 + c] = acc1[j] * inv1;
    }
}

// ---------------------------------------------------------------------------
extern "C" void kernel_launch(void* const* d_in, const int* in_sizes, int n_in,
                              void* d_out, int out_size) {
    const float* x     = (const float*)d_in[0];
    const float* wq    = (const float*)d_in[1];
    const float* wkv_a = (const float*)d_in[2];
    const float* wkv_b = (const float*)d_in[3];
    const float* wo    = (const float*)d_in[4];
    const float* kvs   = (const float*)d_in[5];
    float* out = (float*)d_out;

    float *q, *kva, *ckv, *kv, *ao;
    cudaGetSymbolAddress((void**)&q,   g_q);
    cudaGetSymbolAddress((void**)&kva, g_kva);
    cudaGetSymbolAddress((void**)&ckv, g_ckv);
    cudaGetSymbolAddress((void**)&kv,  g_kv);
    cudaGetSymbolAddress((void**)&ao,  g_ao);

    static bool attr_done = false;
    if (!attr_done) {
        cudaFuncSetAttribute(flash_kernel,
                             cudaFuncAttributeMaxDynamicSharedMemorySize,
                             (int)FSMEM);
        attr_done = true;
    }

    // q = x @ wq : [4096, 3072]
    sgemm128<<<dim3(3072 / 128, RWS / 128), 256>>>(x, wq, q, RWS, HH * QHD, EE);
    // kva = x @ wkv_a : [4096, 576]
    sgemm128<<<dim3((LORA + ROPE_D + 127) / 128, RWS / 128), 256>>>(x, wkv_a, kva, RWS, LORA + ROPE_D, EE);
    // ckv = rmsnorm(kva[:, :512]) * kv_norm_scale
    rmsnorm_kernel<<<RWS, 128>>>(kva, kvs, ckv);
    // rope q_pe (in q) and k_pe (in kva), in place
    rope_kernel<<<RWS, dim3(32, 17)>>>(q, kva);
    // kv = ckv @ wkv_b : [4096, 4096]
    sgemm128<<<dim3((HH * (NOPE + VD)) / 128, RWS / 128), 256>>>(ckv, wkv_b, kv, RWS, HH * (NOPE + VD), LORA);
    // attention -> ao : [4096, 2048]
    flash_kernel<<<dim3(SS / FBM, HH, BB), 256, FSMEM>>>(q, kv, kva, ao);
    // out = ao @ wo : [4096, 2048]
    sgemm128<<<dim3(EE / 128, RWS / 128), 256>>>(ao, wo, out, RWS, EE, HH * VD);
}

// round 2
// speedup vs baseline: 1.3379x; 1.3379x over previous
#include <cuda_runtime.h>
#include <cuda_bf16.h>
#include <math.h>

// Problem constants
#define BB 2
#define SS 2048
#define EE 2048
#define HH 16
#define NOPE 128
#define ROPE_D 64
#define QHD 192          // NOPE + ROPE
#define LORA 512
#define VD 128
#define RWS (BB*SS)      // 4096 rows

// Scratch (device globals; no allocation allowed)
__device__ float g_q[(size_t)RWS * (HH * QHD)];
__device__ float g_kva[(size_t)RWS * (LORA + ROPE_D)];
__device__ float g_ckv[(size_t)RWS * LORA];
__device__ float g_kv[(size_t)RWS * (HH * (NOPE + VD))];
__device__ float g_ao[(size_t)RWS * (HH * VD)];

__device__ __forceinline__ unsigned f2tf(float x) {
    unsigned r; asm("cvt.rna.tf32.f32 %0, %1;" : "=r"(r) : "f"(x)); return r;
}
__device__ __forceinline__ void mma8(float* c, const unsigned* a, const unsigned* b) {
    asm volatile("mma.sync.aligned.m16n8k8.row.col.f32.tf32.tf32.f32 "
        "{%0,%1,%2,%3}, {%4,%5,%6,%7}, {%8,%9}, {%0,%1,%2,%3};"
        : "+f"(c[0]), "+f"(c[1]), "+f"(c[2]), "+f"(c[3])
        : "r"(a[0]), "r"(a[1]), "r"(a[2]), "r"(a[3]), "r"(b[0]), "r"(b[1]));
}

// ---------------------------------------------------------------------------
// TF32 tensor-core GEMM: C[M,N] = A[M,K] @ B[K,N], row-major fp32 in/out.
// 128x128 block tile, BK=32, 256 threads = 8 warps (2 M x 4 N), 64x32/warp.
// ---------------------------------------------------------------------------
#define ASTR 36
#define BSTR 136
__global__ void __launch_bounds__(256) gemm_tf32(const float* __restrict__ A,
                                                 const float* __restrict__ B,
                                                 float* __restrict__ C,
                                                 int M, int N, int K) {
    __shared__ unsigned As[128 * ASTR];
    __shared__ unsigned Bs[32 * BSTR];

    int tid = threadIdx.x;
    int bm = blockIdx.y * 128, bn = blockIdx.x * 128;
    int wid = tid >> 5, lane = tid & 31;
    int wm = (wid >> 2) * 64, wn = (wid & 3) * 32;
    int gr = lane >> 2, tg = lane & 3;

    float acc[4][4][4];
    #pragma unroll
    for (int i = 0; i < 4; i++)
        #pragma unroll
        for (int j = 0; j < 4; j++)
            #pragma unroll
            for (int t = 0; t < 4; t++) acc[i][j][t] = 0.f;

    for (int k0 = 0; k0 < K; k0 += 32) {
        #pragma unroll
        for (int p = 0; p < 4; p++) {
            int idx = tid + p * 256;
            int row = idx >> 3, kc = (idx & 7) * 4;
            float4 v = *(const float4*)(A + (size_t)(bm + row) * K + k0 + kc);
            uint4 t = make_uint4(f2tf(v.x), f2tf(v.y), f2tf(v.z), f2tf(v.w));
            *(uint4*)&As[row * ASTR + kc] = t;
        }
        #pragma unroll
        for (int p = 0; p < 4; p++) {
            int idx = tid + p * 256;
            int kr = idx >> 5, n = (idx & 31) * 4;
            float4 v = make_float4(0.f, 0.f, 0.f, 0.f);
            if (bn + n < N)
                v = *(const float4*)(B + (size_t)(k0 + kr) * N + bn + n);
            uint4 t = make_uint4(f2tf(v.x), f2tf(v.y), f2tf(v.z), f2tf(v.w));
            *(uint4*)&Bs[kr * BSTR + n] = t;
        }
        __syncthreads();

        #pragma unroll
        for (int ks = 0; ks < 4; ks++) {
            int kk = ks * 8;
            unsigned a[4][4], b[4][2];
            #pragma unroll
            for (int i = 0; i < 4; i++) {
                int m = wm + i * 16;
                a[i][0] = As[(m + gr) * ASTR + kk + tg];
                a[i][1] = As[(m + gr + 8) * ASTR + kk + tg];
                a[i][2] = As[(m + gr) * ASTR + kk + tg + 4];
                a[i][3] = As[(m + gr + 8) * ASTR + kk + tg + 4];
            }
            #pragma unroll
            for (int j = 0; j < 4; j++) {
                int n = wn + j * 8;
                b[j][0] = Bs[(kk + tg) * BSTR + n + gr];
                b[j][1] = Bs[(kk + tg + 4) * BSTR + n + gr];
            }
            #pragma unroll
            for (int i = 0; i < 4; i++)
                #pragma unroll
                for (int j = 0; j < 4; j++)
                    mma8(acc[i][j], a[i], b[j]);
        }
        __syncthreads();
    }

    #pragma unroll
    for (int i = 0; i < 4; i++) {
        int r0 = bm + wm + i * 16 + gr;
        #pragma unroll
        for (int j = 0; j < 4; j++) {
            int cc = bn + wn + j * 8 + 2 * tg;
            if (cc < N) {
                *(float2*)(C + (size_t)r0 * N + cc) =
                    make_float2(acc[i][j][0], acc[i][j][1]);
                *(float2*)(C + (size_t)(r0 + 8) * N + cc) =
                    make_float2(acc[i][j][2], acc[i][j][3]);
            }
        }
    }
}

// ---------------------------------------------------------------------------
// RMSNorm over first LORA cols of kva -> ckv, scaled by kv_norm_scale.
// ---------------------------------------------------------------------------
__global__ void __launch_bounds__(128) rmsnorm_kernel(const float* __restrict__ kva,
                                                      const float* __restrict__ kvs,
                                                      float* __restrict__ ckv) {
    int r = blockIdx.x;
    int tid = threadIdx.x;
    const float* row = kva + (size_t)r * (LORA + ROPE_D);

    float x[4];
    float ss = 0.f;
    #pragma unroll
    for (int j = 0; j < 4; j++) {
        x[j] = row[tid + 128 * j];
        ss += x[j] * x[j];
    }
    #pragma unroll
    for (int o = 16; o > 0; o >>= 1)
        ss += __shfl_xor_sync(0xffffffffu, ss, o);

    __shared__ float wsum[4];
    if ((tid & 31) == 0) wsum[tid >> 5] = ss;
    __syncthreads();
    float tot = wsum[0] + wsum[1] + wsum[2] + wsum[3];
    float rms = rsqrtf(tot / (float)LORA + 1e-6f);

    float* orow = ckv + (size_t)r * LORA;
    #pragma unroll
    for (int j = 0; j < 4; j++) {
        int c = tid + 128 * j;
        orow[c] = x[j] * rms * kvs[c];
    }
}

// ---------------------------------------------------------------------------
// RoPE: apply to q_pe (16 heads) and k_pe (in kva), in place.
// ---------------------------------------------------------------------------
__global__ void rope_kernel(float* __restrict__ q, float* __restrict__ kva) {
    int r = blockIdx.x;
    int s = r % SS;
    int i = threadIdx.x;        // 0..31
    int hy = threadIdx.y;       // 0..16

    float inv = powf(10000.f, -(float)i / 32.f);
    float ang = (float)s * inv;
    float sn, cs;
    sincosf(ang, &sn, &cs);

    float* base;
    if (hy < HH) {
        base = q + (size_t)r * (HH * QHD) + hy * QHD + NOPE;
    } else {
        base = kva + (size_t)r * (LORA + ROPE_D) + LORA;
    }
    float x1 = base[i];
    float x2 = base[i + 32];
    base[i]      = x1 * cs - x2 * sn;
    base[i + 32] = x2 * cs + x1 * sn;
}

// ---------------------------------------------------------------------------
// Flash attention (causal) on tensor cores, TF32.
// BM=BN=64, 128 threads = 4 warps; each warp owns 16 query rows.
// Scores (QK^T) and PV both via mma.m16n8k8; P staged through smem.
// ---------------------------------------------------------------------------
#define FBM 64
#define FBN 64
#define QSTR 196
#define KSTR 196
#define VSTR 136
#define SSTR 68
#define FWORDS (FBM*QSTR + FBN*KSTR + FBN*VSTR + FBM*SSTR)
#define FSMEM (FWORDS * 4)

__global__ void __launch_bounds__(128) flash_tf32(const float* __restrict__ q,
                                                  const float* __restrict__ kv,
                                                  const float* __restrict__ kva,
                                                  float* __restrict__ ao) {
    extern __shared__ unsigned sm[];
    unsigned* sQ = sm;
    unsigned* sK = sQ + FBM * QSTR;
    unsigned* sV = sK + FBN * KSTR;
    unsigned* sS = sV + FBN * VSTR;

    int qt = blockIdx.x, h = blockIdx.y, b = blockIdx.z;
    int tid = threadIdx.x, wid = tid >> 5, lane = tid & 31;
    int gr = lane >> 2, tg = lane & 3;
    int qbase = qt * FBM;
    int wrow = wid * 16;

    // Load Q tile (192 dims incl. roped pe), convert to tf32
    for (int i = tid; i < FBM * QHD; i += 128) {
        int row = i / QHD, d = i - row * QHD;
        int r = b * SS + qbase + row;
        sQ[row * QSTR + d] = f2tf(q[(size_t)r * (HH * QHD) + h * QHD + d]);
    }

    float o[16][4];
    #pragma unroll
    for (int n = 0; n < 16; n++)
        #pragma unroll
        for (int t = 0; t < 4; t++) o[n][t] = 0.f;
    float m0 = -1e30f, m1 = -1e30f, l0 = 0.f, l1 = 0.f;
    const float scale = 0.07216878364870323f;  // 192^-0.5

    for (int kt = 0; kt <= qt; kt++) {
        int kbase = kt * FBN;
        __syncthreads();
        // K tile: 128 nope (kv) + 64 roped pe (kva)
        for (int i = tid; i < FBN * QHD; i += 128) {
            int row = i / QHD, d = i - row * QHD;
            int r = b * SS + kbase + row;
            float v;
            if (d < NOPE)
                v = kv[(size_t)r * (HH * (NOPE + VD)) + h * (NOPE + VD) + d];
            else
                v = kva[(size_t)r * (LORA + ROPE_D) + LORA + d - NOPE];
            sK[row * KSTR + d] = f2tf(v);
        }
        // V tile
        for (int i = tid; i < FBN * VD; i += 128) {
            int row = i >> 7, c = i & 127;
            int r = b * SS + kbase + row;
            sV[row * VSTR + c] =
                f2tf(kv[(size_t)r * (HH * (NOPE + VD)) + h * (NOPE + VD) + NOPE + c]);
        }
        __syncthreads();

        // ---- scores: S = Q K^T (16 rows x 64 cols per warp) ----
        float sacc[8][4];
        #pragma unroll
        for (int j = 0; j < 8; j++)
            #pragma unroll
            for (int t = 0; t < 4; t++) sacc[j][t] = 0.f;

        #pragma unroll
        for (int ks = 0; ks < 24; ks++) {
            int kk = ks * 8;
            unsigned a[4];
            a[0] = sQ[(wrow + gr) * QSTR + kk + tg];
            a[1] = sQ[(wrow + gr + 8) * QSTR + kk + tg];
            a[2] = sQ[(wrow + gr) * QSTR + kk + tg + 4];
            a[3] = sQ[(wrow + gr + 8) * QSTR + kk + tg + 4];
            #pragma unroll
            for (int j = 0; j < 8; j++) {
                unsigned bb[2];
                bb[0] = sK[(j * 8 + gr) * KSTR + kk + tg];
                bb[1] = sK[(j * 8 + gr) * KSTR + kk + tg + 4];
                mma8(sacc[j], a, bb);
            }
        }

        // ---- scale + causal mask + online softmax ----
        int qr0 = qbase + wrow + gr;
        int qr1 = qr0 + 8;
        float mx0 = -1e30f, mx1 = -1e30f;
        #pragma unroll
        for (int j = 0; j < 8; j++) {
            int c0 = kbase + j * 8 + 2 * tg;
            sacc[j][0] = (c0     <= qr0) ? sacc[j][0] * scale : -1e30f;
            sacc[j][1] = (c0 + 1 <= qr0) ? sacc[j][1] * scale : -1e30f;
            sacc[j][2] = (c0     <= qr1) ? sacc[j][2] * scale : -1e30f;
            sacc[j][3] = (c0 + 1 <= qr1) ? sacc[j][3] * scale : -1e30f;
            mx0 = fmaxf(mx0, fmaxf(sacc[j][0], sacc[j][1]));
            mx1 = fmaxf(mx1, fmaxf(sacc[j][2], sacc[j][3]));
        }
        mx0 = fmaxf(mx0, __shfl_xor_sync(0xffffffffu, mx0, 1));
        mx0 = fmaxf(mx0, __shfl_xor_sync(0xffffffffu, mx0, 2));
        mx1 = fmaxf(mx1, __shfl_xor_sync(0xffffffffu, mx1, 1));
        mx1 = fmaxf(mx1, __shfl_xor_sync(0xffffffffu, mx1, 2));

        float mn0 = fmaxf(m0, mx0), mn1 = fmaxf(m1, mx1);
        float f0 = __expf(m0 - mn0), f1 = __expf(m1 - mn1);
        m0 = mn0; m1 = mn1;

        float s0 = 0.f, s1 = 0.f;
        #pragma unroll
        for (int j = 0; j < 8; j++) {
            float p0 = __expf(sacc[j][0] - mn0);
            float p1 = __expf(sacc[j][1] - mn0);
            float p2 = __expf(sacc[j][2] - mn1);
            float p3 = __expf(sacc[j][3] - mn1);
            s0 += p0 + p1; s1 += p2 + p3;
            int cc = j * 8 + 2 * tg;
            *(uint2*)&sS[(wrow + gr) * SSTR + cc]     = make_uint2(f2tf(p0), f2tf(p1));
            *(uint2*)&sS[(wrow + gr + 8) * SSTR + cc] = make_uint2(f2tf(p2), f2tf(p3));
        }
        s0 += __shfl_xor_sync(0xffffffffu, s0, 1);
        s0 += __shfl_xor_sync(0xffffffffu, s0, 2);
        s1 += __shfl_xor_sync(0xffffffffu, s1, 1);
        s1 += __shfl_xor_sync(0xffffffffu, s1, 2);
        l0 = l0 * f0 + s0;
        l1 = l1 * f1 + s1;

        #pragma unroll
        for (int n = 0; n < 16; n++) {
            o[n][0] *= f0; o[n][1] *= f0; o[n][2] *= f1; o[n][3] *= f1;
        }
        __syncwarp();

        // ---- PV: O += P V (16 rows x 128 cols per warp) ----
        #pragma unroll
        for (int ks = 0; ks < 8; ks++) {
            int kk = ks * 8;
            unsigned a[4];
            a[0] = sS[(wrow + gr) * SSTR + kk + tg];
            a[1] = sS[(wrow + gr + 8) * SSTR + kk + tg];
            a[2] = sS[(wrow + gr) * SSTR + kk + tg + 4];
            a[3] = sS[(wrow + gr + 8) * SSTR + kk + tg + 4];
            #pragma unroll
            for (int n = 0; n < 16; n++) {
                unsigned bb[2];
                bb[0] = sV[(kk + tg) * VSTR + n * 8 + gr];
                bb[1] = sV[(kk + tg + 4) * VSTR + n * 8 + gr];
                mma8(o[n], a, bb);
            }
        }
        __syncwarp();
    }

    // epilogue
    float inv0 = 1.f / l0, inv1 = 1.f / l1;
    size_t r0 = (size_t)(b * SS + qbase + wrow + gr) * (HH * VD);
    size_t r1 = r0 + 8 * (HH * VD);
    #pragma unroll
    for (int n = 0; n < 16; n++) {
        int cc = h * VD + n * 8 + 2 * tg;
        *(float2*)(ao + r0 + cc) = make_float2(o[n][0] * inv0, o[n][1] * inv0);
        *(float2*)(ao + r1 + cc) = make_float2(o[n][2] * inv1, o[n][3] * inv1);
    }
}

// ---------------------------------------------------------------------------
extern "C" void kernel_launch(void* const* d_in, const int* in_sizes, int n_in,
                              void* d_out, int out_size) {
    const float* x     = (const float*)d_in[0];
    const float* wq    = (const float*)d_in[1];
    const float* wkv_a = (const float*)d_in[2];
    const float* wkv_b = (const float*)d_in[3];
    const float* wo    = (const float*)d_in[4];
    const float* kvs   = (const float*)d_in[5];
    float* out = (float*)d_out;

    float *q, *kva, *ckv, *kv, *ao;
    cudaGetSymbolAddress((void**)&q,   g_q);
    cudaGetSymbolAddress((void**)&kva, g_kva);
    cudaGetSymbolAddress((void**)&ckv, g_ckv);
    cudaGetSymbolAddress((void**)&kv,  g_kv);
    cudaGetSymbolAddress((void**)&ao,  g_ao);

    static bool attr_done = false;
    if (!attr_done) {
        cudaFuncSetAttribute(flash_tf32,
                             cudaFuncAttributeMaxDynamicSharedMemorySize,
                             (int)FSMEM);
        attr_done = true;
    }

    // q = x @ wq : [4096, 3072]
    gemm_tf32<<<dim3(3072 / 128, RWS / 128), 256>>>(x, wq, q, RWS, HH * QHD, EE);
    // kva = x @ wkv_a : [4096, 576]
    gemm_tf32<<<dim3((LORA + ROPE_D + 127) / 128, RWS / 128), 256>>>(x, wkv_a, kva, RWS, LORA + ROPE_D, EE);
    // ckv = rmsnorm(kva[:, :512]) * kv_norm_scale
    rmsnorm_kernel<<<RWS, 128>>>(kva, kvs, ckv);
    // rope q_pe (in q) and k_pe (in kva), in place
    rope_kernel<<<RWS, dim3(32, 17)>>>(q, kva);
    // kv = ckv @ wkv_b : [4096, 4096]
    gemm_tf32<<<dim3((HH * (NOPE + VD)) / 128, RWS / 128), 256>>>(ckv, wkv_b, kv, RWS, HH * (NOPE + VD), LORA);
    // attention -> ao : [4096, 2048]
    flash_tf32<<<dim3(SS / FBM, HH, BB), 128, FSMEM>>>(q, kv, kva, ao);
    // out = ao @ wo : [4096, 2048]
    gemm_tf32<<<dim3(EE / 128, RWS / 128), 256>>>(ao, wo, out, RWS, EE, HH * VD);
}

// round 3
// speedup vs baseline: 4.4206x; 3.3042x over previous
#include <cuda_runtime.h>
#include <cuda_bf16.h>
#include <math.h>

// Problem constants
#define BB 2
#define SS 2048
#define EE 2048
#define HH 16
#define NOPE 128
#define ROPE_D 64
#define QHD 192          // NOPE + ROPE
#define LORA 512
#define VD 128
#define RWS (BB*SS)      // 4096 rows

// Scratch (device globals; no allocation allowed)
__device__ float g_q[(size_t)RWS * (HH * QHD)];
__device__ float g_kva[(size_t)RWS * (LORA + ROPE_D)];
__device__ float g_ckv[(size_t)RWS * LORA];
__device__ float g_kv[(size_t)RWS * (HH * (NOPE + VD))];
__device__ float g_ao[(size_t)RWS * (HH * VD)];

__device__ __forceinline__ unsigned f2tf(float x) {
    unsigned r; asm("cvt.rna.tf32.f32 %0, %1;" : "=r"(r) : "f"(x)); return r;
}
__device__ __forceinline__ void mma8(float* c, const unsigned* a, const unsigned* b) {
    asm volatile("mma.sync.aligned.m16n8k8.row.col.f32.tf32.tf32.f32 "
        "{%0,%1,%2,%3}, {%4,%5,%6,%7}, {%8,%9}, {%0,%1,%2,%3};"
        : "+f"(c[0]), "+f"(c[1]), "+f"(c[2]), "+f"(c[3])
        : "r"(a[0]), "r"(a[1]), "r"(a[2]), "r"(a[3]), "r"(b[0]), "r"(b[1]));
}

// ---------------------------------------------------------------------------
// TF32 tensor-core GEMM, double-buffered smem + register prefetch.
// C[M,N] = A[M,K] @ B[K,N] row-major. 128x128 tile, BK=32, 256 thr, 8 warps.
// ---------------------------------------------------------------------------
#define ASTR 36
#define BSTR 136
#define GSMEM ((2*128*ASTR + 2*32*BSTR) * 4)

__global__ void __launch_bounds__(256) gemm_tf32(const float* __restrict__ A,
                                                 const float* __restrict__ B,
                                                 float* __restrict__ C,
                                                 int M, int N, int K) {
    extern __shared__ unsigned sg[];
    unsigned* As = sg;                  // [2][128*ASTR]
    unsigned* Bs = sg + 2 * 128 * ASTR; // [2][32*BSTR]

    int tid = threadIdx.x;
    int bm = blockIdx.y * 128, bn = blockIdx.x * 128;
    int wid = tid >> 5, lane = tid & 31;
    int wm = (wid >> 2) * 64, wn = (wid & 3) * 32;
    int gr = lane >> 2, tg = lane & 3;

    int aRow = tid >> 3;           // +32p
    int aCol = (tid & 7) * 4;
    int bRow = tid >> 5;           // +8p
    int bCol = (tid & 31) * 4;
    bool bok = (bn + bCol) < N;

    float acc[4][4][4];
    #pragma unroll
    for (int i = 0; i < 4; i++)
        #pragma unroll
        for (int j = 0; j < 4; j++)
            #pragma unroll
            for (int t = 0; t < 4; t++) acc[i][j][t] = 0.f;

    float4 ar[4], br[4];
    // preload tile 0 into regs
    #pragma unroll
    for (int p = 0; p < 4; p++) {
        ar[p] = *(const float4*)(A + (size_t)(bm + aRow + 32 * p) * K + aCol);
        br[p] = bok ? *(const float4*)(B + (size_t)(bRow + 8 * p) * N + bn + bCol)
                    : make_float4(0.f, 0.f, 0.f, 0.f);
    }
    // store tile 0 to buf 0
    #pragma unroll
    for (int p = 0; p < 4; p++) {
        *(uint4*)&As[(aRow + 32 * p) * ASTR + aCol] =
            make_uint4(f2tf(ar[p].x), f2tf(ar[p].y), f2tf(ar[p].z), f2tf(ar[p].w));
        *(uint4*)&Bs[(bRow + 8 * p) * BSTR + bCol] =
            make_uint4(f2tf(br[p].x), f2tf(br[p].y), f2tf(br[p].z), f2tf(br[p].w));
    }
    __syncthreads();

    int nkb = K >> 5;
    for (int kb = 0; kb < nkb; kb++) {
        int buf = kb & 1;
        unsigned* Asb = As + buf * (128 * ASTR);
        unsigned* Bsb = Bs + buf * (32 * BSTR);
        bool more = (kb + 1) < nkb;

        // issue next tile's global loads (latency hides under MMAs below)
        if (more) {
            int k0 = (kb + 1) * 32;
            #pragma unroll
            for (int p = 0; p < 4; p++) {
                ar[p] = *(const float4*)(A + (size_t)(bm + aRow + 32 * p) * K + k0 + aCol);
                br[p] = bok ? *(const float4*)(B + (size_t)(k0 + bRow + 8 * p) * N + bn + bCol)
                            : make_float4(0.f, 0.f, 0.f, 0.f);
            }
        }

        #pragma unroll
        for (int ks = 0; ks < 4; ks++) {
            int kk = ks * 8;
            unsigned a[4][4], b[4][2];
            #pragma unroll
            for (int i = 0; i < 4; i++) {
                int m = wm + i * 16;
                a[i][0] = Asb[(m + gr) * ASTR + kk + tg];
                a[i][1] = Asb[(m + gr + 8) * ASTR + kk + tg];
                a[i][2] = Asb[(m + gr) * ASTR + kk + tg + 4];
                a[i][3] = Asb[(m + gr + 8) * ASTR + kk + tg + 4];
            }
            #pragma unroll
            for (int j = 0; j < 4; j++) {
                int n = wn + j * 8;
                b[j][0] = Bsb[(kk + tg) * BSTR + n + gr];
                b[j][1] = Bsb[(kk + tg + 4) * BSTR + n + gr];
            }
            #pragma unroll
            for (int i = 0; i < 4; i++)
                #pragma unroll
                for (int j = 0; j < 4; j++)
                    mma8(acc[i][j], a[i], b[j]);
        }

        if (more) {
            unsigned* Asn = As + (buf ^ 1) * (128 * ASTR);
            unsigned* Bsn = Bs + (buf ^ 1) * (32 * BSTR);
            #pragma unroll
            for (int p = 0; p < 4; p++) {
                *(uint4*)&Asn[(aRow + 32 * p) * ASTR + aCol] =
                    make_uint4(f2tf(ar[p].x), f2tf(ar[p].y), f2tf(ar[p].z), f2tf(ar[p].w));
                *(uint4*)&Bsn[(bRow + 8 * p) * BSTR + bCol] =
                    make_uint4(f2tf(br[p].x), f2tf(br[p].y), f2tf(br[p].z), f2tf(br[p].w));
            }
        }
        __syncthreads();
    }

    #pragma unroll
    for (int i = 0; i < 4; i++) {
        int r0 = bm + wm + i * 16 + gr;
        #pragma unroll
        for (int j = 0; j < 4; j++) {
            int cc = bn + wn + j * 8 + 2 * tg;
            if (cc < N) {
                *(float2*)(C + (size_t)r0 * N + cc) =
                    make_float2(acc[i][j][0], acc[i][j][1]);
                *(float2*)(C + (size_t)(r0 + 8) * N + cc) =
                    make_float2(acc[i][j][2], acc[i][j][3]);
            }
        }
    }
}

// ---------------------------------------------------------------------------
// RMSNorm over first LORA cols of kva -> ckv, scaled by kv_norm_scale.
// ---------------------------------------------------------------------------
__global__ void __launch_bounds__(128) rmsnorm_kernel(const float* __restrict__ kva,
                                                      const float* __restrict__ kvs,
                                                      float* __restrict__ ckv) {
    int r = blockIdx.x;
    int tid = threadIdx.x;
    const float* row = kva + (size_t)r * (LORA + ROPE_D);

    float x[4];
    float ss = 0.f;
    #pragma unroll
    for (int j = 0; j < 4; j++) {
        x[j] = row[tid + 128 * j];
        ss += x[j] * x[j];
    }
    #pragma unroll
    for (int o = 16; o > 0; o >>= 1)
        ss += __shfl_xor_sync(0xffffffffu, ss, o);

    __shared__ float wsum[4];
    if ((tid & 31) == 0) wsum[tid >> 5] = ss;
    __syncthreads();
    float tot = wsum[0] + wsum[1] + wsum[2] + wsum[3];
    float rms = rsqrtf(tot / (float)LORA + 1e-6f);

    float* orow = ckv + (size_t)r * LORA;
    #pragma unroll
    for (int j = 0; j < 4; j++) {
        int c = tid + 128 * j;
        orow[c] = x[j] * rms * kvs[c];
    }
}

// ---------------------------------------------------------------------------
// RoPE: apply to q_pe (16 heads) and k_pe (in kva), in place.
// ---------------------------------------------------------------------------
__global__ void rope_kernel(float* __restrict__ q, float* __restrict__ kva) {
    int r = blockIdx.x;
    int s = r % SS;
    int i = threadIdx.x;        // 0..31
    int hy = threadIdx.y;       // 0..16

    float inv = powf(10000.f, -(float)i / 32.f);
    float ang = (float)s * inv;
    float sn, cs;
    sincosf(ang, &sn, &cs);

    float* base;
    if (hy < HH) {
        base = q + (size_t)r * (HH * QHD) + hy * QHD + NOPE;
    } else {
        base = kva + (size_t)r * (LORA + ROPE_D) + LORA;
    }
    float x1 = base[i];
    float x2 = base[i + 32];
    base[i]      = x1 * cs - x2 * sn;
    base[i + 32] = x2 * cs + x1 * sn;
}

// ---------------------------------------------------------------------------
// Flash attention (causal) on tensor cores, TF32.
// BM=128, BN=64, 256 threads = 8 warps; each warp owns 16 query rows.
// ---------------------------------------------------------------------------
#define FBM 128
#define FBN 64
#define QSTR 196
#define KSTR 196
#define VSTR 136
#define SSTR 68
#define FSMEM ((FBM*QSTR + FBN*KSTR + FBN*VSTR + FBM*SSTR) * 4)

__global__ void __launch_bounds__(256) flash_tf32(const float* __restrict__ q,
                                                  const float* __restrict__ kv,
                                                  const float* __restrict__ kva,
                                                  float* __restrict__ ao) {
    extern __shared__ unsigned sm[];
    unsigned* sQ = sm;
    unsigned* sK = sQ + FBM * QSTR;
    unsigned* sV = sK + FBN * KSTR;
    unsigned* sS = sV + FBN * VSTR;

    int qt = blockIdx.x, h = blockIdx.y, b = blockIdx.z;
    int tid = threadIdx.x, wid = tid >> 5, lane = tid & 31;
    int gr = lane >> 2, tg = lane & 3;
    int qbase = qt * FBM;
    int wrow = wid * 16;

    // Load Q tile (vectorized), convert to tf32
    for (int i = tid; i < FBM * 48; i += 256) {
        int row = i / 48, d = (i - row * 48) * 4;
        int r = b * SS + qbase + row;
        float4 v = *(const float4*)(q + (size_t)r * (HH * QHD) + h * QHD + d);
        *(uint4*)&sQ[row * QSTR + d] =
            make_uint4(f2tf(v.x), f2tf(v.y), f2tf(v.z), f2tf(v.w));
    }

    float o[16][4];
    #pragma unroll
    for (int n = 0; n < 16; n++)
        #pragma unroll
        for (int t = 0; t < 4; t++) o[n][t] = 0.f;
    float m0 = -1e30f, m1 = -1e30f, l0 = 0.f, l1 = 0.f;
    const float scale = 0.07216878364870323f;  // 192^-0.5

    int ktmax = (qbase + FBM) / FBN;
    for (int kt = 0; kt < ktmax; kt++) {
        int kbase = kt * FBN;
        __syncthreads();
        // K tile: 128 nope (kv) + 64 roped pe (kva), vectorized
        for (int i = tid; i < FBN * 48; i += 256) {
            int row = i / 48, d = (i - row * 48) * 4;
            int r = b * SS + kbase + row;
            float4 v;
            if (d < NOPE)
                v = *(const float4*)(kv + (size_t)r * (HH * (NOPE + VD)) + h * (NOPE + VD) + d);
            else
                v = *(const float4*)(kva + (size_t)r * (LORA + ROPE_D) + LORA + d - NOPE);
            *(uint4*)&sK[row * KSTR + d] =
                make_uint4(f2tf(v.x), f2tf(v.y), f2tf(v.z), f2tf(v.w));
        }
        // V tile, vectorized
        for (int i = tid; i < FBN * 32; i += 256) {
            int row = i >> 5, d = (i & 31) * 4;
            int r = b * SS + kbase + row;
            float4 v = *(const float4*)(kv + (size_t)r * (HH * (NOPE + VD)) + h * (NOPE + VD) + NOPE + d);
            *(uint4*)&sV[row * VSTR + d] =
                make_uint4(f2tf(v.x), f2tf(v.y), f2tf(v.z), f2tf(v.w));
        }
        __syncthreads();

        // ---- scores: S = Q K^T (16 rows x 64 cols per warp) ----
        float sacc[8][4];
        #pragma unroll
        for (int j = 0; j < 8; j++)
            #pragma unroll
            for (int t = 0; t < 4; t++) sacc[j][t] = 0.f;

        #pragma unroll
        for (int ks = 0; ks < 24; ks++) {
            int kk = ks * 8;
            unsigned a[4];
            a[0] = sQ[(wrow + gr) * QSTR + kk + tg];
            a[1] = sQ[(wrow + gr + 8) * QSTR + kk + tg];
            a[2] = sQ[(wrow + gr) * QSTR + kk + tg + 4];
            a[3] = sQ[(wrow + gr + 8) * QSTR + kk + tg + 4];
            #pragma unroll
            for (int j = 0; j < 8; j++) {
                unsigned bb[2];
                bb[0] = sK[(j * 8 + gr) * KSTR + kk + tg];
                bb[1] = sK[(j * 8 + gr) * KSTR + kk + tg + 4];
                mma8(sacc[j], a, bb);
            }
        }

        // ---- scale + causal mask + online softmax ----
        int qr0 = qbase + wrow + gr;
        int qr1 = qr0 + 8;
        float mx0 = -1e30f, mx1 = -1e30f;
        #pragma unroll
        for (int j = 0; j < 8; j++) {
            int c0 = kbase + j * 8 + 2 * tg;
            sacc[j][0] = (c0     <= qr0) ? sacc[j][0] * scale : -1e30f;
            sacc[j][1] = (c0 + 1 <= qr0) ? sacc[j][1] * scale : -1e30f;
            sacc[j][2] = (c0     <= qr1) ? sacc[j][2] * scale : -1e30f;
            sacc[j][3] = (c0 + 1 <= qr1) ? sacc[j][3] * scale : -1e30f;
            mx0 = fmaxf(mx0, fmaxf(sacc[j][0], sacc[j][1]));
            mx1 = fmaxf(mx1, fmaxf(sacc[j][2], sacc[j][3]));
        }
        mx0 = fmaxf(mx0, __shfl_xor_sync(0xffffffffu, mx0, 1));
        mx0 = fmaxf(mx0, __shfl_xor_sync(0xffffffffu, mx0, 2));
        mx1 = fmaxf(mx1, __shfl_xor_sync(0xffffffffu, mx1, 1));
        mx1 = fmaxf(mx1, __shfl_xor_sync(0xffffffffu, mx1, 2));

        float mn0 = fmaxf(m0, mx0), mn1 = fmaxf(m1, mx1);
        float f0 = __expf(m0 - mn0), f1 = __expf(m1 - mn1);
        m0 = mn0; m1 = mn1;

        float s0 = 0.f, s1 = 0.f;
        #pragma unroll
        for (int j = 0; j < 8; j++) {
            float p0 = __expf(sacc[j][0] - mn0);
            float p1 = __expf(sacc[j][1] - mn0);
            float p2 = __expf(sacc[j][2] - mn1);
            float p3 = __expf(sacc[j][3] - mn1);
            s0 += p0 + p1; s1 += p2 + p3;
            int cc = j * 8 + 2 * tg;
            *(uint2*)&sS[(wrow + gr) * SSTR + cc]     = make_uint2(f2tf(p0), f2tf(p1));
            *(uint2*)&sS[(wrow + gr + 8) * SSTR + cc] = make_uint2(f2tf(p2), f2tf(p3));
        }
        s0 += __shfl_xor_sync(0xffffffffu, s0, 1);
        s0 += __shfl_xor_sync(0xffffffffu, s0, 2);
        s1 += __shfl_xor_sync(0xffffffffu, s1, 1);
        s1 += __shfl_xor_sync(0xffffffffu, s1, 2);
        l0 = l0 * f0 + s0;
        l1 = l1 * f1 + s1;

        #pragma unroll
        for (int n = 0; n < 16; n++) {
            o[n][0] *= f0; o[n][1] *= f0; o[n][2] *= f1; o[n][3] *= f1;
        }
        __syncwarp();

        // ---- PV: O += P V (16 rows x 128 cols per warp) ----
        #pragma unroll
        for (int ks = 0; ks < 8; ks++) {
            int kk = ks * 8;
            unsigned a[4];
            a[0] = sS[(wrow + gr) * SSTR + kk + tg];
            a[1] = sS[(wrow + gr + 8) * SSTR + kk + tg];
            a[2] = sS[(wrow + gr) * SSTR + kk + tg + 4];
            a[3] = sS[(wrow + gr + 8) * SSTR + kk + tg + 4];
            #pragma unroll
            for (int n = 0; n < 16; n++) {
                unsigned bb[2];
                bb[0] = sV[(kk + tg) * VSTR + n * 8 + gr];
                bb[1] = sV[(kk + tg + 4) * VSTR + n * 8 + gr];
                mma8(o[n], a, bb);
            }
        }
        __syncwarp();
    }

    // epilogue
    float inv0 = 1.f / l0, inv1 = 1.f / l1;
    size_t r0 = (size_t)(b * SS + qbase + wrow + gr) * (HH * VD);
    size_t r1 = r0 + 8 * (HH * VD);
    #pragma unroll
    for (int n = 0; n < 16; n++) {
        int cc = h * VD + n * 8 + 2 * tg;
        *(float2*)(ao + r0 + cc) = make_float2(o[n][0] * inv0, o[n][1] * inv0);
        *(float2*)(ao + r1 + cc) = make_float2(o[n][2] * inv1, o[n][3] * inv1);
    }
}

// ---------------------------------------------------------------------------
extern "C" void kernel_launch(void* const* d_in, const int* in_sizes, int n_in,
                              void* d_out, int out_size) {
    const float* x     = (const float*)d_in[0];
    const float* wq    = (const float*)d_in[1];
    const float* wkv_a = (const float*)d_in[2];
    const float* wkv_b = (const float*)d_in[3];
    const float* wo    = (const float*)d_in[4];
    const float* kvs   = (const float*)d_in[5];
    float* out = (float*)d_out;

    float *q, *kva, *ckv, *kv, *ao;
    cudaGetSymbolAddress((void**)&q,   g_q);
    cudaGetSymbolAddress((void**)&kva, g_kva);
    cudaGetSymbolAddress((void**)&ckv, g_ckv);
    cudaGetSymbolAddress((void**)&kv,  g_kv);
    cudaGetSymbolAddress((void**)&ao,  g_ao);

    static bool attr_done = false;
    if (!attr_done) {
        cudaFuncSetAttribute(flash_tf32,
                             cudaFuncAttributeMaxDynamicSharedMemorySize,
                             (int)FSMEM);
        cudaFuncSetAttribute(gemm_tf32,
                             cudaFuncAttributeMaxDynamicSharedMemorySize,
                             (int)GSMEM);
        attr_done = true;
    }

    // q = x @ wq : [4096, 3072]
    gemm_tf32<<<dim3(3072 / 128, RWS / 128), 256, GSMEM>>>(x, wq, q, RWS, HH * QHD, EE);
    // kva = x @ wkv_a : [4096, 576]
    gemm_tf32<<<dim3((LORA + ROPE_D + 127) / 128, RWS / 128), 256, GSMEM>>>(x, wkv_a, kva, RWS, LORA + ROPE_D, EE);
    // ckv = rmsnorm(kva[:, :512]) * kv_norm_scale
    rmsnorm_kernel<<<RWS, 128>>>(kva, kvs, ckv);
    // rope q_pe (in q) and k_pe (in kva), in place
    rope_kernel<<<RWS, dim3(32, 17)>>>(q, kva);
    // kv = ckv @ wkv_b : [4096, 4096]
    gemm_tf32<<<dim3((HH * (NOPE + VD)) / 128, RWS / 128), 256, GSMEM>>>(ckv, wkv_b, kv, RWS, HH * (NOPE + VD), LORA);
    // attention -> ao : [4096, 2048]
    flash_tf32<<<dim3(SS / FBM, HH, BB), 256, FSMEM>>>(q, kv, kva, ao);
    // out = ao @ wo : [4096, 2048]
    gemm_tf32<<<dim3(EE / 128, RWS / 128), 256, GSMEM>>>(ao, wo, out, RWS, EE, HH * VD);
}

// round 4
// speedup vs baseline: 4.7906x; 1.0837x over previous
#include <cuda_runtime.h>
#include <cuda_bf16.h>
#include <math.h>

// Problem constants
#define BB 2
#define SS 2048
#define EE 2048
#define HH 16
#define NOPE 128
#define ROPE_D 64
#define QHD 192          // NOPE + ROPE
#define LORA 512
#define VD 128
#define RWS (BB*SS)      // 4096 rows

// Scratch (device globals; no allocation allowed)
__device__ float g_q[(size_t)RWS * (HH * QHD)];
__device__ float g_kva[(size_t)RWS * (LORA + ROPE_D)];
__device__ float g_ckv[(size_t)RWS * LORA];
__device__ float g_kv[(size_t)RWS * (HH * (NOPE + VD))];
__device__ float g_ao[(size_t)RWS * (HH * VD)];

__device__ __forceinline__ unsigned f2tf(float x) {
    unsigned r; asm("cvt.rna.tf32.f32 %0, %1;" : "=r"(r) : "f"(x)); return r;
}
__device__ __forceinline__ void mma8(float* c, const unsigned* a, const unsigned* b) {
    asm volatile("mma.sync.aligned.m16n8k8.row.col.f32.tf32.tf32.f32 "
        "{%0,%1,%2,%3}, {%4,%5,%6,%7}, {%8,%9}, {%0,%1,%2,%3};"
        : "+f"(c[0]), "+f"(c[1]), "+f"(c[2]), "+f"(c[3])
        : "r"(a[0]), "r"(a[1]), "r"(a[2]), "r"(a[3]), "r"(b[0]), "r"(b[1]));
}
__device__ __forceinline__ void cp16(void* dst, const void* src, bool pred) {
    unsigned d = (unsigned)__cvta_generic_to_shared(dst);
    int sz = pred ? 16 : 0;
    asm volatile("cp.async.cg.shared.global [%0], [%1], 16, %2;"
                 :: "r"(d), "l"(src), "r"(sz));
}
__device__ __forceinline__ void cp_commit() {
    asm volatile("cp.async.commit_group;");
}
template<int N> __device__ __forceinline__ void cp_wait() {
    asm volatile("cp.async.wait_group %0;" :: "n"(N));
}

// ---------------------------------------------------------------------------
// TF32 tensor-core GEMM, cp.async 3-stage pipeline.
// C[M,N] = A[M,K] @ B[K,N] row-major fp32. 128x128 tile, BK=32, 256 thr.
// Smem holds raw fp32; cvt to tf32 at fragment load.
// ---------------------------------------------------------------------------
#define ASTR 36
#define BSTR 136
#define STG_W (128*ASTR + 32*BSTR)
#define GSMEM (3 * STG_W * 4)

__global__ void __launch_bounds__(256, 2) gemm_tf32(const float* __restrict__ A,
                                                    const float* __restrict__ B,
                                                    float* __restrict__ C,
                                                    int M, int N, int K) {
    extern __shared__ float sg[];

    int tid = threadIdx.x;
    int bm = blockIdx.y * 128, bn = blockIdx.x * 128;
    int wid = tid >> 5, lane = tid & 31;
    int wm = (wid >> 2) * 64, wn = (wid & 3) * 32;
    int gr = lane >> 2, tg = lane & 3;

    int aRow = tid >> 3;           // 0..31, +32p
    int aCol = (tid & 7) * 4;
    int bRow = tid >> 5;           // 0..7, +8p
    int bCol = (tid & 31) * 4;
    bool bok = (bn + bCol) < N;

    int nkb = K >> 5;

    // issue one stage's loads
    auto issue = [&](int kb, int stg) {
        float* As = sg + stg * STG_W;
        float* Bs = As + 128 * ASTR;
        int k0 = kb * 32;
        #pragma unroll
        for (int p = 0; p < 4; p++) {
            int row = aRow + 32 * p;
            cp16(As + row * ASTR + aCol,
                 A + (size_t)(bm + row) * K + k0 + aCol, true);
        }
        #pragma unroll
        for (int p = 0; p < 4; p++) {
            int row = bRow + 8 * p;
            cp16(Bs + row * BSTR + bCol,
                 B + (size_t)(k0 + row) * N + bn + bCol, bok);
        }
        cp_commit();
    };

    issue(0, 0);
    if (nkb > 1) issue(1, 1);

    float acc[4][4][4];
    #pragma unroll
    for (int i = 0; i < 4; i++)
        #pragma unroll
        for (int j = 0; j < 4; j++)
            #pragma unroll
            for (int t = 0; t < 4; t++) acc[i][j][t] = 0.f;

    int stg = 0;
    for (int kb = 0; kb < nkb; kb++) {
        cp_wait<1>();
        __syncthreads();
        if (kb + 2 < nkb) {
            int ns = stg + 2; if (ns >= 3) ns -= 3;
            issue(kb + 2, ns);
        }

        float* As = sg + stg * STG_W;
        float* Bs = As + 128 * ASTR;

        #pragma unroll
        for (int ks = 0; ks < 4; ks++) {
            int kk = ks * 8;
            unsigned a[4][4], b[4][2];
            #pragma unroll
            for (int i = 0; i < 4; i++) {
                int m = wm + i * 16;
                a[i][0] = f2tf(As[(m + gr) * ASTR + kk + tg]);
                a[i][1] = f2tf(As[(m + gr + 8) * ASTR + kk + tg]);
                a[i][2] = f2tf(As[(m + gr) * ASTR + kk + tg + 4]);
                a[i][3] = f2tf(As[(m + gr + 8) * ASTR + kk + tg + 4]);
            }
            #pragma unroll
            for (int j = 0; j < 4; j++) {
                int n = wn + j * 8;
                b[j][0] = f2tf(Bs[(kk + tg) * BSTR + n + gr]);
                b[j][1] = f2tf(Bs[(kk + tg + 4) * BSTR + n + gr]);
            }
            #pragma unroll
            for (int i = 0; i < 4; i++)
                #pragma unroll
                for (int j = 0; j < 4; j++)
                    mma8(acc[i][j], a[i], b[j]);
        }
        __syncthreads();
        stg++; if (stg >= 3) stg = 0;
    }

    #pragma unroll
    for (int i = 0; i < 4; i++) {
        int r0 = bm + wm + i * 16 + gr;
        #pragma unroll
        for (int j = 0; j < 4; j++) {
            int cc = bn + wn + j * 8 + 2 * tg;
            if (cc < N) {
                *(float2*)(C + (size_t)r0 * N + cc) =
                    make_float2(acc[i][j][0], acc[i][j][1]);
                *(float2*)(C + (size_t)(r0 + 8) * N + cc) =
                    make_float2(acc[i][j][2], acc[i][j][3]);
            }
        }
    }
}

// ---------------------------------------------------------------------------
// RMSNorm over first LORA cols of kva -> ckv, scaled by kv_norm_scale.
// ---------------------------------------------------------------------------
__global__ void __launch_bounds__(128) rmsnorm_kernel(const float* __restrict__ kva,
                                                      const float* __restrict__ kvs,
                                                      float* __restrict__ ckv) {
    int r = blockIdx.x;
    int tid = threadIdx.x;
    const float* row = kva + (size_t)r * (LORA + ROPE_D);

    float x[4];
    float ss = 0.f;
    #pragma unroll
    for (int j = 0; j < 4; j++) {
        x[j] = row[tid + 128 * j];
        ss += x[j] * x[j];
    }
    #pragma unroll
    for (int o = 16; o > 0; o >>= 1)
        ss += __shfl_xor_sync(0xffffffffu, ss, o);

    __shared__ float wsum[4];
    if ((tid & 31) == 0) wsum[tid >> 5] = ss;
    __syncthreads();
    float tot = wsum[0] + wsum[1] + wsum[2] + wsum[3];
    float rms = rsqrtf(tot / (float)LORA + 1e-6f);

    float* orow = ckv + (size_t)r * LORA;
    #pragma unroll
    for (int j = 0; j < 4; j++) {
        int c = tid + 128 * j;
        orow[c] = x[j] * rms * kvs[c];
    }
}

// ---------------------------------------------------------------------------
// RoPE: apply to q_pe (16 heads) and k_pe (in kva), in place.
// ---------------------------------------------------------------------------
__global__ void rope_kernel(float* __restrict__ q, float* __restrict__ kva) {
    int r = blockIdx.x;
    int s = r % SS;
    int i = threadIdx.x;        // 0..31
    int hy = threadIdx.y;       // 0..16

    float inv = powf(10000.f, -(float)i / 32.f);
    float ang = (float)s * inv;
    float sn, cs;
    sincosf(ang, &sn, &cs);

    float* base;
    if (hy < HH) {
        base = q + (size_t)r * (HH * QHD) + hy * QHD + NOPE;
    } else {
        base = kva + (size_t)r * (LORA + ROPE_D) + LORA;
    }
    float x1 = base[i];
    float x2 = base[i + 32];
    base[i]      = x1 * cs - x2 * sn;
    base[i + 32] = x2 * cs + x1 * sn;
}

// ---------------------------------------------------------------------------
// Flash attention (causal), TF32 tensor cores.
// BM=128, BN=64, 256 thr = 8 warps (16 q-rows each).
// Q fragments live in registers; K/V double-buffered via cp.async.
// ---------------------------------------------------------------------------
#define FBM 128
#define FBN 64
#define KSTR 196
#define VSTR 136
#define SSTR 68
// layout: sK[2] (2*64*196) | sV[2] (2*64*136) | sS (128*68)
#define SK_W (64*KSTR)
#define SV_W (64*VSTR)
#define FSMEM ((2*SK_W + 2*SV_W + FBM*SSTR) * 4)

__global__ void __launch_bounds__(256, 1) flash_tf32(const float* __restrict__ q,
                                                     const float* __restrict__ kv,
                                                     const float* __restrict__ kva,
                                                     float* __restrict__ ao) {
    extern __shared__ float fsm[];
    float* sK = fsm;                    // [2][SK_W]
    float* sV = fsm + 2 * SK_W;         // [2][SV_W]
    unsigned* sS = (unsigned*)(fsm + 2 * SK_W + 2 * SV_W);

    int qt = blockIdx.x, h = blockIdx.y, b = blockIdx.z;
    int tid = threadIdx.x, wid = tid >> 5, lane = tid & 31;
    int gr = lane >> 2, tg = lane & 3;
    int qbase = qt * FBM;
    int wrow = wid * 16;

    // --- stage Q through the sK area (overlay), pull fragments to registers
    unsigned* sQ = (unsigned*)fsm;      // 128*196 words == 2*SK_W exactly
    for (int i = tid; i < FBM * 48; i += 256) {
        int row = i / 48, d = (i - row * 48) * 4;
        int r = b * SS + qbase + row;
        float4 v = *(const float4*)(q + (size_t)r * (HH * QHD) + h * QHD + d);
        *(uint4*)&sQ[row * KSTR + d] =
            make_uint4(f2tf(v.x), f2tf(v.y), f2tf(v.z), f2tf(v.w));
    }
    __syncthreads();
    unsigned qf[24][4];
    #pragma unroll
    for (int ks = 0; ks < 24; ks++) {
        int kk = ks * 8;
        qf[ks][0] = sQ[(wrow + gr) * KSTR + kk + tg];
        qf[ks][1] = sQ[(wrow + gr + 8) * KSTR + kk + tg];
        qf[ks][2] = sQ[(wrow + gr) * KSTR + kk + tg + 4];
        qf[ks][3] = sQ[(wrow + gr + 8) * KSTR + kk + tg + 4];
    }
    __syncthreads();   // everyone has Q frags; sK area now free

    // K/V stage loader (cp.async, fp32 into smem)
    auto load_kv = [&](int kbase, int stg) {
        float* K = sK + stg * SK_W;
        float* V = sV + stg * SV_W;
        #pragma unroll
        for (int p = 0; p < 12; p++) {
            int idx = tid + p * 256;
            int row = idx / 48, c = idx - row * 48;   // c: 16B units
            int r = b * SS + kbase + row;
            const float* src = (c < 32)
                ? kv  + (size_t)r * (HH * (NOPE + VD)) + h * (NOPE + VD) + c * 4
                : kva + (size_t)r * (LORA + ROPE_D) + LORA + (c - 32) * 4;
            cp16(K + row * KSTR + c * 4, src, true);
        }
        #pragma unroll
        for (int p = 0; p < 8; p++) {
            int idx = tid + p * 256;
            int row = idx >> 5, c = idx & 31;
            int r = b * SS + kbase + row;
            cp16(V + row * VSTR + c * 4,
                 kv + (size_t)r * (HH * (NOPE + VD)) + h * (NOPE + VD) + NOPE + c * 4,
                 true);
        }
        cp_commit();
    };

    float o[16][4];
    #pragma unroll
    for (int n = 0; n < 16; n++)
        #pragma unroll
        for (int t = 0; t < 4; t++) o[n][t] = 0.f;
    float m0 = -1e30f, m1 = -1e30f, l0 = 0.f, l1 = 0.f;
    const float scale = 0.07216878364870323f;  // 192^-0.5

    int ktmax = (qbase + FBM) / FBN;
    load_kv(0, 0);

    for (int kt = 0; kt < ktmax; kt++) {
        int kbase = kt * FBN;
        int stg = kt & 1;
        cp_wait<0>();
        __syncthreads();
        if (kt + 1 < ktmax) load_kv(kbase + FBN, stg ^ 1);

        float* K = sK + stg * SK_W;
        float* V = sV + stg * SV_W;

        // ---- scores: S = Q K^T ----
        float sacc[8][4];
        #pragma unroll
        for (int j = 0; j < 8; j++)
            #pragma unroll
            for (int t = 0; t < 4; t++) sacc[j][t] = 0.f;

        #pragma unroll
        for (int ks = 0; ks < 24; ks++) {
            int kk = ks * 8;
            #pragma unroll
            for (int j = 0; j < 8; j++) {
                unsigned bb[2];
                bb[0] = f2tf(K[(j * 8 + gr) * KSTR + kk + tg]);
                bb[1] = f2tf(K[(j * 8 + gr) * KSTR + kk + tg + 4]);
                mma8(sacc[j], qf[ks], bb);
            }
        }

        // ---- scale + causal mask + online softmax ----
        int qr0 = qbase + wrow + gr;
        int qr1 = qr0 + 8;
        float mx0 = -1e30f, mx1 = -1e30f;
        #pragma unroll
        for (int j = 0; j < 8; j++) {
            int c0 = kbase + j * 8 + 2 * tg;
            sacc[j][0] = (c0     <= qr0) ? sacc[j][0] * scale : -1e30f;
            sacc[j][1] = (c0 + 1 <= qr0) ? sacc[j][1] * scale : -1e30f;
            sacc[j][2] = (c0     <= qr1) ? sacc[j][2] * scale : -1e30f;
            sacc[j][3] = (c0 + 1 <= qr1) ? sacc[j][3] * scale : -1e30f;
            mx0 = fmaxf(mx0, fmaxf(sacc[j][0], sacc[j][1]));
            mx1 = fmaxf(mx1, fmaxf(sacc[j][2], sacc[j][3]));
        }
        mx0 = fmaxf(mx0, __shfl_xor_sync(0xffffffffu, mx0, 1));
        mx0 = fmaxf(mx0, __shfl_xor_sync(0xffffffffu, mx0, 2));
        mx1 = fmaxf(mx1, __shfl_xor_sync(0xffffffffu, mx1, 1));
        mx1 = fmaxf(mx1, __shfl_xor_sync(0xffffffffu, mx1, 2));

        float mn0 = fmaxf(m0, mx0), mn1 = fmaxf(m1, mx1);
        float f0 = __expf(m0 - mn0), f1 = __expf(m1 - mn1);
        m0 = mn0; m1 = mn1;

        float s0 = 0.f, s1 = 0.f;
        #pragma unroll
        for (int j = 0; j < 8; j++) {
            float p0 = __expf(sacc[j][0] - mn0);
            float p1 = __expf(sacc[j][1] - mn0);
            float p2 = __expf(sacc[j][2] - mn1);
            float p3 = __expf(sacc[j][3] - mn1);
            s0 += p0 + p1; s1 += p2 + p3;
            int cc = j * 8 + 2 * tg;
            *(uint2*)&sS[(wrow + gr) * SSTR + cc]     = make_uint2(f2tf(p0), f2tf(p1));
            *(uint2*)&sS[(wrow + gr + 8) * SSTR + cc] = make_uint2(f2tf(p2), f2tf(p3));
        }
        s0 += __shfl_xor_sync(0xffffffffu, s0, 1);
        s0 += __shfl_xor_sync(0xffffffffu, s0, 2);
        s1 += __shfl_xor_sync(0xffffffffu, s1, 1);
        s1 += __shfl_xor_sync(0xffffffffu, s1, 2);
        l0 = l0 * f0 + s0;
        l1 = l1 * f1 + s1;

        #pragma unroll
        for (int n = 0; n < 16; n++) {
            o[n][0] *= f0; o[n][1] *= f0; o[n][2] *= f1; o[n][3] *= f1;
        }
        __syncwarp();

        // ---- PV: O += P V ----
        #pragma unroll
        for (int ks = 0; ks < 8; ks++) {
            int kk = ks * 8;
            unsigned a[4];
            a[0] = sS[(wrow + gr) * SSTR + kk + tg];
            a[1] = sS[(wrow + gr + 8) * SSTR + kk + tg];
            a[2] = sS[(wrow + gr) * SSTR + kk + tg + 4];
            a[3] = sS[(wrow + gr + 8) * SSTR + kk + tg + 4];
            #pragma unroll
            for (int n = 0; n < 16; n++) {
                unsigned bb[2];
                bb[0] = f2tf(V[(kk + tg) * VSTR + n * 8 + gr]);
                bb[1] = f2tf(V[(kk + tg + 4) * VSTR + n * 8 + gr]);
                mma8(o[n], a, bb);
            }
        }
        __syncwarp();
    }

    // epilogue
    float inv0 = 1.f / l0, inv1 = 1.f / l1;
    size_t r0 = (size_t)(b * SS + qbase + wrow + gr) * (HH * VD);
    size_t r1 = r0 + 8 * (HH * VD);
    #pragma unroll
    for (int n = 0; n < 16; n++) {
        int cc = h * VD + n * 8 + 2 * tg;
        *(float2*)(ao + r0 + cc) = make_float2(o[n][0] * inv0, o[n][1] * inv0);
        *(float2*)(ao + r1 + cc) = make_float2(o[n][2] * inv1, o[n][3] * inv1);
    }
}

// ---------------------------------------------------------------------------
extern "C" void kernel_launch(void* const* d_in, const int* in_sizes, int n_in,
                              void* d_out, int out_size) {
    const float* x     = (const float*)d_in[0];
    const float* wq    = (const float*)d_in[1];
    const float* wkv_a = (const float*)d_in[2];
    const float* wkv_b = (const float*)d_in[3];
    const float* wo    = (const float*)d_in[4];
    const float* kvs   = (const float*)d_in[5];
    float* out = (float*)d_out;

    float *q, *kva, *ckv, *kv, *ao;
    cudaGetSymbolAddress((void**)&q,   g_q);
    cudaGetSymbolAddress((void**)&kva, g_kva);
    cudaGetSymbolAddress((void**)&ckv, g_ckv);
    cudaGetSymbolAddress((void**)&kv,  g_kv);
    cudaGetSymbolAddress((void**)&ao,  g_ao);

    static bool attr_done = false;
    if (!attr_done) {
        cudaFuncSetAttribute(flash_tf32,
                             cudaFuncAttributeMaxDynamicSharedMemorySize,
                             (int)FSMEM);
        cudaFuncSetAttribute(gemm_tf32,
                             cudaFuncAttributeMaxDynamicSharedMemorySize,
                             (int)GSMEM);
        attr_done = true;
    }

    // q = x @ wq : [4096, 3072]
    gemm_tf32<<<dim3(3072 / 128, RWS / 128), 256, GSMEM>>>(x, wq, q, RWS, HH * QHD, EE);
    // kva = x @ wkv_a : [4096, 576]
    gemm_tf32<<<dim3((LORA + ROPE_D + 127) / 128, RWS / 128), 256, GSMEM>>>(x, wkv_a, kva, RWS, LORA + ROPE_D, EE);
    // ckv = rmsnorm(kva[:, :512]) * kv_norm_scale
    rmsnorm_kernel<<<RWS, 128>>>(kva, kvs, ckv);
    // rope q_pe (in q) and k_pe (in kva), in place
    rope_kernel<<<RWS, dim3(32, 17)>>>(q, kva);
    // kv = ckv @ wkv_b : [4096, 4096]
    gemm_tf32<<<dim3((HH * (NOPE + VD)) / 128, RWS / 128), 256, GSMEM>>>(ckv, wkv_b, kv, RWS, HH * (NOPE + VD), LORA);
    // attention -> ao : [4096, 2048]
    flash_tf32<<<dim3(SS / FBM, HH, BB), 256, FSMEM>>>(q, kv, kva, ao);
    // out = ao @ wo : [4096, 2048]
    gemm_tf32<<<dim3(EE / 128, RWS / 128), 256, GSMEM>>>(ao, wo, out, RWS, EE, HH * VD);
}

// round 6
// speedup vs baseline: 10.4564x; 2.1827x over previous
#include <cuda_runtime.h>
#include <cuda_fp16.h>
#include <math.h>

// Problem constants
#define BB 2
#define SS 2048
#define EE 2048
#define HH 16
#define NOPE 128
#define ROPE_D 64
#define QHD 192          // NOPE + ROPE
#define LORA 512
#define VD 128
#define RWS (BB*SS)      // 4096 rows

// Scratch (device globals; no allocation allowed)
__device__ float  g_q[(size_t)RWS * (HH * QHD)];       // fp32 q (pre-rope)
__device__ float  g_kva[(size_t)RWS * (LORA + ROPE_D)];
__device__ __half g_qh[(size_t)RWS * (HH * QHD)];      // roped q, half
__device__ __half g_kpeh[(size_t)RWS * ROPE_D];        // roped k_pe, half
__device__ __half g_ckvh[(size_t)RWS * LORA];
__device__ __half g_kvh[(size_t)RWS * (HH * (NOPE + VD))];
__device__ __half g_aoh[(size_t)RWS * (HH * VD)];
__device__ __half g_xh[(size_t)RWS * EE];
__device__ __half g_wqT[(size_t)3072 * 2048];
__device__ __half g_wkvaT[(size_t)640 * 2048];         // padded 576->640
__device__ __half g_wkvbT[(size_t)4096 * 512];
__device__ __half g_woT[(size_t)2048 * 2048];

// ---------------- helpers ----------------
__device__ __forceinline__ void mma16(float* c, const unsigned* a, const unsigned* b) {
    asm volatile("mma.sync.aligned.m16n8k16.row.col.f32.f16.f16.f32 "
        "{%0,%1,%2,%3}, {%4,%5,%6,%7}, {%8,%9}, {%0,%1,%2,%3};"
        : "+f"(c[0]), "+f"(c[1]), "+f"(c[2]), "+f"(c[3])
        : "r"(a[0]), "r"(a[1]), "r"(a[2]), "r"(a[3]), "r"(b[0]), "r"(b[1]));
}
__device__ __forceinline__ void ldm_x4(unsigned* r, const void* p) {
    unsigned s = (unsigned)__cvta_generic_to_shared(p);
    asm volatile("ldmatrix.sync.aligned.m8n8.x4.shared.b16 {%0,%1,%2,%3}, [%4];"
        : "=r"(r[0]), "=r"(r[1]), "=r"(r[2]), "=r"(r[3]) : "r"(s));
}
__device__ __forceinline__ void ldm_x2(unsigned* r, const void* p) {
    unsigned s = (unsigned)__cvta_generic_to_shared(p);
    asm volatile("ldmatrix.sync.aligned.m8n8.x2.shared.b16 {%0,%1}, [%2];"
        : "=r"(r[0]), "=r"(r[1]) : "r"(s));
}
__device__ __forceinline__ void ldm_x2t(unsigned* r, const void* p) {
    unsigned s = (unsigned)__cvta_generic_to_shared(p);
    asm volatile("ldmatrix.sync.aligned.m8n8.x2.trans.shared.b16 {%0,%1}, [%2];"
        : "=r"(r[0]), "=r"(r[1]) : "r"(s));
}
__device__ __forceinline__ void cp16(void* dst, const void* src) {
    unsigned d = (unsigned)__cvta_generic_to_shared(dst);
    asm volatile("cp.async.cg.shared.global [%0], [%1], 16;" :: "r"(d), "l"(src));
}
__device__ __forceinline__ void cp_commit() {
    asm volatile("cp.async.commit_group;");
}
template<int N> __device__ __forceinline__ void cp_wait() {
    asm volatile("cp.async.wait_group %0;" :: "n"(N));
}
__device__ __forceinline__ void st2o(float* p, float x, float y) {
    *(float2*)p = make_float2(x, y);
}
__device__ __forceinline__ void st2o(__half* p, float x, float y) {
    *(__half2*)p = __floats2half2_rn(x, y);
}

// ---------------------------------------------------------------------------
// FP16 tensor-core GEMM: C[M,N] = A[M,K] @ BT[N,K]^T. A,BT half; C float/half.
// 128x128 tile, BK=32, 256 thr = 8 warps (2Mx4N, 64x32 each), 3-stage cp.async.
// ---------------------------------------------------------------------------
#define ASTRH 40
#define STG_B (2 * 128 * ASTRH * 2)   // A(10240B) + B(10240B)
#define GSMEM (3 * STG_B)

template<typename OutT>
__global__ void __launch_bounds__(256, 2) hgemm(const __half* __restrict__ A,
                                                const __half* __restrict__ BT,
                                                OutT* __restrict__ C,
                                                int N, int K) {
    extern __shared__ __half hs[];

    int tid = threadIdx.x, wid = tid >> 5, lane = tid & 31;
    int bm = blockIdx.y * 128, bn = blockIdx.x * 128;
    int wm = (wid >> 2) * 64, wn = (wid & 3) * 32;
    int gr = lane >> 2, tg = lane & 3;

    int a_r = (lane & 7) + ((lane >> 3) & 1) * 8;   // ldmatrix x4 row map
    int a_c = ((lane >> 4) & 1) * 8;
    int b_r = lane & 7;                             // ldmatrix x2 row map
    int b_c = ((lane >> 3) & 1) * 8;

    int nkb = K >> 5;

    auto issue = [&](int kb, int slot) {
        __half* sA = hs + slot * (STG_B / 2);
        __half* sB = sA + 128 * ASTRH;
        int k0 = kb * 32;
        #pragma unroll
        for (int p = 0; p < 2; p++) {
            int idx = tid + p * 256;         // 0..511
            int row = idx >> 2, c = idx & 3; // 4 x 16B chunks per row
            cp16(sA + row * ASTRH + c * 8, A + (size_t)(bm + row) * K + k0 + c * 8);
        }
        #pragma unroll
        for (int p = 0; p < 2; p++) {
            int idx = tid + p * 256;
            int row = idx >> 2, c = idx & 3;
            cp16(sB + row * ASTRH + c * 8, BT + (size_t)(bn + row) * K + k0 + c * 8);
        }
        cp_commit();
    };

    issue(0, 0);
    if (nkb > 1) issue(1, 1);

    float acc[4][4][4];
    #pragma unroll
    for (int i = 0; i < 4; i++)
        #pragma unroll
        for (int j = 0; j < 4; j++)
            #pragma unroll
            for (int t = 0; t < 4; t++) acc[i][j][t] = 0.f;

    int slot = 0;
    for (int kb = 0; kb < nkb; kb++) {
        if (kb + 1 < nkb) cp_wait<1>(); else cp_wait<0>();
        __syncthreads();
        if (kb + 2 < nkb) {
            int ns = slot + 2; if (ns >= 3) ns -= 3;
            issue(kb + 2, ns);
        }

        __half* sA = hs + slot * (STG_B / 2);
        __half* sB = sA + 128 * ASTRH;

        #pragma unroll
        for (int ks = 0; ks < 2; ks++) {
            int kk = ks * 16;
            unsigned a[4][4], b[4][2];
            #pragma unroll
            for (int i = 0; i < 4; i++)
                ldm_x4(a[i], sA + (wm + i * 16 + a_r) * ASTRH + kk + a_c);
            #pragma unroll
            for (int j = 0; j < 4; j++)
                ldm_x2(b[j], sB + (wn + j * 8 + b_r) * ASTRH + kk + b_c);
            #pragma unroll
            for (int i = 0; i < 4; i++)
                #pragma unroll
                for (int j = 0; j < 4; j++)
                    mma16(acc[i][j], a[i], b[j]);
        }
        __syncthreads();
        slot++; if (slot >= 3) slot = 0;
    }

    #pragma unroll
    for (int i = 0; i < 4; i++) {
        int r0 = bm + wm + i * 16 + gr;
        #pragma unroll
        for (int j = 0; j < 4; j++) {
            int cc = bn + wn + j * 8 + 2 * tg;
            if (cc < N) {
                st2o(C + (size_t)r0 * N + cc, acc[i][j][0], acc[i][j][1]);
                st2o(C + (size_t)(r0 + 8) * N + cc, acc[i][j][2], acc[i][j][3]);
            }
        }
    }
}

// ---------------------------------------------------------------------------
// Prep kernels
// ---------------------------------------------------------------------------
__global__ void f2h_copy(const float* __restrict__ src, __half* __restrict__ dst,
                         int n4) {
    for (int i = blockIdx.x * blockDim.x + threadIdx.x; i < n4; i += gridDim.x * blockDim.x) {
        float4 v = *(const float4*)(src + i * 4);
        __half2* d = (__half2*)(dst + i * 4);
        d[0] = __floats2half2_rn(v.x, v.y);
        d[1] = __floats2half2_rn(v.z, v.w);
    }
}

// transpose + half: src[K,N] fp32 -> dst[Npad,K] half (pad rows zeroed)
__global__ void transpose_h(const float* __restrict__ src, __half* __restrict__ dst,
                            int K, int N, int Npad) {
    __shared__ float t[32][33];
    int kb = blockIdx.x * 32, nb = blockIdx.y * 32;
    int tx = threadIdx.x, ty = threadIdx.y;
    #pragma unroll
    for (int j = 0; j < 4; j++) {
        int k = kb + ty + j * 8, n = nb + tx;
        float v = 0.f;
        if (k < K && n < N) v = src[(size_t)k * N + n];
        t[ty + j * 8][tx] = v;
    }
    __syncthreads();
    #pragma unroll
    for (int j = 0; j < 4; j++) {
        int n = nb + ty + j * 8, k = kb + tx;
        if (n < Npad && k < K) dst[(size_t)n * K + k] = __float2half(t[tx][ty + j * 8]);
    }
}

// RMSNorm over first LORA cols of kva -> ckvh (half)
__global__ void __launch_bounds__(128) rmsnorm_kernel(const float* __restrict__ kva,
                                                      const float* __restrict__ kvs,
                                                      __half* __restrict__ ckv) {
    int r = blockIdx.x;
    int tid = threadIdx.x;
    const float* row = kva + (size_t)r * (LORA + ROPE_D);

    float x[4];
    float ss = 0.f;
    #pragma unroll
    for (int j = 0; j < 4; j++) {
        x[j] = row[tid + 128 * j];
        ss += x[j] * x[j];
    }
    #pragma unroll
    for (int o = 16; o > 0; o >>= 1)
        ss += __shfl_xor_sync(0xffffffffu, ss, o);

    __shared__ float wsum[4];
    if ((tid & 31) == 0) wsum[tid >> 5] = ss;
    __syncthreads();
    float tot = wsum[0] + wsum[1] + wsum[2] + wsum[3];
    float rms = rsqrtf(tot / (float)LORA + 1e-6f);

    __half* orow = ckv + (size_t)r * LORA;
    #pragma unroll
    for (int j = 0; j < 4; j++) {
        int c = tid + 128 * j;
        orow[c] = __float2half(x[j] * rms * kvs[c]);
    }
}

// rope + pack q (fp32 -> half, rope on pe dims) and k_pe (kva -> half roped)
__global__ void __launch_bounds__(256) rope_pack(const float* __restrict__ q,
                                                 const float* __restrict__ kva,
                                                 __half* __restrict__ qh,
                                                 __half* __restrict__ kpeh) {
    int r = blockIdx.x;
    int s = r % SS;
    int t = threadIdx.x;
    const float* qr = q + (size_t)r * (HH * QHD);
    __half* qo = qh + (size_t)r * (HH * QHD);

    // nope dims: straight convert (16 heads x 128 = 2048)
    #pragma unroll
    for (int p = 0; p < 8; p++) {
        int i = t + p * 256;
        int head = i >> 7, d = i & 127;
        int off = head * QHD + d;
        qo[off] = __float2half(qr[off]);
    }
    // q pe pairs: 16 heads x 32 = 512 pairs
    #pragma unroll
    for (int p = 0; p < 2; p++) {
        int i = t + p * 256;
        int head = i >> 5, ii = i & 31;
        float inv = powf(10000.f, -(float)ii / 32.f);
        float sn, cs;
        sincosf((float)s * inv, &sn, &cs);
        int off = head * QHD + NOPE + ii;
        float x1 = qr[off], x2 = qr[off + 32];
        qo[off]      = __float2half(x1 * cs - x2 * sn);
        qo[off + 32] = __float2half(x2 * cs + x1 * sn);
    }
    // k_pe pairs: 32
    if (t < 32) {
        float inv = powf(10000.f, -(float)t / 32.f);
        float sn, cs;
        sincosf((float)s * inv, &sn, &cs);
        const float* kp = kva + (size_t)r * (LORA + ROPE_D) + LORA;
        __half* ko = kpeh + (size_t)r * ROPE_D;
        float x1 = kp[t], x2 = kp[t + 32];
        ko[t]      = __float2half(x1 * cs - x2 * sn);
        ko[t + 32] = __float2half(x2 * cs + x1 * sn);
    }
}

// ---------------------------------------------------------------------------
// Flash attention (causal), FP16 mma. BM=128, BN=64, 256 thr = 8 warps.
// Q frags in registers; K/V double-buffered via cp.async; all operands half.
// ---------------------------------------------------------------------------
#define FBM 128
#define FBN 64
#define KSTRH 200
#define VSTRH 136
#define SSTRH 72
#define SK_W (64 * KSTRH)      // halves per K stage
#define SV_W (64 * VSTRH)
#define FSMEM ((2*SK_W + 2*SV_W + FBM*SSTRH) * 2)

__global__ void __launch_bounds__(256, 1) flash_h(const __half* __restrict__ qh,
                                                  const __half* __restrict__ kvh,
                                                  const __half* __restrict__ kpeh,
                                                  __half* __restrict__ aoh) {
    extern __shared__ __half fh[];
    __half* sK = fh;                    // [2][SK_W]
    __half* sV = fh + 2 * SK_W;         // [2][SV_W]
    __half* sS = fh + 2 * SK_W + 2 * SV_W;

    int qt = blockIdx.x, h = blockIdx.y, b = blockIdx.z;
    int tid = threadIdx.x, wid = tid >> 5, lane = tid & 31;
    int gr = lane >> 2, tg = lane & 3;
    int qbase = qt * FBM;
    int wrow = wid * 16;

    int a_r = (lane & 7) + ((lane >> 3) & 1) * 8;
    int a_c = ((lane >> 4) & 1) * 8;
    int b_r = lane & 7;
    int b_c = ((lane >> 3) & 1) * 8;
    int v_r = lane & 15;

    // --- stage Q through sK overlay (128 x 200 halves = 2*SK_W exactly)
    __half* sQ = fh;
    #pragma unroll
    for (int p = 0; p < 12; p++) {
        int idx = tid + p * 256;           // 0..3071
        int row = idx / 24, c = idx - row * 24;
        int r = b * SS + qbase + row;
        cp16(sQ + row * KSTRH + c * 8,
             qh + (size_t)r * (HH * QHD) + h * QHD + c * 8);
    }
    cp_commit();
    cp_wait<0>();
    __syncthreads();

    unsigned qf[12][4];
    #pragma unroll
    for (int ks = 0; ks < 12; ks++)
        ldm_x4(qf[ks], sQ + (wrow + a_r) * KSTRH + ks * 16 + a_c);
    __syncthreads();   // Q consumed; sK area free

    auto load_kv = [&](int kbase, int stg) {
        __half* K = sK + stg * SK_W;
        __half* V = sV + stg * SV_W;
        #pragma unroll
        for (int p = 0; p < 6; p++) {
            int idx = tid + p * 256;       // 0..1535
            int row = idx / 24, c = idx - row * 24;
            int r = b * SS + kbase + row;
            const __half* src = (c < 16)
                ? kvh  + (size_t)r * (HH * (NOPE + VD)) + h * (NOPE + VD) + c * 8
                : kpeh + (size_t)r * ROPE_D + (c - 16) * 8;
            cp16(K + row * KSTRH + c * 8, src);
        }
        #pragma unroll
        for (int p = 0; p < 4; p++) {
            int idx = tid + p * 256;       // 0..1023
            int row = idx >> 4, c = idx & 15;
            int r = b * SS + kbase + row;
            cp16(V + row * VSTRH + c * 8,
                 kvh + (size_t)r * (HH * (NOPE + VD)) + h * (NOPE + VD) + NOPE + c * 8);
        }
        cp_commit();
    };

    float o[16][4];
    #pragma unroll
    for (int n = 0; n < 16; n++)
        #pragma unroll
        for (int t = 0; t < 4; t++) o[n][t] = 0.f;
    float m0 = -1e30f, m1 = -1e30f, l0 = 0.f, l1 = 0.f;
    const float scale = 0.07216878364870323f;  // 192^-0.5

    int ktmax = (qbase + FBM) / FBN;
    load_kv(0, 0);

    for (int kt = 0; kt < ktmax; kt++) {
        int kbase = kt * FBN;
        int stg = kt & 1;
        cp_wait<0>();
        __syncthreads();
        if (kt + 1 < ktmax) load_kv(kbase + FBN, stg ^ 1);

        __half* K = sK + stg * SK_W;
        __half* V = sV + stg * SV_W;

        // ---- scores: S = Q K^T (16 rows x 64 cols per warp) ----
        float sacc[8][4];
        #pragma unroll
        for (int j = 0; j < 8; j++)
            #pragma unroll
            for (int t = 0; t < 4; t++) sacc[j][t] = 0.f;

        #pragma unroll
        for (int ks = 0; ks < 12; ks++) {
            int kk = ks * 16;
            #pragma unroll
            for (int j = 0; j < 8; j++) {
                unsigned bb[2];
                ldm_x2(bb, K + (j * 8 + b_r) * KSTRH + kk + b_c);
                mma16(sacc[j], qf[ks], bb);
            }
        }

        // ---- scale + causal mask + online softmax ----
        int qr0 = qbase + wrow + gr;
        int qr1 = qr0 + 8;
        float mx0 = -1e30f, mx1 = -1e30f;
        #pragma unroll
        for (int j = 0; j < 8; j++) {
            int c0 = kbase + j * 8 + 2 * tg;
            sacc[j][0] = (c0     <= qr0) ? sacc[j][0] * scale : -1e30f;
            sacc[j][1] = (c0 + 1 <= qr0) ? sacc[j][1] * scale : -1e30f;
            sacc[j][2] = (c0     <= qr1) ? sacc[j][2] * scale : -1e30f;
            sacc[j][3] = (c0 + 1 <= qr1) ? sacc[j][3] * scale : -1e30f;
            mx0 = fmaxf(mx0, fmaxf(sacc[j][0], sacc[j][1]));
            mx1 = fmaxf(mx1, fmaxf(sacc[j][2], sacc[j][3]));
        }
        mx0 = fmaxf(mx0, __shfl_xor_sync(0xffffffffu, mx0, 1));
        mx0 = fmaxf(mx0, __shfl_xor_sync(0xffffffffu, mx0, 2));
        mx1 = fmaxf(mx1, __shfl_xor_sync(0xffffffffu, mx1, 1));
        mx1 = fmaxf(mx1, __shfl_xor_sync(0xffffffffu, mx1, 2));

        float mn0 = fmaxf(m0, mx0), mn1 = fmaxf(m1, mx1);
        float f0 = __expf(m0 - mn0), f1 = __expf(m1 - mn1);
        m0 = mn0; m1 = mn1;

        float s0 = 0.f, s1 = 0.f;
        #pragma unroll
        for (int j = 0; j < 8; j++) {
            float p0 = __expf(sacc[j][0] - mn0);
            float p1 = __expf(sacc[j][1] - mn0);
            float p2 = __expf(sacc[j][2] - mn1);
            float p3 = __expf(sacc[j][3] - mn1);
            s0 += p0 + p1; s1 += p2 + p3;
            int cc = j * 8 + 2 * tg;
            *(__half2*)&sS[(wrow + gr) * SSTRH + cc]     = __floats2half2_rn(p0, p1);
            *(__half2*)&sS[(wrow + gr + 8) * SSTRH + cc] = __floats2half2_rn(p2, p3);
        }
        s0 += __shfl_xor_sync(0xffffffffu, s0, 1);
        s0 += __shfl_xor_sync(0xffffffffu, s0, 2);
        s1 += __shfl_xor_sync(0xffffffffu, s1, 1);
        s1 += __shfl_xor_sync(0xffffffffu, s1, 2);
        l0 = l0 * f0 + s0;
        l1 = l1 * f1 + s1;

        #pragma unroll
        for (int n = 0; n < 16; n++) {
            o[n][0] *= f0; o[n][1] *= f0; o[n][2] *= f1; o[n][3] *= f1;
        }
        __syncwarp();

        // ---- PV: O += P V (16 rows x 128 cols per warp) ----
        #pragma unroll
        for (int ks = 0; ks < 4; ks++) {
            int kk = ks * 16;
            unsigned a[4];
            ldm_x4(a, sS + (wrow + a_r) * SSTRH + kk + a_c);
            #pragma unroll
            for (int n = 0; n < 16; n++) {
                unsigned bb[2];
                ldm_x2t(bb, V + (kk + v_r) * VSTRH + n * 8);
                mma16(o[n], a, bb);
            }
        }
        __syncwarp();
    }

    // epilogue -> half
    float inv0 = 1.f / l0, inv1 = 1.f / l1;
    size_t r0 = (size_t)(b * SS + qbase + wrow + gr) * (HH * VD);
    size_t r1 = r0 + 8 * (HH * VD);
    #pragma unroll
    for (int n = 0; n < 16; n++) {
        int cc = h * VD + n * 8 + 2 * tg;
        *(__half2*)(aoh + r0 + cc) = __floats2half2_rn(o[n][0] * inv0, o[n][1] * inv0);
        *(__half2*)(aoh + r1 + cc) = __floats2half2_rn(o[n][2] * inv1, o[n][3] * inv1);
    }
}

// ---------------------------------------------------------------------------
extern "C" void kernel_launch(void* const* d_in, const int* in_sizes, int n_in,
                              void* d_out, int out_size) {
    const float* x     = (const float*)d_in[0];
    const float* wq    = (const float*)d_in[1];
    const float* wkv_a = (const float*)d_in[2];
    const float* wkv_b = (const float*)d_in[3];
    const float* wo    = (const float*)d_in[4];
    const float* kvs   = (const float*)d_in[5];
    float* out = (float*)d_out;

    float *q, *kva;
    __half *qh, *kpeh, *ckvh, *kvh, *aoh, *xh, *wqT, *wkvaT, *wkvbT, *woT;
    cudaGetSymbolAddress((void**)&q,     g_q);
    cudaGetSymbolAddress((void**)&kva,   g_kva);
    cudaGetSymbolAddress((void**)&qh,    g_qh);
    cudaGetSymbolAddress((void**)&kpeh,  g_kpeh);
    cudaGetSymbolAddress((void**)&ckvh,  g_ckvh);
    cudaGetSymbolAddress((void**)&kvh,   g_kvh);
    cudaGetSymbolAddress((void**)&aoh,   g_aoh);
    cudaGetSymbolAddress((void**)&xh,    g_xh);
    cudaGetSymbolAddress((void**)&wqT,   g_wqT);
    cudaGetSymbolAddress((void**)&wkvaT, g_wkvaT);
    cudaGetSymbolAddress((void**)&wkvbT, g_wkvbT);
    cudaGetSymbolAddress((void**)&woT,   g_woT);

    static bool attr_done = false;
    if (!attr_done) {
        cudaFuncSetAttribute(flash_h,
                             cudaFuncAttributeMaxDynamicSharedMemorySize, (int)FSMEM);
        cudaFuncSetAttribute(hgemm<float>,
                             cudaFuncAttributeMaxDynamicSharedMemorySize, (int)GSMEM);
        cudaFuncSetAttribute(hgemm<__half>,
                             cudaFuncAttributeMaxDynamicSharedMemorySize, (int)GSMEM);
        attr_done = true;
    }

    // prep: half x, transposed half weights
    f2h_copy<<<1024, 256>>>(x, xh, RWS * EE / 4);
    transpose_h<<<dim3(64, 96),  dim3(32, 8)>>>(wq,    wqT,   2048, 3072, 3072);
    transpose_h<<<dim3(64, 20),  dim3(32, 8)>>>(wkv_a, wkvaT, 2048, 576,  640);
    transpose_h<<<dim3(16, 128), dim3(32, 8)>>>(wkv_b, wkvbT, 512,  4096, 4096);
    transpose_h<<<dim3(64, 64),  dim3(32, 8)>>>(wo,    woT,   2048, 2048, 2048);

    // q = x @ wq : [4096, 3072] fp32
    hgemm<float><<<dim3(24, 32), 256, GSMEM>>>(xh, wqT, q, 3072, 2048);
    // kva = x @ wkv_a : [4096, 576] fp32
    hgemm<float><<<dim3(5, 32), 256, GSMEM>>>(xh, wkvaT, kva, 576, 2048);
    // ckvh = rmsnorm(kva[:, :512]) * kv_norm_scale (half)
    rmsnorm_kernel<<<RWS, 128>>>(kva, kvs, ckvh);
    // rope + pack q -> qh, k_pe -> kpeh
    rope_pack<<<RWS, 256>>>(q, kva, qh, kpeh);
    // kvh = ckv @ wkv_b : [4096, 4096] half
    hgemm<__half><<<dim3(32, 32), 256, GSMEM>>>(ckvh, wkvbT, kvh, 4096, 512);
    // attention -> aoh : [4096, 2048] half
    flash_h<<<dim3(SS / FBM, HH, BB), 256, FSMEM>>>(qh, kvh, kpeh, aoh);
    // out = ao @ wo : [4096, 2048] fp32
    hgemm<float><<<dim3(16, 32), 256, GSMEM>>>(aoh, woT, out, 2048, 2048);
}

// round 7
// speedup vs baseline: 11.1214x; 1.0636x over previous
#include <cuda_runtime.h>
#include <cuda_fp16.h>
#include <math.h>

// Problem constants
#define BB 2
#define SS 2048
#define EE 2048
#define HH 16
#define NOPE 128
#define ROPE_D 64
#define QHD 192          // NOPE + ROPE
#define LORA 512
#define VD 128
#define RWS (BB*SS)      // 4096 rows

// Scratch (device globals; no allocation allowed)
__device__ float  g_q[(size_t)RWS * (HH * QHD)];       // fp32 q (pre-rope)
__device__ float  g_kva[(size_t)RWS * (LORA + ROPE_D)];
__device__ __half g_qh[(size_t)RWS * (HH * QHD)];      // roped q, half
__device__ __half g_kpeh[(size_t)RWS * ROPE_D];        // roped k_pe, half
__device__ __half g_ckvh[(size_t)RWS * LORA];
__device__ __half g_kvh[(size_t)RWS * (HH * (NOPE + VD))];
__device__ __half g_aoh[(size_t)RWS * (HH * VD)];
__device__ __half g_xh[(size_t)RWS * EE];
__device__ __half g_wqT[(size_t)3072 * 2048];
__device__ __half g_wkvaT[(size_t)640 * 2048];         // padded 576->640
__device__ __half g_wkvbT[(size_t)4096 * 512];
__device__ __half g_woT[(size_t)2048 * 2048];

// ---------------- helpers ----------------
__device__ __forceinline__ void mma16(float* c, const unsigned* a, const unsigned* b) {
    asm volatile("mma.sync.aligned.m16n8k16.row.col.f32.f16.f16.f32 "
        "{%0,%1,%2,%3}, {%4,%5,%6,%7}, {%8,%9}, {%0,%1,%2,%3};"
        : "+f"(c[0]), "+f"(c[1]), "+f"(c[2]), "+f"(c[3])
        : "r"(a[0]), "r"(a[1]), "r"(a[2]), "r"(a[3]), "r"(b[0]), "r"(b[1]));
}
__device__ __forceinline__ void ldm_x4(unsigned* r, const void* p) {
    unsigned s = (unsigned)__cvta_generic_to_shared(p);
    asm volatile("ldmatrix.sync.aligned.m8n8.x4.shared.b16 {%0,%1,%2,%3}, [%4];"
        : "=r"(r[0]), "=r"(r[1]), "=r"(r[2]), "=r"(r[3]) : "r"(s));
}
__device__ __forceinline__ void ldm_x4t(unsigned* r, const void* p) {
    unsigned s = (unsigned)__cvta_generic_to_shared(p);
    asm volatile("ldmatrix.sync.aligned.m8n8.x4.trans.shared.b16 {%0,%1,%2,%3}, [%4];"
        : "=r"(r[0]), "=r"(r[1]), "=r"(r[2]), "=r"(r[3]) : "r"(s));
}
__device__ __forceinline__ void cp16(void* dst, const void* src) {
    unsigned d = (unsigned)__cvta_generic_to_shared(dst);
    asm volatile("cp.async.cg.shared.global [%0], [%1], 16;" :: "r"(d), "l"(src));
}
__device__ __forceinline__ void cp_commit() {
    asm volatile("cp.async.commit_group;");
}
template<int N> __device__ __forceinline__ void cp_wait() {
    asm volatile("cp.async.wait_group %0;" :: "n"(N));
}
__device__ __forceinline__ void st2o(float* p, float x, float y) {
    *(float2*)p = make_float2(x, y);
}
__device__ __forceinline__ void st2o(__half* p, float x, float y) {
    *(__half2*)p = __floats2half2_rn(x, y);
}

// ---------------------------------------------------------------------------
// FP16 tensor-core GEMM: C[M,N] = A[M,K] @ BT[N,K]^T. A,BT half; C float/half.
// 128x128 tile, BK=32, 256 thr = 8 warps (2Mx4N, 64x32 each), 3-stage cp.async.
// One barrier per K-block.
// ---------------------------------------------------------------------------
#define ASTRH 40
#define STG_B (2 * 128 * ASTRH * 2)   // A(10240B) + B(10240B)
#define GSMEM (3 * STG_B)

template<typename OutT>
__global__ void __launch_bounds__(256, 2) hgemm(const __half* __restrict__ A,
                                                const __half* __restrict__ BT,
                                                OutT* __restrict__ C,
                                                int N, int K) {
    extern __shared__ __half hs[];

    int tid = threadIdx.x, wid = tid >> 5, lane = tid & 31;
    int bm = blockIdx.y * 128, bn = blockIdx.x * 128;
    int wm = (wid >> 2) * 64, wn = (wid & 3) * 32;
    int gr = lane >> 2, tg = lane & 3;

    int a_r = (lane & 7) + ((lane >> 3) & 1) * 8;   // ldmatrix x4 A row map
    int a_c = ((lane >> 4) & 1) * 8;
    int b_r = (lane & 7) + ((lane >> 4) & 1) * 8;   // ldmatrix x4 B (j-pair) map
    int b_c = ((lane >> 3) & 1) * 8;

    int nkb = K >> 5;

    auto issue = [&](int kb, int slot) {
        __half* sA = hs + slot * (STG_B / 2);
        __half* sB = sA + 128 * ASTRH;
        int k0 = kb * 32;
        #pragma unroll
        for (int p = 0; p < 2; p++) {
            int idx = tid + p * 256;         // 0..511
            int row = idx >> 2, c = idx & 3; // 4 x 16B chunks per row
            cp16(sA + row * ASTRH + c * 8, A + (size_t)(bm + row) * K + k0 + c * 8);
        }
        #pragma unroll
        for (int p = 0; p < 2; p++) {
            int idx = tid + p * 256;
            int row = idx >> 2, c = idx & 3;
            cp16(sB + row * ASTRH + c * 8, BT + (size_t)(bn + row) * K + k0 + c * 8);
        }
        cp_commit();
    };

    issue(0, 0);
    if (nkb > 1) issue(1, 1);

    float acc[4][4][4];
    #pragma unroll
    for (int i = 0; i < 4; i++)
        #pragma unroll
        for (int j = 0; j < 4; j++)
            #pragma unroll
            for (int t = 0; t < 4; t++) acc[i][j][t] = 0.f;

    int slot = 0;
    for (int kb = 0; kb < nkb; kb++) {
        if (kb + 1 < nkb) cp_wait<1>(); else cp_wait<0>();
        __syncthreads();
        if (kb + 2 < nkb) {
            int ns = slot + 2; if (ns >= 3) ns -= 3;
            issue(kb + 2, ns);
        }

        __half* sA = hs + slot * (STG_B / 2);
        __half* sB = sA + 128 * ASTRH;

        #pragma unroll
        for (int ks = 0; ks < 2; ks++) {
            int kk = ks * 16;
            unsigned a[4][4], b[2][4];
            #pragma unroll
            for (int i = 0; i < 4; i++)
                ldm_x4(a[i], sA + (wm + i * 16 + a_r) * ASTRH + kk + a_c);
            #pragma unroll
            for (int j = 0; j < 2; j++)
                ldm_x4(b[j], sB + (wn + j * 16 + b_r) * ASTRH + kk + b_c);
            #pragma unroll
            for (int i = 0; i < 4; i++)
                #pragma unroll
                for (int j = 0; j < 2; j++) {
                    mma16(acc[i][j * 2],     a[i], b[j]);
                    mma16(acc[i][j * 2 + 1], a[i], b[j] + 2);
                }
        }
        slot++; if (slot >= 3) slot = 0;
    }

    #pragma unroll
    for (int i = 0; i < 4; i++) {
        int r0 = bm + wm + i * 16 + gr;
        #pragma unroll
        for (int j = 0; j < 4; j++) {
            int cc = bn + wn + j * 8 + 2 * tg;
            if (cc < N) {
                st2o(C + (size_t)r0 * N + cc, acc[i][j][0], acc[i][j][1]);
                st2o(C + (size_t)(r0 + 8) * N + cc, acc[i][j][2], acc[i][j][3]);
            }
        }
    }
}

// ---------------------------------------------------------------------------
// Prep kernels
// ---------------------------------------------------------------------------
__global__ void f2h_copy(const float* __restrict__ src, __half* __restrict__ dst,
                         int n4) {
    for (int i = blockIdx.x * blockDim.x + threadIdx.x; i < n4; i += gridDim.x * blockDim.x) {
        float4 v = *(const float4*)(src + i * 4);
        __half2* d = (__half2*)(dst + i * 4);
        d[0] = __floats2half2_rn(v.x, v.y);
        d[1] = __floats2half2_rn(v.z, v.w);
    }
}

// transpose + half: src[K,N] fp32 -> dst[Npad,K] half (pad rows zeroed)
__global__ void transpose_h(const float* __restrict__ src, __half* __restrict__ dst,
                            int K, int N, int Npad) {
    __shared__ float t[32][33];
    int kb = blockIdx.x * 32, nb = blockIdx.y * 32;
    int tx = threadIdx.x, ty = threadIdx.y;
    #pragma unroll
    for (int j = 0; j < 4; j++) {
        int k = kb + ty + j * 8, n = nb + tx;
        float v = 0.f;
        if (k < K && n < N) v = src[(size_t)k * N + n];
        t[ty + j * 8][tx] = v;
    }
    __syncthreads();
    #pragma unroll
    for (int j = 0; j < 4; j++) {
        int n = nb + ty + j * 8, k = kb + tx;
        if (n < Npad && k < K) dst[(size_t)n * K + k] = __float2half(t[tx][ty + j * 8]);
    }
}

// RMSNorm over first LORA cols of kva -> ckvh (half)
__global__ void __launch_bounds__(128) rmsnorm_kernel(const float* __restrict__ kva,
                                                      const float* __restrict__ kvs,
                                                      __half* __restrict__ ckv) {
    int r = blockIdx.x;
    int tid = threadIdx.x;
    const float* row = kva + (size_t)r * (LORA + ROPE_D);

    float x[4];
    float ss = 0.f;
    #pragma unroll
    for (int j = 0; j < 4; j++) {
        x[j] = row[tid + 128 * j];
        ss += x[j] * x[j];
    }
    #pragma unroll
    for (int o = 16; o > 0; o >>= 1)
        ss += __shfl_xor_sync(0xffffffffu, ss, o);

    __shared__ float wsum[4];
    if ((tid & 31) == 0) wsum[tid >> 5] = ss;
    __syncthreads();
    float tot = wsum[0] + wsum[1] + wsum[2] + wsum[3];
    float rms = rsqrtf(tot / (float)LORA + 1e-6f);

    __half* orow = ckv + (size_t)r * LORA;
    #pragma unroll
    for (int j = 0; j < 4; j++) {
        int c = tid + 128 * j;
        orow[c] = __float2half(x[j] * rms * kvs[c]);
    }
}

// rope + pack q (fp32 -> half, rope on pe dims) and k_pe (kva -> half roped)
__global__ void __launch_bounds__(256) rope_pack(const float* __restrict__ q,
                                                 const float* __restrict__ kva,
                                                 __half* __restrict__ qh,
                                                 __half* __restrict__ kpeh) {
    int r = blockIdx.x;
    int s = r % SS;
    int t = threadIdx.x;
    const float* qr = q + (size_t)r * (HH * QHD);
    __half* qo = qh + (size_t)r * (HH * QHD);

    // nope dims: straight convert (16 heads x 128 = 2048)
    #pragma unroll
    for (int p = 0; p < 8; p++) {
        int i = t + p * 256;
        int head = i >> 7, d = i & 127;
        int off = head * QHD + d;
        qo[off] = __float2half(qr[off]);
    }
    // q pe pairs: 16 heads x 32 = 512 pairs
    #pragma unroll
    for (int p = 0; p < 2; p++) {
        int i = t + p * 256;
        int head = i >> 5, ii = i & 31;
        float inv = powf(10000.f, -(float)ii / 32.f);
        float sn, cs;
        sincosf((float)s * inv, &sn, &cs);
        int off = head * QHD + NOPE + ii;
        float x1 = qr[off], x2 = qr[off + 32];
        qo[off]      = __float2half(x1 * cs - x2 * sn);
        qo[off + 32] = __float2half(x2 * cs + x1 * sn);
    }
    // k_pe pairs: 32
    if (t < 32) {
        float inv = powf(10000.f, -(float)t / 32.f);
        float sn, cs;
        sincosf((float)s * inv, &sn, &cs);
        const float* kp = kva + (size_t)r * (LORA + ROPE_D) + LORA;
        __half* ko = kpeh + (size_t)r * ROPE_D;
        float x1 = kp[t], x2 = kp[t + 32];
        ko[t]      = __float2half(x1 * cs - x2 * sn);
        ko[t + 32] = __float2half(x2 * cs + x1 * sn);
    }
}

// ---------------------------------------------------------------------------
// Flash attention (causal), FP16 mma. BM=128, BN=64, 256 thr = 8 warps.
// Q frags in registers; K/V double-buffered via cp.async; all operands half.
// ---------------------------------------------------------------------------
#define FBM 128
#define FBN 64
#define KSTRH 200
#define VSTRH 136
#define SSTRH 72
#define SK_W (64 * KSTRH)      // halves per K stage
#define SV_W (64 * VSTRH)
#define FSMEM ((2*SK_W + 2*SV_W + FBM*SSTRH) * 2)

__global__ void __launch_bounds__(256, 1) flash_h(const __half* __restrict__ qh,
                                                  const __half* __restrict__ kvh,
                                                  const __half* __restrict__ kpeh,
                                                  __half* __restrict__ aoh) {
    extern __shared__ __half fh[];
    __half* sK = fh;                    // [2][SK_W]
    __half* sV = fh + 2 * SK_W;         // [2][SV_W]
    __half* sS = fh + 2 * SK_W + 2 * SV_W;

    int qt = gridDim.x - 1 - blockIdx.x;   // heavy tiles first
    int h = blockIdx.y, b = blockIdx.z;
    int tid = threadIdx.x, wid = tid >> 5, lane = tid & 31;
    int gr = lane >> 2, tg = lane & 3;
    int qbase = qt * FBM;
    int wrow = wid * 16;

    int a_r = (lane & 7) + ((lane >> 3) & 1) * 8;
    int a_c = ((lane >> 4) & 1) * 8;
    int k_r = (lane & 7) + ((lane >> 4) & 1) * 8;  // K x4 j-pair map
    int k_c = ((lane >> 3) & 1) * 8;
    int v_r = lane & 15;                            // V x4t map
    int v_c = ((lane >> 4) & 1) * 8;

    // --- stage Q through sK overlay (128 x 200 halves = 2*SK_W exactly)
    __half* sQ = fh;
    #pragma unroll
    for (int p = 0; p < 12; p++) {
        int idx = tid + p * 256;           // 0..3071
        int row = idx / 24, c = idx - row * 24;
        int r = b * SS + qbase + row;
        cp16(sQ + row * KSTRH + c * 8,
             qh + (size_t)r * (HH * QHD) + h * QHD + c * 8);
    }
    cp_commit();
    cp_wait<0>();
    __syncthreads();

    unsigned qf[12][4];
    #pragma unroll
    for (int ks = 0; ks < 12; ks++)
        ldm_x4(qf[ks], sQ + (wrow + a_r) * KSTRH + ks * 16 + a_c);
    __syncthreads();   // Q consumed; sK area free

    auto load_kv = [&](int kbase, int stg) {
        __half* K = sK + stg * SK_W;
        __half* V = sV + stg * SV_W;
        #pragma unroll
        for (int p = 0; p < 6; p++) {
            int idx = tid + p * 256;       // 0..1535
            int row = idx / 24, c = idx - row * 24;
            int r = b * SS + kbase + row;
            const __half* src = (c < 16)
                ? kvh  + (size_t)r * (HH * (NOPE + VD)) + h * (NOPE + VD) + c * 8
                : kpeh + (size_t)r * ROPE_D + (c - 16) * 8;
            cp16(K + row * KSTRH + c * 8, src);
        }
        #pragma unroll
        for (int p = 0; p < 4; p++) {
            int idx = tid + p * 256;       // 0..1023
            int row = idx >> 4, c = idx & 15;
            int r = b * SS + kbase + row;
            cp16(V + row * VSTRH + c * 8,
                 kvh + (size_t)r * (HH * (NOPE + VD)) + h * (NOPE + VD) + NOPE + c * 8);
        }
        cp_commit();
    };

    float o[16][4];
    #pragma unroll
    for (int n = 0; n < 16; n++)
        #pragma unroll
        for (int t = 0; t < 4; t++) o[n][t] = 0.f;
    float m0 = -1e30f, m1 = -1e30f, l0 = 0.f, l1 = 0.f;
    const float scale = 0.07216878364870323f;  // 192^-0.5

    int ktmax = (qbase + FBM) / FBN;
    load_kv(0, 0);

    for (int kt = 0; kt < ktmax; kt++) {
        int kbase = kt * FBN;
        int stg = kt & 1;
        cp_wait<0>();
        __syncthreads();
        if (kt + 1 < ktmax) load_kv(kbase + FBN, stg ^ 1);

        __half* K = sK + stg * SK_W;
        __half* V = sV + stg * SV_W;

        // ---- scores: S = Q K^T (16 rows x 64 cols per warp) ----
        float sacc[8][4];
        #pragma unroll
        for (int j = 0; j < 8; j++)
            #pragma unroll
            for (int t = 0; t < 4; t++) sacc[j][t] = 0.f;

        #pragma unroll
        for (int ks = 0; ks < 12; ks++) {
            int kk = ks * 16;
            #pragma unroll
            for (int j = 0; j < 8; j += 2) {
                unsigned bb[4];
                ldm_x4(bb, K + (j * 8 + k_r) * KSTRH + kk + k_c);
                mma16(sacc[j],     qf[ks], bb);
                mma16(sacc[j + 1], qf[ks], bb + 2);
            }
        }

        // ---- scale + (conditional) causal mask + online softmax ----
        int qr0 = qbase + wrow + gr;
        int qr1 = qr0 + 8;
        float mx0 = -1e30f, mx1 = -1e30f;
        if (kbase + FBN - 1 <= qbase + wrow) {
            // tile fully visible for all rows of this warp
            #pragma unroll
            for (int j = 0; j < 8; j++) {
                sacc[j][0] *= scale; sacc[j][1] *= scale;
                sacc[j][2] *= scale; sacc[j][3] *= scale;
                mx0 = fmaxf(mx0, fmaxf(sacc[j][0], sacc[j][1]));
                mx1 = fmaxf(mx1, fmaxf(sacc[j][2], sacc[j][3]));
            }
        } else {
            #pragma unroll
            for (int j = 0; j < 8; j++) {
                int c0 = kbase + j * 8 + 2 * tg;
                sacc[j][0] = (c0     <= qr0) ? sacc[j][0] * scale : -1e30f;
                sacc[j][1] = (c0 + 1 <= qr0) ? sacc[j][1] * scale : -1e30f;
                sacc[j][2] = (c0     <= qr1) ? sacc[j][2] * scale : -1e30f;
                sacc[j][3] = (c0 + 1 <= qr1) ? sacc[j][3] * scale : -1e30f;
                mx0 = fmaxf(mx0, fmaxf(sacc[j][0], sacc[j][1]));
                mx1 = fmaxf(mx1, fmaxf(sacc[j][2], sacc[j][3]));
            }
        }
        mx0 = fmaxf(mx0, __shfl_xor_sync(0xffffffffu, mx0, 1));
        mx0 = fmaxf(mx0, __shfl_xor_sync(0xffffffffu, mx0, 2));
        mx1 = fmaxf(mx1, __shfl_xor_sync(0xffffffffu, mx1, 1));
        mx1 = fmaxf(mx1, __shfl_xor_sync(0xffffffffu, mx1, 2));

        float mn0 = fmaxf(m0, mx0), mn1 = fmaxf(m1, mx1);
        float f0 = __expf(m0 - mn0), f1 = __expf(m1 - mn1);
        m0 = mn0; m1 = mn1;

        float s0 = 0.f, s1 = 0.f;
        #pragma unroll
        for (int j = 0; j < 8; j++) {
            float p0 = __expf(sacc[j][0] - mn0);
            float p1 = __expf(sacc[j][1] - mn0);
            float p2 = __expf(sacc[j][2] - mn1);
            float p3 = __expf(sacc[j][3] - mn1);
            s0 += p0 + p1; s1 += p2 + p3;
            int cc = j * 8 + 2 * tg;
            *(__half2*)&sS[(wrow + gr) * SSTRH + cc]     = __floats2half2_rn(p0, p1);
            *(__half2*)&sS[(wrow + gr + 8) * SSTRH + cc] = __floats2half2_rn(p2, p3);
        }
        s0 += __shfl_xor_sync(0xffffffffu, s0, 1);
        s0 += __shfl_xor_sync(0xffffffffu, s0, 2);
        s1 += __shfl_xor_sync(0xffffffffu, s1, 1);
        s1 += __shfl_xor_sync(0xffffffffu, s1, 2);
        l0 = l0 * f0 + s0;
        l1 = l1 * f1 + s1;

        #pragma unroll
        for (int n = 0; n < 16; n++) {
            o[n][0] *= f0; o[n][1] *= f0; o[n][2] *= f1; o[n][3] *= f1;
        }
        __syncwarp();

        // ---- PV: O += P V (16 rows x 128 cols per warp) ----
        #pragma unroll
        for (int ks = 0; ks < 4; ks++) {
            int kk = ks * 16;
            unsigned a[4];
            ldm_x4(a, sS + (wrow + a_r) * SSTRH + kk + a_c);
            #pragma unroll
            for (int n = 0; n < 16; n += 2) {
                unsigned bb[4];
                ldm_x4t(bb, V + (kk + v_r) * VSTRH + n * 8 + v_c);
                mma16(o[n],     a, bb);
                mma16(o[n + 1], a, bb + 2);
            }
        }
        __syncwarp();
    }

    // epilogue -> half
    float inv0 = 1.f / l0, inv1 = 1.f / l1;
    size_t r0 = (size_t)(b * SS + qbase + wrow + gr) * (HH * VD);
    size_t r1 = r0 + 8 * (HH * VD);
    #pragma unroll
    for (int n = 0; n < 16; n++) {
        int cc = h * VD + n * 8 + 2 * tg;
        *(__half2*)(aoh + r0 + cc) = __floats2half2_rn(o[n][0] * inv0, o[n][1] * inv0);
        *(__half2*)(aoh + r1 + cc) = __floats2half2_rn(o[n][2] * inv1, o[n][3] * inv1);
    }
}

// ---------------------------------------------------------------------------
extern "C" void kernel_launch(void* const* d_in, const int* in_sizes, int n_in,
                              void* d_out, int out_size) {
    const float* x     = (const float*)d_in[0];
    const float* wq    = (const float*)d_in[1];
    const float* wkv_a = (const float*)d_in[2];
    const float* wkv_b = (const float*)d_in[3];
    const float* wo    = (const float*)d_in[4];
    const float* kvs   = (const float*)d_in[5];
    float* out = (float*)d_out;

    float *q, *kva;
    __half *qh, *kpeh, *ckvh, *kvh, *aoh, *xh, *wqT, *wkvaT, *wkvbT, *woT;
    cudaGetSymbolAddress((void**)&q,     g_q);
    cudaGetSymbolAddress((void**)&kva,   g_kva);
    cudaGetSymbolAddress((void**)&qh,    g_qh);
    cudaGetSymbolAddress((void**)&kpeh,  g_kpeh);
    cudaGetSymbolAddress((void**)&ckvh,  g_ckvh);
    cudaGetSymbolAddress((void**)&kvh,   g_kvh);
    cudaGetSymbolAddress((void**)&aoh,   g_aoh);
    cudaGetSymbolAddress((void**)&xh,    g_xh);
    cudaGetSymbolAddress((void**)&wqT,   g_wqT);
    cudaGetSymbolAddress((void**)&wkvaT, g_wkvaT);
    cudaGetSymbolAddress((void**)&wkvbT, g_wkvbT);
    cudaGetSymbolAddress((void**)&woT,   g_woT);

    static bool attr_done = false;
    if (!attr_done) {
        cudaFuncSetAttribute(flash_h,
                             cudaFuncAttributeMaxDynamicSharedMemorySize, (int)FSMEM);
        cudaFuncSetAttribute(hgemm<float>,
                             cudaFuncAttributeMaxDynamicSharedMemorySize, (int)GSMEM);
        cudaFuncSetAttribute(hgemm<__half>,
                             cudaFuncAttributeMaxDynamicSharedMemorySize, (int)GSMEM);
        attr_done = true;
    }

    // prep: half x, transposed half weights
    f2h_copy<<<1024, 256>>>(x, xh, RWS * EE / 4);
    transpose_h<<<dim3(64, 96),  dim3(32, 8)>>>(wq,    wqT,   2048, 3072, 3072);
    transpose_h<<<dim3(64, 20),  dim3(32, 8)>>>(wkv_a, wkvaT, 2048, 576,  640);
    transpose_h<<<dim3(16, 128), dim3(32, 8)>>>(wkv_b, wkvbT, 512,  4096, 4096);
    transpose_h<<<dim3(64, 64),  dim3(32, 8)>>>(wo,    woT,   2048, 2048, 2048);

    // q = x @ wq : [4096, 3072] fp32
    hgemm<float><<<dim3(24, 32), 256, GSMEM>>>(xh, wqT, q, 3072, 2048);
    // kva = x @ wkv_a : [4096, 576] fp32
    hgemm<float><<<dim3(5, 32), 256, GSMEM>>>(xh, wkvaT, kva, 576, 2048);
    // ckvh = rmsnorm(kva[:, :512]) * kv_norm_scale (half)
    rmsnorm_kernel<<<RWS, 128>>>(kva, kvs, ckvh);
    // rope + pack q -> qh, k_pe -> kpeh
    rope_pack<<<RWS, 256>>>(q, kva, qh, kpeh);
    // kvh = ckv @ wkv_b : [4096, 4096] half
    hgemm<__half><<<dim3(32, 32), 256, GSMEM>>>(ckvh, wkvbT, kvh, 4096, 512);
    // attention -> aoh : [4096, 2048] half
    flash_h<<<dim3(SS / FBM, HH, BB), 256, FSMEM>>>(qh, kvh, kpeh, aoh);
    // out = ao @ wo : [4096, 2048] fp32
    hgemm<float><<<dim3(16, 32), 256, GSMEM>>>(aoh, woT, out, 2048, 2048);
}

// round 8
// speedup vs baseline: 11.4279x; 1.0276x over previous
#include <cuda_runtime.h>
#include <cuda_fp16.h>
#include <math.h>

// Problem constants
#define BB 2
#define SS 2048
#define EE 2048
#define HH 16
#define NOPE 128
#define ROPE_D 64
#define QHD 192          // NOPE + ROPE
#define LORA 512
#define VD 128
#define RWS (BB*SS)      // 4096 rows
#define QAW 3712         // fused q(3072) + kva(576->640 pad) width

// Scratch (device globals; no allocation allowed)
__device__ float  g_qkva[(size_t)RWS * QAW];           // fused x@[wq|wkv_a]
__device__ __half g_qh[(size_t)RWS * (HH * QHD)];      // roped q, half
__device__ __half g_kpeh[(size_t)RWS * ROPE_D];        // roped k_pe, half
__device__ __half g_ckvh[(size_t)RWS * LORA];
__device__ __half g_kvh[(size_t)RWS * (HH * (NOPE + VD))];
__device__ __half g_aoh[(size_t)RWS * (HH * VD)];
__device__ __half g_xh[(size_t)RWS * EE];
__device__ __half g_wqaT[(size_t)QAW * 2048];          // [wq^T ; wkv_a^T(pad)]
__device__ __half g_wkvbT[(size_t)4096 * 512];
__device__ __half g_woT[(size_t)2048 * 2048];
__device__ float  g_cs[SS * ROPE_D];                   // cos[0..31], sin[32..63]

// ---------------- helpers ----------------
__device__ __forceinline__ void mma16(float* c, const unsigned* a, const unsigned* b) {
    asm volatile("mma.sync.aligned.m16n8k16.row.col.f32.f16.f16.f32 "
        "{%0,%1,%2,%3}, {%4,%5,%6,%7}, {%8,%9}, {%0,%1,%2,%3};"
        : "+f"(c[0]), "+f"(c[1]), "+f"(c[2]), "+f"(c[3])
        : "r"(a[0]), "r"(a[1]), "r"(a[2]), "r"(a[3]), "r"(b[0]), "r"(b[1]));
}
__device__ __forceinline__ void ldm_x4(unsigned* r, const void* p) {
    unsigned s = (unsigned)__cvta_generic_to_shared(p);
    asm volatile("ldmatrix.sync.aligned.m8n8.x4.shared.b16 {%0,%1,%2,%3}, [%4];"
        : "=r"(r[0]), "=r"(r[1]), "=r"(r[2]), "=r"(r[3]) : "r"(s));
}
__device__ __forceinline__ void ldm_x4t(unsigned* r, const void* p) {
    unsigned s = (unsigned)__cvta_generic_to_shared(p);
    asm volatile("ldmatrix.sync.aligned.m8n8.x4.trans.shared.b16 {%0,%1,%2,%3}, [%4];"
        : "=r"(r[0]), "=r"(r[1]), "=r"(r[2]), "=r"(r[3]) : "r"(s));
}
__device__ __forceinline__ void cp16(void* dst, const void* src) {
    unsigned d = (unsigned)__cvta_generic_to_shared(dst);
    asm volatile("cp.async.cg.shared.global [%0], [%1], 16;" :: "r"(d), "l"(src));
}
__device__ __forceinline__ void cp_commit() {
    asm volatile("cp.async.commit_group;");
}
template<int N> __device__ __forceinline__ void cp_wait() {
    asm volatile("cp.async.wait_group %0;" :: "n"(N));
}
__device__ __forceinline__ void st2o(float* p, float x, float y) {
    *(float2*)p = make_float2(x, y);
}
__device__ __forceinline__ void st2o(__half* p, float x, float y) {
    *(__half2*)p = __floats2half2_rn(x, y);
}

// ---------------------------------------------------------------------------
// FP16 tensor-core GEMM: C[M,N] = A[M,K] @ BT[N,K]^T. A,BT half; C float/half.
// 128x128 tile, BK=32, 256 thr = 8 warps (2Mx4N, 64x32 each), 3-stage cp.async.
// ---------------------------------------------------------------------------
#define ASTRH 40
#define STG_B (2 * 128 * ASTRH * 2)   // A(10240B) + B(10240B)
#define GSMEM (3 * STG_B)

template<typename OutT>
__global__ void __launch_bounds__(256, 2) hgemm(const __half* __restrict__ A,
                                                const __half* __restrict__ BT,
                                                OutT* __restrict__ C,
                                                int N, int K) {
    extern __shared__ __half hs[];

    int tid = threadIdx.x, wid = tid >> 5, lane = tid & 31;
    int bm = blockIdx.y * 128, bn = blockIdx.x * 128;
    int wm = (wid >> 2) * 64, wn = (wid & 3) * 32;
    int gr = lane >> 2, tg = lane & 3;

    int a_r = (lane & 7) + ((lane >> 3) & 1) * 8;   // ldmatrix x4 A row map
    int a_c = ((lane >> 4) & 1) * 8;
    int b_r = (lane & 7) + ((lane >> 4) & 1) * 8;   // ldmatrix x4 B (j-pair) map
    int b_c = ((lane >> 3) & 1) * 8;

    int nkb = K >> 5;

    auto issue = [&](int kb, int slot) {
        __half* sA = hs + slot * (STG_B / 2);
        __half* sB = sA + 128 * ASTRH;
        int k0 = kb * 32;
        #pragma unroll
        for (int p = 0; p < 2; p++) {
            int idx = tid + p * 256;
            int row = idx >> 2, c = idx & 3;
            cp16(sA + row * ASTRH + c * 8, A + (size_t)(bm + row) * K + k0 + c * 8);
        }
        #pragma unroll
        for (int p = 0; p < 2; p++) {
            int idx = tid + p * 256;
            int row = idx >> 2, c = idx & 3;
            cp16(sB + row * ASTRH + c * 8, BT + (size_t)(bn + row) * K + k0 + c * 8);
        }
        cp_commit();
    };

    issue(0, 0);
    if (nkb > 1) issue(1, 1);

    float acc[4][4][4];
    #pragma unroll
    for (int i = 0; i < 4; i++)
        #pragma unroll
        for (int j = 0; j < 4; j++)
            #pragma unroll
            for (int t = 0; t < 4; t++) acc[i][j][t] = 0.f;

    int slot = 0;
    for (int kb = 0; kb < nkb; kb++) {
        if (kb + 1 < nkb) cp_wait<1>(); else cp_wait<0>();
        __syncthreads();
        if (kb + 2 < nkb) {
            int ns = slot + 2; if (ns >= 3) ns -= 3;
            issue(kb + 2, ns);
        }

        __half* sA = hs + slot * (STG_B / 2);
        __half* sB = sA + 128 * ASTRH;

        #pragma unroll
        for (int ks = 0; ks < 2; ks++) {
            int kk = ks * 16;
            unsigned a[4][4], b[2][4];
            #pragma unroll
            for (int i = 0; i < 4; i++)
                ldm_x4(a[i], sA + (wm + i * 16 + a_r) * ASTRH + kk + a_c);
            #pragma unroll
            for (int j = 0; j < 2; j++)
                ldm_x4(b[j], sB + (wn + j * 16 + b_r) * ASTRH + kk + b_c);
            #pragma unroll
            for (int i = 0; i < 4; i++)
                #pragma unroll
                for (int j = 0; j < 2; j++) {
                    mma16(acc[i][j * 2],     a[i], b[j]);
                    mma16(acc[i][j * 2 + 1], a[i], b[j] + 2);
                }
        }
        slot++; if (slot >= 3) slot = 0;
    }

    #pragma unroll
    for (int i = 0; i < 4; i++) {
        int r0 = bm + wm + i * 16 + gr;
        #pragma unroll
        for (int j = 0; j < 4; j++) {
            int cc = bn + wn + j * 8 + 2 * tg;
            if (cc < N) {
                st2o(C + (size_t)r0 * N + cc, acc[i][j][0], acc[i][j][1]);
                st2o(C + (size_t)(r0 + 8) * N + cc, acc[i][j][2], acc[i][j][3]);
            }
        }
    }
}

// ---------------------------------------------------------------------------
// Prep kernels
// ---------------------------------------------------------------------------
__global__ void f2h_copy(const float* __restrict__ src, __half* __restrict__ dst,
                         int n4) {
    for (int i = blockIdx.x * blockDim.x + threadIdx.x; i < n4; i += gridDim.x * blockDim.x) {
        float4 v = *(const float4*)(src + i * 4);
        __half2* d = (__half2*)(dst + i * 4);
        d[0] = __floats2half2_rn(v.x, v.y);
        d[1] = __floats2half2_rn(v.z, v.w);
    }
}

// transpose + half: src[K,N] fp32 -> dst[Npad,K] half (pad rows zeroed)
__global__ void transpose_h(const float* __restrict__ src, __half* __restrict__ dst,
                            int K, int N, int Npad) {
    __shared__ float t[32][33];
    int kb = blockIdx.x * 32, nb = blockIdx.y * 32;
    int tx = threadIdx.x, ty = threadIdx.y;
    #pragma unroll
    for (int j = 0; j < 4; j++) {
        int k = kb + ty + j * 8, n = nb + tx;
        float v = 0.f;
        if (k < K && n < N) v = src[(size_t)k * N + n];
        t[ty + j * 8][tx] = v;
    }
    __syncthreads();
    #pragma unroll
    for (int j = 0; j < 4; j++) {
        int n = nb + ty + j * 8, k = kb + tx;
        if (n < Npad && k < K) dst[(size_t)n * K + k] = __float2half(t[tx][ty + j * 8]);
    }
}

// cos/sin table: g_cs[s*64 + i] = cos(s*inv_i), [s*64 + 32 + i] = sin
__global__ void cs_table(float* __restrict__ cs) {
    int s = blockIdx.x, i = threadIdx.x;   // 32 threads
    float inv = powf(10000.f, -(float)i / 32.f);
    float sn, c;
    sincosf((float)s * inv, &sn, &c);
    cs[s * ROPE_D + i] = c;
    cs[s * ROPE_D + 32 + i] = sn;
}

// RMSNorm over kva cols of fused buffer -> ckvh (half)
__global__ void __launch_bounds__(128) rmsnorm_kernel(const float* __restrict__ qkva,
                                                      const float* __restrict__ kvs,
                                                      __half* __restrict__ ckv) {
    int r = blockIdx.x;
    int tid = threadIdx.x;
    const float* row = qkva + (size_t)r * QAW + 3072;

    float x[4];
    float ss = 0.f;
    #pragma unroll
    for (int j = 0; j < 4; j++) {
        x[j] = row[tid + 128 * j];
        ss += x[j] * x[j];
    }
    #pragma unroll
    for (int o = 16; o > 0; o >>= 1)
        ss += __shfl_xor_sync(0xffffffffu, ss, o);

    __shared__ float wsum[4];
    if ((tid & 31) == 0) wsum[tid >> 5] = ss;
    __syncthreads();
    float tot = wsum[0] + wsum[1] + wsum[2] + wsum[3];
    float rms = rsqrtf(tot / (float)LORA + 1e-6f);

    __half* orow = ckv + (size_t)r * LORA;
    #pragma unroll
    for (int j = 0; j < 4; j++) {
        int c = tid + 128 * j;
        orow[c] = __float2half(x[j] * rms * kvs[c]);
    }
}

// rope + pack q (from fused buffer) and k_pe, using cos/sin table
__global__ void __launch_bounds__(256) rope_pack(const float* __restrict__ qkva,
                                                 const float* __restrict__ cs,
                                                 __half* __restrict__ qh,
                                                 __half* __restrict__ kpeh) {
    int r = blockIdx.x;
    int s = r % SS;
    int t = threadIdx.x;
    const float* qr = qkva + (size_t)r * QAW;
    const float* csr = cs + s * ROPE_D;
    __half* qo = qh + (size_t)r * (HH * QHD);

    // nope dims: straight convert (16 heads x 128 = 2048)
    #pragma unroll
    for (int p = 0; p < 8; p++) {
        int i = t + p * 256;
        int head = i >> 7, d = i & 127;
        int off = head * QHD + d;
        qo[off] = __float2half(qr[off]);
    }
    // q pe pairs: 16 heads x 32 = 512 pairs
    #pragma unroll
    for (int p = 0; p < 2; p++) {
        int i = t + p * 256;
        int head = i >> 5, ii = i & 31;
        float c = csr[ii], sn = csr[ii + 32];
        int off = head * QHD + NOPE + ii;
        float x1 = qr[off], x2 = qr[off + 32];
        qo[off]      = __float2half(x1 * c - x2 * sn);
        qo[off + 32] = __float2half(x2 * c + x1 * sn);
    }
    // k_pe pairs: 32
    if (t < 32) {
        float c = csr[t], sn = csr[t + 32];
        const float* kp = qkva + (size_t)r * QAW + 3072 + LORA;
        __half* ko = kpeh + (size_t)r * ROPE_D;
        float x1 = kp[t], x2 = kp[t + 32];
        ko[t]      = __float2half(x1 * c - x2 * sn);
        ko[t + 32] = __float2half(x2 * c + x1 * sn);
    }
}

// ---------------------------------------------------------------------------
// Flash attention (causal), FP16 mma. BM=128, BN=128, 256 thr = 8 warps.
// Q frags in registers; K/V double-buffered via cp.async; all operands half.
// ---------------------------------------------------------------------------
#define FBM 128
#define FBN 128
#define KSTRH 200
#define VSTRH 136
#define SSTRH 136
#define SK_W (FBN * KSTRH)
#define SV_W (FBN * VSTRH)
#define FSMEM ((2*SK_W + 2*SV_W + FBM*SSTRH) * 2)

__global__ void __launch_bounds__(256, 1) flash_h(const __half* __restrict__ qh,
                                                  const __half* __restrict__ kvh,
                                                  const __half* __restrict__ kpeh,
                                                  __half* __restrict__ aoh) {
    extern __shared__ __half fh[];
    __half* sK = fh;                    // [2][SK_W]
    __half* sV = fh + 2 * SK_W;         // [2][SV_W]
    __half* sS = fh + 2 * SK_W + 2 * SV_W;

    int qt = gridDim.x - 1 - blockIdx.x;   // heavy tiles first
    int h = blockIdx.y, b = blockIdx.z;
    int tid = threadIdx.x, wid = tid >> 5, lane = tid & 31;
    int gr = lane >> 2, tg = lane & 3;
    int qbase = qt * FBM;
    int wrow = wid * 16;

    int a_r = (lane & 7) + ((lane >> 3) & 1) * 8;
    int a_c = ((lane >> 4) & 1) * 8;
    int k_r = (lane & 7) + ((lane >> 4) & 1) * 8;  // K x4 j-pair map
    int k_c = ((lane >> 3) & 1) * 8;
    int v_r = lane & 15;                            // V x4t map
    int v_c = ((lane >> 4) & 1) * 8;

    // --- stage Q through sK[0] overlay (128 x 200 halves = SK_W)
    __half* sQ = fh;
    #pragma unroll
    for (int p = 0; p < 12; p++) {
        int idx = tid + p * 256;           // 0..3071
        int row = idx / 24, c = idx - row * 24;
        int r = b * SS + qbase + row;
        cp16(sQ + row * KSTRH + c * 8,
             qh + (size_t)r * (HH * QHD) + h * QHD + c * 8);
    }
    cp_commit();
    cp_wait<0>();
    __syncthreads();

    unsigned qf[12][4];
    #pragma unroll
    for (int ks = 0; ks < 12; ks++)
        ldm_x4(qf[ks], sQ + (wrow + a_r) * KSTRH + ks * 16 + a_c);
    __syncthreads();   // Q consumed; sK area free

    auto load_kv = [&](int kbase, int stg) {
        __half* K = sK + stg * SK_W;
        __half* V = sV + stg * SV_W;
        #pragma unroll
        for (int p = 0; p < 12; p++) {
            int idx = tid + p * 256;       // 0..3071
            int row = idx / 24, c = idx - row * 24;
            int r = b * SS + kbase + row;
            const __half* src = (c < 16)
                ? kvh  + (size_t)r * (HH * (NOPE + VD)) + h * (NOPE + VD) + c * 8
                : kpeh + (size_t)r * ROPE_D + (c - 16) * 8;
            cp16(K + row * KSTRH + c * 8, src);
        }
        #pragma unroll
        for (int p = 0; p < 8; p++) {
            int idx = tid + p * 256;       // 0..2047
            int row = idx >> 4, c = idx & 15;
            int r = b * SS + kbase + row;
            cp16(V + row * VSTRH + c * 8,
                 kvh + (size_t)r * (HH * (NOPE + VD)) + h * (NOPE + VD) + NOPE + c * 8);
        }
        cp_commit();
    };

    float o[16][4];
    #pragma unroll
    for (int n = 0; n < 16; n++)
        #pragma unroll
        for (int t = 0; t < 4; t++) o[n][t] = 0.f;
    float m0 = -1e30f, m1 = -1e30f, l0 = 0.f, l1 = 0.f;
    const float scale = 0.07216878364870323f;  // 192^-0.5

    int ktmax = qt + 1;
    load_kv(0, 0);

    for (int kt = 0; kt < ktmax; kt++) {
        int kbase = kt * FBN;
        int stg = kt & 1;
        cp_wait<0>();
        __syncthreads();
        if (kt + 1 < ktmax) load_kv(kbase + FBN, stg ^ 1);

        __half* K = sK + stg * SK_W;
        __half* V = sV + stg * SV_W;

        // ---- scores: S = Q K^T (16 rows x 128 cols per warp) ----
        float sacc[16][4];
        #pragma unroll
        for (int j = 0; j < 16; j++)
            #pragma unroll
            for (int t = 0; t < 4; t++) sacc[j][t] = 0.f;

        #pragma unroll
        for (int ks = 0; ks < 12; ks++) {
            int kk = ks * 16;
            #pragma unroll
            for (int j = 0; j < 16; j += 2) {
                unsigned bb[4];
                ldm_x4(bb, K + (j * 8 + k_r) * KSTRH + kk + k_c);
                mma16(sacc[j],     qf[ks], bb);
                mma16(sacc[j + 1], qf[ks], bb + 2);
            }
        }

        // ---- scale + (diag-only) causal mask + online softmax ----
        int qr0 = qbase + wrow + gr;
        int qr1 = qr0 + 8;
        float mx0 = -1e30f, mx1 = -1e30f;
        if (kt < qt) {
            #pragma unroll
            for (int j = 0; j < 16; j++) {
                sacc[j][0] *= scale; sacc[j][1] *= scale;
                sacc[j][2] *= scale; sacc[j][3] *= scale;
                mx0 = fmaxf(mx0, fmaxf(sacc[j][0], sacc[j][1]));
                mx1 = fmaxf(mx1, fmaxf(sacc[j][2], sacc[j][3]));
            }
        } else {
            #pragma unroll
            for (int j = 0; j < 16; j++) {
                int c0 = kbase + j * 8 + 2 * tg;
                sacc[j][0] = (c0     <= qr0) ? sacc[j][0] * scale : -1e30f;
                sacc[j][1] = (c0 + 1 <= qr0) ? sacc[j][1] * scale : -1e30f;
                sacc[j][2] = (c0     <= qr1) ? sacc[j][2] * scale : -1e30f;
                sacc[j][3] = (c0 + 1 <= qr1) ? sacc[j][3] * scale : -1e30f;
                mx0 = fmaxf(mx0, fmaxf(sacc[j][0], sacc[j][1]));
                mx1 = fmaxf(mx1, fmaxf(sacc[j][2], sacc[j][3]));
            }
        }
        mx0 = fmaxf(mx0, __shfl_xor_sync(0xffffffffu, mx0, 1));
        mx0 = fmaxf(mx0, __shfl_xor_sync(0xffffffffu, mx0, 2));
        mx1 = fmaxf(mx1, __shfl_xor_sync(0xffffffffu, mx1, 1));
        mx1 = fmaxf(mx1, __shfl_xor_sync(0xffffffffu, mx1, 2));

        float mn0 = fmaxf(m0, mx0), mn1 = fmaxf(m1, mx1);
        float f0 = __expf(m0 - mn0), f1 = __expf(m1 - mn1);
        m0 = mn0; m1 = mn1;

        float s0 = 0.f, s1 = 0.f;
        #pragma unroll
        for (int j = 0; j < 16; j++) {
            float p0 = __expf(sacc[j][0] - mn0);
            float p1 = __expf(sacc[j][1] - mn0);
            float p2 = __expf(sacc[j][2] - mn1);
            float p3 = __expf(sacc[j][3] - mn1);
            s0 += p0 + p1; s1 += p2 + p3;
            int cc = j * 8 + 2 * tg;
            *(__half2*)&sS[(wrow + gr) * SSTRH + cc]     = __floats2half2_rn(p0, p1);
            *(__half2*)&sS[(wrow + gr + 8) * SSTRH + cc] = __floats2half2_rn(p2, p3);
        }
        s0 += __shfl_xor_sync(0xffffffffu, s0, 1);
        s0 += __shfl_xor_sync(0xffffffffu, s0, 2);
        s1 += __shfl_xor_sync(0xffffffffu, s1, 1);
        s1 += __shfl_xor_sync(0xffffffffu, s1, 2);
        l0 = l0 * f0 + s0;
        l1 = l1 * f1 + s1;

        #pragma unroll
        for (int n = 0; n < 16; n++) {
            o[n][0] *= f0; o[n][1] *= f0; o[n][2] *= f1; o[n][3] *= f1;
        }
        __syncwarp();

        // ---- PV: O += P V (16 rows x 128 cols per warp) ----
        #pragma unroll
        for (int ks = 0; ks < 8; ks++) {
            int kk = ks * 16;
            unsigned a[4];
            ldm_x4(a, sS + (wrow + a_r) * SSTRH + kk + a_c);
            #pragma unroll
            for (int n = 0; n < 16; n += 2) {
                unsigned bb[4];
                ldm_x4t(bb, V + (kk + v_r) * VSTRH + n * 8 + v_c);
                mma16(o[n],     a, bb);
                mma16(o[n + 1], a, bb + 2);
            }
        }
        __syncwarp();
    }

    // epilogue -> half
    float inv0 = 1.f / l0, inv1 = 1.f / l1;
    size_t r0 = (size_t)(b * SS + qbase + wrow + gr) * (HH * VD);
    size_t r1 = r0 + 8 * (HH * VD);
    #pragma unroll
    for (int n = 0; n < 16; n++) {
        int cc = h * VD + n * 8 + 2 * tg;
        *(__half2*)(aoh + r0 + cc) = __floats2half2_rn(o[n][0] * inv0, o[n][1] * inv0);
        *(__half2*)(aoh + r1 + cc) = __floats2half2_rn(o[n][2] * inv1, o[n][3] * inv1);
    }
}

// ---------------------------------------------------------------------------
extern "C" void kernel_launch(void* const* d_in, const int* in_sizes, int n_in,
                              void* d_out, int out_size) {
    const float* x     = (const float*)d_in[0];
    const float* wq    = (const float*)d_in[1];
    const float* wkv_a = (const float*)d_in[2];
    const float* wkv_b = (const float*)d_in[3];
    const float* wo    = (const float*)d_in[4];
    const float* kvs   = (const float*)d_in[5];
    float* out = (float*)d_out;

    float *qkva, *cs;
    __half *qh, *kpeh, *ckvh, *kvh, *aoh, *xh, *wqaT, *wkvbT, *woT;
    cudaGetSymbolAddress((void**)&qkva,  g_qkva);
    cudaGetSymbolAddress((void**)&cs,    g_cs);
    cudaGetSymbolAddress((void**)&qh,    g_qh);
    cudaGetSymbolAddress((void**)&kpeh,  g_kpeh);
    cudaGetSymbolAddress((void**)&ckvh,  g_ckvh);
    cudaGetSymbolAddress((void**)&kvh,   g_kvh);
    cudaGetSymbolAddress((void**)&aoh,   g_aoh);
    cudaGetSymbolAddress((void**)&xh,    g_xh);
    cudaGetSymbolAddress((void**)&wqaT,  g_wqaT);
    cudaGetSymbolAddress((void**)&wkvbT, g_wkvbT);
    cudaGetSymbolAddress((void**)&woT,   g_woT);

    static bool attr_done = false;
    if (!attr_done) {
        cudaFuncSetAttribute(flash_h,
                             cudaFuncAttributeMaxDynamicSharedMemorySize, (int)FSMEM);
        cudaFuncSetAttribute(hgemm<float>,
                             cudaFuncAttributeMaxDynamicSharedMemorySize, (int)GSMEM);
        cudaFuncSetAttribute(hgemm<__half>,
                             cudaFuncAttributeMaxDynamicSharedMemorySize, (int)GSMEM);
        attr_done = true;
    }

    // prep
    f2h_copy<<<1024, 256>>>(x, xh, RWS * EE / 4);
    cs_table<<<SS, 32>>>(cs);
    transpose_h<<<dim3(64, 96),  dim3(32, 8)>>>(wq,    wqaT,               2048, 3072, 3072);
    transpose_h<<<dim3(64, 20),  dim3(32, 8)>>>(wkv_a, wqaT + (size_t)3072 * 2048, 2048, 576, 640);
    transpose_h<<<dim3(16, 128), dim3(32, 8)>>>(wkv_b, wkvbT, 512,  4096, 4096);
    transpose_h<<<dim3(64, 64),  dim3(32, 8)>>>(wo,    woT,   2048, 2048, 2048);

    // qkva = x @ [wq | wkv_a] : [4096, 3712] fp32
    hgemm<float><<<dim3(QAW / 128, 32), 256, GSMEM>>>(xh, wqaT, qkva, QAW, 2048);
    // ckvh = rmsnorm(qkva[:, 3072:3584]) * kv_norm_scale (half)
    rmsnorm_kernel<<<RWS, 128>>>(qkva, kvs, ckvh);
    // rope + pack q -> qh, k_pe -> kpeh
    rope_pack<<<RWS, 256>>>(qkva, cs, qh, kpeh);
    // kvh = ckv @ wkv_b : [4096, 4096] half
    hgemm<__half><<<dim3(32, 32), 256, GSMEM>>>(ckvh, wkvbT, kvh, 4096, 512);
    // attention -> aoh : [4096, 2048] half
    flash_h<<<dim3(SS / FBM, HH, BB), 256, FSMEM>>>(qh, kvh, kpeh, aoh);
    // out = ao @ wo : [4096, 2048] fp32
    hgemm<float><<<dim3(16, 32), 256, GSMEM>>>(aoh, woT, out, 2048, 2048);
}

// round 9
// speedup vs baseline: 12.3074x; 1.0770x over previous
#include <cuda_runtime.h>
#include <cuda_fp16.h>
#include <math.h>

// Problem constants
#define BB 2
#define SS 2048
#define EE 2048
#define HH 16
#define NOPE 128
#define ROPE_D 64
#define QHD 192          // NOPE + ROPE
#define LORA 512
#define VD 128
#define RWS (BB*SS)      // 4096 rows
#define QAW 3712         // fused q(3072) + kva(576->640 pad) width

// Scratch (device globals; no allocation allowed)
__device__ __half g_qkvah[(size_t)RWS * QAW];          // fused x@[wq|wkv_a], half
__device__ __half g_qh[(size_t)RWS * (HH * QHD)];      // roped q, half
__device__ __half g_kpeh[(size_t)RWS * ROPE_D];        // roped k_pe, half
__device__ __half g_ckvh[(size_t)RWS * LORA];
__device__ __half g_kvh[(size_t)RWS * (HH * (NOPE + VD))];
__device__ __half g_aoh[(size_t)RWS * (HH * VD)];
__device__ __half g_xh[(size_t)RWS * EE];
__device__ __half g_wqaT[(size_t)QAW * 2048];          // [wq^T ; wkv_a^T(pad)]
__device__ __half g_wkvbT[(size_t)4096 * 512];
__device__ __half g_woT[(size_t)2048 * 2048];
__device__ float  g_cs[SS * ROPE_D];                   // cos[0..31], sin[32..63]

// ---------------- helpers ----------------
__device__ __forceinline__ void mma16(float* c, const unsigned* a, const unsigned* b) {
    asm volatile("mma.sync.aligned.m16n8k16.row.col.f32.f16.f16.f32 "
        "{%0,%1,%2,%3}, {%4,%5,%6,%7}, {%8,%9}, {%0,%1,%2,%3};"
        : "+f"(c[0]), "+f"(c[1]), "+f"(c[2]), "+f"(c[3])
        : "r"(a[0]), "r"(a[1]), "r"(a[2]), "r"(a[3]), "r"(b[0]), "r"(b[1]));
}
__device__ __forceinline__ void ldm_x4(unsigned* r, const void* p) {
    unsigned s = (unsigned)__cvta_generic_to_shared(p);
    asm volatile("ldmatrix.sync.aligned.m8n8.x4.shared.b16 {%0,%1,%2,%3}, [%4];"
        : "=r"(r[0]), "=r"(r[1]), "=r"(r[2]), "=r"(r[3]) : "r"(s));
}
__device__ __forceinline__ void ldm_x4t(unsigned* r, const void* p) {
    unsigned s = (unsigned)__cvta_generic_to_shared(p);
    asm volatile("ldmatrix.sync.aligned.m8n8.x4.trans.shared.b16 {%0,%1,%2,%3}, [%4];"
        : "=r"(r[0]), "=r"(r[1]), "=r"(r[2]), "=r"(r[3]) : "r"(s));
}
__device__ __forceinline__ void cp16(void* dst, const void* src) {
    unsigned d = (unsigned)__cvta_generic_to_shared(dst);
    asm volatile("cp.async.cg.shared.global [%0], [%1], 16;" :: "r"(d), "l"(src));
}
__device__ __forceinline__ void cp_commit() {
    asm volatile("cp.async.commit_group;");
}
template<int N> __device__ __forceinline__ void cp_wait() {
    asm volatile("cp.async.wait_group %0;" :: "n"(N));
}
__device__ __forceinline__ void st2o(float* p, float x, float y) {
    *(float2*)p = make_float2(x, y);
}
__device__ __forceinline__ void st2o(__half* p, float x, float y) {
    *(__half2*)p = __floats2half2_rn(x, y);
}

// ---------------------------------------------------------------------------
// FP16 tensor-core GEMM: C[M,N] = A[M,K] @ BT[N,K]^T. A,BT half; C float/half.
// 128x128 tile, BK=64, 256 thr = 8 warps (2Mx4N, 64x32 each), 3-stage cp.async.
// ---------------------------------------------------------------------------
#define ASTRH 72
#define STG_H (2 * 128 * ASTRH)       // halves per stage (A + B)
#define GSMEM (3 * STG_H * 2)         // 110592 bytes

template<typename OutT>
__global__ void __launch_bounds__(256, 2) hgemm(const __half* __restrict__ A,
                                                const __half* __restrict__ BT,
                                                OutT* __restrict__ C,
                                                int N, int K) {
    extern __shared__ __half hs[];

    int tid = threadIdx.x, wid = tid >> 5, lane = tid & 31;
    int bm = blockIdx.y * 128, bn = blockIdx.x * 128;
    int wm = (wid >> 2) * 64, wn = (wid & 3) * 32;
    int gr = lane >> 2, tg = lane & 3;

    int a_r = (lane & 7) + ((lane >> 3) & 1) * 8;   // ldmatrix x4 A row map
    int a_c = ((lane >> 4) & 1) * 8;
    int b_r = (lane & 7) + ((lane >> 4) & 1) * 8;   // ldmatrix x4 B (j-pair) map
    int b_c = ((lane >> 3) & 1) * 8;

    int nkb = K >> 6;

    auto issue = [&](int kb, int slot) {
        __half* sA = hs + slot * STG_H;
        __half* sB = sA + 128 * ASTRH;
        int k0 = kb * 64;
        #pragma unroll
        for (int p = 0; p < 4; p++) {
            int idx = tid + p * 256;          // 0..1023
            int row = idx >> 3, c = idx & 7;  // 8 x 16B chunks per 64-half row
            cp16(sA + row * ASTRH + c * 8, A + (size_t)(bm + row) * K + k0 + c * 8);
        }
        #pragma unroll
        for (int p = 0; p < 4; p++) {
            int idx = tid + p * 256;
            int row = idx >> 3, c = idx & 7;
            cp16(sB + row * ASTRH + c * 8, BT + (size_t)(bn + row) * K + k0 + c * 8);
        }
        cp_commit();
    };

    issue(0, 0);
    if (nkb > 1) issue(1, 1);

    float acc[4][4][4];
    #pragma unroll
    for (int i = 0; i < 4; i++)
        #pragma unroll
        for (int j = 0; j < 4; j++)
            #pragma unroll
            for (int t = 0; t < 4; t++) acc[i][j][t] = 0.f;

    int slot = 0;
    for (int kb = 0; kb < nkb; kb++) {
        if (kb + 1 < nkb) cp_wait<1>(); else cp_wait<0>();
        __syncthreads();
        if (kb + 2 < nkb) {
            int ns = slot + 2; if (ns >= 3) ns -= 3;
            issue(kb + 2, ns);
        }

        __half* sA = hs + slot * STG_H;
        __half* sB = sA + 128 * ASTRH;

        #pragma unroll
        for (int ks = 0; ks < 4; ks++) {
            int kk = ks * 16;
            unsigned a[4][4], b[2][4];
            #pragma unroll
            for (int i = 0; i < 4; i++)
                ldm_x4(a[i], sA + (wm + i * 16 + a_r) * ASTRH + kk + a_c);
            #pragma unroll
            for (int j = 0; j < 2; j++)
                ldm_x4(b[j], sB + (wn + j * 16 + b_r) * ASTRH + kk + b_c);
            #pragma unroll
            for (int i = 0; i < 4; i++)
                #pragma unroll
                for (int j = 0; j < 2; j++) {
                    mma16(acc[i][j * 2],     a[i], b[j]);
                    mma16(acc[i][j * 2 + 1], a[i], b[j] + 2);
                }
        }
        slot++; if (slot >= 3) slot = 0;
    }

    #pragma unroll
    for (int i = 0; i < 4; i++) {
        int r0 = bm + wm + i * 16 + gr;
        #pragma unroll
        for (int j = 0; j < 4; j++) {
            int cc = bn + wn + j * 8 + 2 * tg;
            if (cc < N) {
                st2o(C + (size_t)r0 * N + cc, acc[i][j][0], acc[i][j][1]);
                st2o(C + (size_t)(r0 + 8) * N + cc, acc[i][j][2], acc[i][j][3]);
            }
        }
    }
}

// ---------------------------------------------------------------------------
// Prep kernels
// ---------------------------------------------------------------------------
__global__ void f2h_copy(const float* __restrict__ src, __half* __restrict__ dst,
                         int n4) {
    for (int i = blockIdx.x * blockDim.x + threadIdx.x; i < n4; i += gridDim.x * blockDim.x) {
        float4 v = *(const float4*)(src + i * 4);
        __half2* d = (__half2*)(dst + i * 4);
        d[0] = __floats2half2_rn(v.x, v.y);
        d[1] = __floats2half2_rn(v.z, v.w);
    }
}

// transpose + half: src[K,N] fp32 -> dst[Npad,K] half (pad rows zeroed)
__global__ void transpose_h(const float* __restrict__ src, __half* __restrict__ dst,
                            int K, int N, int Npad) {
    __shared__ float t[32][33];
    int kb = blockIdx.x * 32, nb = blockIdx.y * 32;
    int tx = threadIdx.x, ty = threadIdx.y;
    #pragma unroll
    for (int j = 0; j < 4; j++) {
        int k = kb + ty + j * 8, n = nb + tx;
        float v = 0.f;
        if (k < K && n < N) v = src[(size_t)k * N + n];
        t[ty + j * 8][tx] = v;
    }
    __syncthreads();
    #pragma unroll
    for (int j = 0; j < 4; j++) {
        int n = nb + ty + j * 8, k = kb + tx;
        if (n < Npad && k < K) dst[(size_t)n * K + k] = __float2half(t[tx][ty + j * 8]);
    }
}

// cos/sin table: g_cs[s*64 + i] = cos(s*inv_i), [s*64 + 32 + i] = sin
__global__ void cs_table(float* __restrict__ cs) {
    int s = blockIdx.x, i = threadIdx.x;   // 32 threads
    float inv = powf(10000.f, -(float)i / 32.f);
    float sn, c;
    sincosf((float)s * inv, &sn, &c);
    cs[s * ROPE_D + i] = c;
    cs[s * ROPE_D + 32 + i] = sn;
}

// RMSNorm over kva cols of fused (half) buffer -> ckvh (half)
__global__ void __launch_bounds__(128) rmsnorm_kernel(const __half* __restrict__ qkva,
                                                      const float* __restrict__ kvs,
                                                      __half* __restrict__ ckv) {
    int r = blockIdx.x;
    int tid = threadIdx.x;
    const __half* row = qkva + (size_t)r * QAW + 3072;

    float x[4];
    float ss = 0.f;
    #pragma unroll
    for (int j = 0; j < 4; j++) {
        x[j] = __half2float(row[tid + 128 * j]);
        ss += x[j] * x[j];
    }
    #pragma unroll
    for (int o = 16; o > 0; o >>= 1)
        ss += __shfl_xor_sync(0xffffffffu, ss, o);

    __shared__ float wsum[4];
    if ((tid & 31) == 0) wsum[tid >> 5] = ss;
    __syncthreads();
    float tot = wsum[0] + wsum[1] + wsum[2] + wsum[3];
    float rms = rsqrtf(tot / (float)LORA + 1e-6f);

    __half* orow = ckv + (size_t)r * LORA;
    #pragma unroll
    for (int j = 0; j < 4; j++) {
        int c = tid + 128 * j;
        orow[c] = __float2half(x[j] * rms * kvs[c]);
    }
}

// rope + pack q (from fused half buffer) and k_pe, using cos/sin table
__global__ void __launch_bounds__(256) rope_pack(const __half* __restrict__ qkva,
                                                 const float* __restrict__ cs,
                                                 __half* __restrict__ qh,
                                                 __half* __restrict__ kpeh) {
    int r = blockIdx.x;
    int s = r % SS;
    int t = threadIdx.x;
    const __half* qr = qkva + (size_t)r * QAW;
    const float* csr = cs + s * ROPE_D;
    __half* qo = qh + (size_t)r * (HH * QHD);

    // nope dims: straight copy (16 heads x 128 = 2048), vectorized 8 halves
    #pragma unroll
    for (int p = 0; p < 1; p++) { }
    for (int i = t; i < 256; i += 256) { }
    #pragma unroll
    for (int p = 0; p < 1; p++) {
        // 2048 halves / 8 per thread = 256 iterations over 256 threads
        int i = t;                     // 0..255 -> 8-half chunk index
        int head = i >> 4;             // 16 chunks per head (128 halves)
        int d = (i & 15) * 8;
        int off = head * QHD + d;
        *(uint4*)(qo + off) = *(const uint4*)(qr + off);
    }
    // q pe pairs: 16 heads x 32 = 512 pairs
    #pragma unroll
    for (int p = 0; p < 2; p++) {
        int i = t + p * 256;
        int head = i >> 5, ii = i & 31;
        float c = csr[ii], sn = csr[ii + 32];
        int off = head * QHD + NOPE + ii;
        float x1 = __half2float(qr[off]), x2 = __half2float(qr[off + 32]);
        qo[off]      = __float2half(x1 * c - x2 * sn);
        qo[off + 32] = __float2half(x2 * c + x1 * sn);
    }
    // k_pe pairs: 32
    if (t < 32) {
        float c = csr[t], sn = csr[t + 32];
        const __half* kp = qkva + (size_t)r * QAW + 3072 + LORA;
        __half* ko = kpeh + (size_t)r * ROPE_D;
        float x1 = __half2float(kp[t]), x2 = __half2float(kp[t + 32]);
        ko[t]      = __float2half(x1 * c - x2 * sn);
        ko[t + 32] = __float2half(x2 * c + x1 * sn);
    }
}

// ---------------------------------------------------------------------------
// Flash attention (causal), FP16 mma. BM=128, BN=128, 256 thr = 8 warps.
// Q frags in registers; K/V double-buffered via cp.async; all operands half.
// ---------------------------------------------------------------------------
#define FBM 128
#define FBN 128
#define KSTRH 200
#define VSTRH 136
#define SSTRH 136
#define SK_W (FBN * KSTRH)
#define SV_W (FBN * VSTRH)
#define FSMEM ((2*SK_W + 2*SV_W + FBM*SSTRH) * 2)

__global__ void __launch_bounds__(256, 1) flash_h(const __half* __restrict__ qh,
                                                  const __half* __restrict__ kvh,
                                                  const __half* __restrict__ kpeh,
                                                  __half* __restrict__ aoh) {
    extern __shared__ __half fh[];
    __half* sK = fh;                    // [2][SK_W]
    __half* sV = fh + 2 * SK_W;         // [2][SV_W]
    __half* sS = fh + 2 * SK_W + 2 * SV_W;

    int qt = gridDim.x - 1 - blockIdx.x;   // heavy tiles first
    int h = blockIdx.y, b = blockIdx.z;
    int tid = threadIdx.x, wid = tid >> 5, lane = tid & 31;
    int gr = lane >> 2, tg = lane & 3;
    int qbase = qt * FBM;
    int wrow = wid * 16;

    int a_r = (lane & 7) + ((lane >> 3) & 1) * 8;
    int a_c = ((lane >> 4) & 1) * 8;
    int k_r = (lane & 7) + ((lane >> 4) & 1) * 8;  // K x4 j-pair map
    int k_c = ((lane >> 3) & 1) * 8;
    int v_r = lane & 15;                            // V x4t map
    int v_c = ((lane >> 4) & 1) * 8;

    // --- stage Q through sK[0] overlay (128 x 200 halves = SK_W)
    __half* sQ = fh;
    #pragma unroll
    for (int p = 0; p < 12; p++) {
        int idx = tid + p * 256;           // 0..3071
        int row = idx / 24, c = idx - row * 24;
        int r = b * SS + qbase + row;
        cp16(sQ + row * KSTRH + c * 8,
             qh + (size_t)r * (HH * QHD) + h * QHD + c * 8);
    }
    cp_commit();
    cp_wait<0>();
    __syncthreads();

    unsigned qf[12][4];
    #pragma unroll
    for (int ks = 0; ks < 12; ks++)
        ldm_x4(qf[ks], sQ + (wrow + a_r) * KSTRH + ks * 16 + a_c);
    __syncthreads();   // Q consumed; sK area free

    auto load_kv = [&](int kbase, int stg) {
        __half* K = sK + stg * SK_W;
        __half* V = sV + stg * SV_W;
        #pragma unroll
        for (int p = 0; p < 12; p++) {
            int idx = tid + p * 256;       // 0..3071
            int row = idx / 24, c = idx - row * 24;
            int r = b * SS + kbase + row;
            const __half* src = (c < 16)
                ? kvh  + (size_t)r * (HH * (NOPE + VD)) + h * (NOPE + VD) + c * 8
                : kpeh + (size_t)r * ROPE_D + (c - 16) * 8;
            cp16(K + row * KSTRH + c * 8, src);
        }
        #pragma unroll
        for (int p = 0; p < 8; p++) {
            int idx = tid + p * 256;       // 0..2047
            int row = idx >> 4, c = idx & 15;
            int r = b * SS + kbase + row;
            cp16(V + row * VSTRH + c * 8,
                 kvh + (size_t)r * (HH * (NOPE + VD)) + h * (NOPE + VD) + NOPE + c * 8);
        }
        cp_commit();
    };

    float o[16][4];
    #pragma unroll
    for (int n = 0; n < 16; n++)
        #pragma unroll
        for (int t = 0; t < 4; t++) o[n][t] = 0.f;
    float m0 = -1e30f, m1 = -1e30f, l0 = 0.f, l1 = 0.f;
    const float scale = 0.07216878364870323f;  // 192^-0.5

    int ktmax = qt + 1;
    load_kv(0, 0);

    for (int kt = 0; kt < ktmax; kt++) {
        int kbase = kt * FBN;
        int stg = kt & 1;
        cp_wait<0>();
        __syncthreads();
        if (kt + 1 < ktmax) load_kv(kbase + FBN, stg ^ 1);

        __half* K = sK + stg * SK_W;
        __half* V = sV + stg * SV_W;

        // ---- scores: S = Q K^T (16 rows x 128 cols per warp) ----
        float sacc[16][4];
        #pragma unroll
        for (int j = 0; j < 16; j++)
            #pragma unroll
            for (int t = 0; t < 4; t++) sacc[j][t] = 0.f;

        #pragma unroll
        for (int ks = 0; ks < 12; ks++) {
            int kk = ks * 16;
            #pragma unroll
            for (int j = 0; j < 16; j += 2) {
                unsigned bb[4];
                ldm_x4(bb, K + (j * 8 + k_r) * KSTRH + kk + k_c);
                mma16(sacc[j],     qf[ks], bb);
                mma16(sacc[j + 1], qf[ks], bb + 2);
            }
        }

        // ---- scale + (diag-only) causal mask + online softmax ----
        int qr0 = qbase + wrow + gr;
        int qr1 = qr0 + 8;
        float mx0 = -1e30f, mx1 = -1e30f;
        if (kt < qt) {
            #pragma unroll
            for (int j = 0; j < 16; j++) {
                sacc[j][0] *= scale; sacc[j][1] *= scale;
                sacc[j][2] *= scale; sacc[j][3] *= scale;
                mx0 = fmaxf(mx0, fmaxf(sacc[j][0], sacc[j][1]));
                mx1 = fmaxf(mx1, fmaxf(sacc[j][2], sacc[j][3]));
            }
        } else {
            #pragma unroll
            for (int j = 0; j < 16; j++) {
                int c0 = kbase + j * 8 + 2 * tg;
                sacc[j][0] = (c0     <= qr0) ? sacc[j][0] * scale : -1e30f;
                sacc[j][1] = (c0 + 1 <= qr0) ? sacc[j][1] * scale : -1e30f;
                sacc[j][2] = (c0     <= qr1) ? sacc[j][2] * scale : -1e30f;
                sacc[j][3] = (c0 + 1 <= qr1) ? sacc[j][3] * scale : -1e30f;
                mx0 = fmaxf(mx0, fmaxf(sacc[j][0], sacc[j][1]));
                mx1 = fmaxf(mx1, fmaxf(sacc[j][2], sacc[j][3]));
            }
        }
        mx0 = fmaxf(mx0, __shfl_xor_sync(0xffffffffu, mx0, 1));
        mx0 = fmaxf(mx0, __shfl_xor_sync(0xffffffffu, mx0, 2));
        mx1 = fmaxf(mx1, __shfl_xor_sync(0xffffffffu, mx1, 1));
        mx1 = fmaxf(mx1, __shfl_xor_sync(0xffffffffu, mx1, 2));

        float mn0 = fmaxf(m0, mx0), mn1 = fmaxf(m1, mx1);
        float f0 = __expf(m0 - mn0), f1 = __expf(m1 - mn1);
        m0 = mn0; m1 = mn1;

        float s0 = 0.f, s1 = 0.f;
        #pragma unroll
        for (int j = 0; j < 16; j++) {
            float p0 = __expf(sacc[j][0] - mn0);
            float p1 = __expf(sacc[j][1] - mn0);
            float p2 = __expf(sacc[j][2] - mn1);
            float p3 = __expf(sacc[j][3] - mn1);
            s0 += p0 + p1; s1 += p2 + p3;
            int cc = j * 8 + 2 * tg;
            *(__half2*)&sS[(wrow + gr) * SSTRH + cc]     = __floats2half2_rn(p0, p1);
            *(__half2*)&sS[(wrow + gr + 8) * SSTRH + cc] = __floats2half2_rn(p2, p3);
        }
        s0 += __shfl_xor_sync(0xffffffffu, s0, 1);
        s0 += __shfl_xor_sync(0xffffffffu, s0, 2);
        s1 += __shfl_xor_sync(0xffffffffu, s1, 1);
        s1 += __shfl_xor_sync(0xffffffffu, s1, 2);
        l0 = l0 * f0 + s0;
        l1 = l1 * f1 + s1;

        #pragma unroll
        for (int n = 0; n < 16; n++) {
            o[n][0] *= f0; o[n][1] *= f0; o[n][2] *= f1; o[n][3] *= f1;
        }
        __syncwarp();

        // ---- PV: O += P V (16 rows x 128 cols per warp) ----
        #pragma unroll
        for (int ks = 0; ks < 8; ks++) {
            int kk = ks * 16;
            unsigned a[4];
            ldm_x4(a, sS + (wrow + a_r) * SSTRH + kk + a_c);
            #pragma unroll
            for (int n = 0; n < 16; n += 2) {
                unsigned bb[4];
                ldm_x4t(bb, V + (kk + v_r) * VSTRH + n * 8 + v_c);
                mma16(o[n],     a, bb);
                mma16(o[n + 1], a, bb + 2);
            }
        }
        __syncwarp();
    }

    // epilogue -> half
    float inv0 = 1.f / l0, inv1 = 1.f / l1;
    size_t r0 = (size_t)(b * SS + qbase + wrow + gr) * (HH * VD);
    size_t r1 = r0 + 8 * (HH * VD);
    #pragma unroll
    for (int n = 0; n < 16; n++) {
        int cc = h * VD + n * 8 + 2 * tg;
        *(__half2*)(aoh + r0 + cc) = __floats2half2_rn(o[n][0] * inv0, o[n][1] * inv0);
        *(__half2*)(aoh + r1 + cc) = __floats2half2_rn(o[n][2] * inv1, o[n][3] * inv1);
    }
}

// ---------------------------------------------------------------------------
extern "C" void kernel_launch(void* const* d_in, const int* in_sizes, int n_in,
                              void* d_out, int out_size) {
    const float* x     = (const float*)d_in[0];
    const float* wq    = (const float*)d_in[1];
    const float* wkv_a = (const float*)d_in[2];
    const float* wkv_b = (const float*)d_in[3];
    const float* wo    = (const float*)d_in[4];
    const float* kvs   = (const float*)d_in[5];
    float* out = (float*)d_out;

    float *cs;
    __half *qkvah, *qh, *kpeh, *ckvh, *kvh, *aoh, *xh, *wqaT, *wkvbT, *woT;
    cudaGetSymbolAddress((void**)&qkvah, g_qkvah);
    cudaGetSymbolAddress((void**)&cs,    g_cs);
    cudaGetSymbolAddress((void**)&qh,    g_qh);
    cudaGetSymbolAddress((void**)&kpeh,  g_kpeh);
    cudaGetSymbolAddress((void**)&ckvh,  g_ckvh);
    cudaGetSymbolAddress((void**)&kvh,   g_kvh);
    cudaGetSymbolAddress((void**)&aoh,   g_aoh);
    cudaGetSymbolAddress((void**)&xh,    g_xh);
    cudaGetSymbolAddress((void**)&wqaT,  g_wqaT);
    cudaGetSymbolAddress((void**)&wkvbT, g_wkvbT);
    cudaGetSymbolAddress((void**)&woT,   g_woT);

    static bool attr_done = false;
    if (!attr_done) {
        cudaFuncSetAttribute(flash_h,
                             cudaFuncAttributeMaxDynamicSharedMemorySize, (int)FSMEM);
        cudaFuncSetAttribute(hgemm<float>,
                             cudaFuncAttributeMaxDynamicSharedMemorySize, (int)GSMEM);
        cudaFuncSetAttribute(hgemm<__half>,
                             cudaFuncAttributeMaxDynamicSharedMemorySize, (int)GSMEM);
        attr_done = true;
    }

    // prep
    f2h_copy<<<1024, 256>>>(x, xh, RWS * EE / 4);
    cs_table<<<SS, 32>>>(cs);
    transpose_h<<<dim3(64, 96),  dim3(32, 8)>>>(wq,    wqaT,               2048, 3072, 3072);
    transpose_h<<<dim3(64, 20),  dim3(32, 8)>>>(wkv_a, wqaT + (size_t)3072 * 2048, 2048, 576, 640);
    transpose_h<<<dim3(16, 128), dim3(32, 8)>>>(wkv_b, wkvbT, 512,  4096, 4096);
    transpose_h<<<dim3(64, 64),  dim3(32, 8)>>>(wo,    woT,   2048, 2048, 2048);

    // qkva = x @ [wq | wkv_a] : [4096, 3712] half
    hgemm<__half><<<dim3(QAW / 128, 32), 256, GSMEM>>>(xh, wqaT, qkvah, QAW, 2048);
    // ckvh = rmsnorm(qkva[:, 3072:3584]) * kv_norm_scale (half)
    rmsnorm_kernel<<<RWS, 128>>>(qkvah, kvs, ckvh);
    // rope + pack q -> qh, k_pe -> kpeh
    rope_pack<<<RWS, 256>>>(qkvah, cs, qh, kpeh);
    // kvh = ckv @ wkv_b : [4096, 4096] half
    hgemm<__half><<<dim3(32, 32), 256, GSMEM>>>(ckvh, wkvbT, kvh, 4096, 512);
    // attention -> aoh : [4096, 2048] half
    flash_h<<<dim3(SS / FBM, HH, BB), 256, FSMEM>>>(qh, kvh, kpeh, aoh);
    // out = ao @ wo : [4096, 2048] fp32
    hgemm<float><<<dim3(16, 32), 256, GSMEM>>>(aoh, woT, out, 2048, 2048);
}

// round 10
// speedup vs baseline: 12.8107x; 1.0409x over previous
#include <cuda_runtime.h>
#include <cuda_fp16.h>
#include <math.h>

// Problem constants
#define BB 2
#define SS 2048
#define EE 2048
#define HH 16
#define NOPE 128
#define ROPE_D 64
#define QHD 192          // NOPE + ROPE
#define LORA 512
#define VD 128
#define RWS (BB*SS)      // 4096 rows
#define QAW 3712         // fused q(3072) + kva(576->640 pad) width

// Scratch (device globals; no allocation allowed)
__device__ __half g_qkvah[(size_t)RWS * QAW];          // fused x@[wq|wkv_a], half
__device__ __half g_qh[(size_t)RWS * (HH * QHD)];      // roped q, half
__device__ __half g_kpeh[(size_t)RWS * ROPE_D];        // roped k_pe, half
__device__ __half g_ckvh[(size_t)RWS * LORA];
__device__ __half g_kvh[(size_t)RWS * (HH * (NOPE + VD))];
__device__ __half g_aoh[(size_t)RWS * (HH * VD)];
__device__ __half g_xh[(size_t)RWS * EE];
__device__ __half g_wqaT[(size_t)QAW * 2048];          // [wq^T ; wkv_a^T(pad)]
__device__ __half g_wkvbT[(size_t)4096 * 512];
__device__ __half g_woT[(size_t)2048 * 2048];
__device__ float  g_cs[SS * ROPE_D];                   // cos[0..31], sin[32..63]

// ---------------- helpers ----------------
__device__ __forceinline__ void mma16(float* c, const unsigned* a, const unsigned* b) {
    asm volatile("mma.sync.aligned.m16n8k16.row.col.f32.f16.f16.f32 "
        "{%0,%1,%2,%3}, {%4,%5,%6,%7}, {%8,%9}, {%0,%1,%2,%3};"
        : "+f"(c[0]), "+f"(c[1]), "+f"(c[2]), "+f"(c[3])
        : "r"(a[0]), "r"(a[1]), "r"(a[2]), "r"(a[3]), "r"(b[0]), "r"(b[1]));
}
__device__ __forceinline__ void ldm_x4(unsigned* r, const void* p) {
    unsigned s = (unsigned)__cvta_generic_to_shared(p);
    asm volatile("ldmatrix.sync.aligned.m8n8.x4.shared.b16 {%0,%1,%2,%3}, [%4];"
        : "=r"(r[0]), "=r"(r[1]), "=r"(r[2]), "=r"(r[3]) : "r"(s));
}
__device__ __forceinline__ void ldm_x4t(unsigned* r, const void* p) {
    unsigned s = (unsigned)__cvta_generic_to_shared(p);
    asm volatile("ldmatrix.sync.aligned.m8n8.x4.trans.shared.b16 {%0,%1,%2,%3}, [%4];"
        : "=r"(r[0]), "=r"(r[1]), "=r"(r[2]), "=r"(r[3]) : "r"(s));
}
__device__ __forceinline__ void cp16(void* dst, const void* src) {
    unsigned d = (unsigned)__cvta_generic_to_shared(dst);
    asm volatile("cp.async.cg.shared.global [%0], [%1], 16;" :: "r"(d), "l"(src));
}
__device__ __forceinline__ void cp_commit() {
    asm volatile("cp.async.commit_group;");
}
template<int N> __device__ __forceinline__ void cp_wait() {
    asm volatile("cp.async.wait_group %0;" :: "n"(N));
}
__device__ __forceinline__ void st2o(float* p, float x, float y) {
    *(float2*)p = make_float2(x, y);
}
__device__ __forceinline__ void st2o(__half* p, float x, float y) {
    *(__half2*)p = __floats2half2_rn(x, y);
}
__device__ __forceinline__ unsigned packh2(float a, float b) {
    __half2 h = __floats2half2_rn(a, b);
    return *(unsigned*)&h;
}

// ---------------------------------------------------------------------------
// FP16 tensor-core GEMM: C[M,N] = A[M,K] @ BT[N,K]^T. A,BT half; C float/half.
// 128x128 tile, BK=64, 256 thr = 8 warps (2Mx4N, 64x32 each), 3-stage cp.async.
// ---------------------------------------------------------------------------
#define ASTRH 72
#define STG_H (2 * 128 * ASTRH)       // halves per stage (A + B)
#define GSMEM (3 * STG_H * 2)         // 110592 bytes

template<typename OutT>
__global__ void __launch_bounds__(256, 2) hgemm(const __half* __restrict__ A,
                                                const __half* __restrict__ BT,
                                                OutT* __restrict__ C,
                                                int N, int K) {
    extern __shared__ __half hs[];

    int tid = threadIdx.x, wid = tid >> 5, lane = tid & 31;
    int bm = blockIdx.y * 128, bn = blockIdx.x * 128;
    int wm = (wid >> 2) * 64, wn = (wid & 3) * 32;
    int gr = lane >> 2, tg = lane & 3;

    int a_r = (lane & 7) + ((lane >> 3) & 1) * 8;   // ldmatrix x4 A row map
    int a_c = ((lane >> 4) & 1) * 8;
    int b_r = (lane & 7) + ((lane >> 4) & 1) * 8;   // ldmatrix x4 B (j-pair) map
    int b_c = ((lane >> 3) & 1) * 8;

    int nkb = K >> 6;

    auto issue = [&](int kb, int slot) {
        __half* sA = hs + slot * STG_H;
        __half* sB = sA + 128 * ASTRH;
        int k0 = kb * 64;
        #pragma unroll
        for (int p = 0; p < 4; p++) {
            int idx = tid + p * 256;          // 0..1023
            int row = idx >> 3, c = idx & 7;  // 8 x 16B chunks per 64-half row
            cp16(sA + row * ASTRH + c * 8, A + (size_t)(bm + row) * K + k0 + c * 8);
        }
        #pragma unroll
        for (int p = 0; p < 4; p++) {
            int idx = tid + p * 256;
            int row = idx >> 3, c = idx & 7;
            cp16(sB + row * ASTRH + c * 8, BT + (size_t)(bn + row) * K + k0 + c * 8);
        }
        cp_commit();
    };

    issue(0, 0);
    if (nkb > 1) issue(1, 1);

    float acc[4][4][4];
    #pragma unroll
    for (int i = 0; i < 4; i++)
        #pragma unroll
        for (int j = 0; j < 4; j++)
            #pragma unroll
            for (int t = 0; t < 4; t++) acc[i][j][t] = 0.f;

    int slot = 0;
    for (int kb = 0; kb < nkb; kb++) {
        if (kb + 1 < nkb) cp_wait<1>(); else cp_wait<0>();
        __syncthreads();
        if (kb + 2 < nkb) {
            int ns = slot + 2; if (ns >= 3) ns -= 3;
            issue(kb + 2, ns);
        }

        __half* sA = hs + slot * STG_H;
        __half* sB = sA + 128 * ASTRH;

        #pragma unroll
        for (int ks = 0; ks < 4; ks++) {
            int kk = ks * 16;
            unsigned a[4][4], b[2][4];
            #pragma unroll
            for (int i = 0; i < 4; i++)
                ldm_x4(a[i], sA + (wm + i * 16 + a_r) * ASTRH + kk + a_c);
            #pragma unroll
            for (int j = 0; j < 2; j++)
                ldm_x4(b[j], sB + (wn + j * 16 + b_r) * ASTRH + kk + b_c);
            #pragma unroll
            for (int i = 0; i < 4; i++)
                #pragma unroll
                for (int j = 0; j < 2; j++) {
                    mma16(acc[i][j * 2],     a[i], b[j]);
                    mma16(acc[i][j * 2 + 1], a[i], b[j] + 2);
                }
        }
        slot++; if (slot >= 3) slot = 0;
    }

    #pragma unroll
    for (int i = 0; i < 4; i++) {
        int r0 = bm + wm + i * 16 + gr;
        #pragma unroll
        for (int j = 0; j < 4; j++) {
            int cc = bn + wn + j * 8 + 2 * tg;
            if (cc < N) {
                st2o(C + (size_t)r0 * N + cc, acc[i][j][0], acc[i][j][1]);
                st2o(C + (size_t)(r0 + 8) * N + cc, acc[i][j][2], acc[i][j][3]);
            }
        }
    }
}

// ---------------------------------------------------------------------------
// Prep kernels
// ---------------------------------------------------------------------------
__global__ void f2h_copy(const float* __restrict__ src, __half* __restrict__ dst,
                         int n4) {
    for (int i = blockIdx.x * blockDim.x + threadIdx.x; i < n4; i += gridDim.x * blockDim.x) {
        float4 v = *(const float4*)(src + i * 4);
        __half2* d = (__half2*)(dst + i * 4);
        d[0] = __floats2half2_rn(v.x, v.y);
        d[1] = __floats2half2_rn(v.z, v.w);
    }
}

// transpose + half: src[K,N] fp32 -> dst[Npad,K] half (pad rows zeroed)
__global__ void transpose_h(const float* __restrict__ src, __half* __restrict__ dst,
                            int K, int N, int Npad) {
    __shared__ float t[32][33];
    int kb = blockIdx.x * 32, nb = blockIdx.y * 32;
    int tx = threadIdx.x, ty = threadIdx.y;
    #pragma unroll
    for (int j = 0; j < 4; j++) {
        int k = kb + ty + j * 8, n = nb + tx;
        float v = 0.f;
        if (k < K && n < N) v = src[(size_t)k * N + n];
        t[ty + j * 8][tx] = v;
    }
    __syncthreads();
    #pragma unroll
    for (int j = 0; j < 4; j++) {
        int n = nb + ty + j * 8, k = kb + tx;
        if (n < Npad && k < K) dst[(size_t)n * K + k] = __float2half(t[tx][ty + j * 8]);
    }
}

// cos/sin table: g_cs[s*64 + i] = cos(s*inv_i), [s*64 + 32 + i] = sin
__global__ void cs_table(float* __restrict__ cs) {
    int s = blockIdx.x, i = threadIdx.x;   // 32 threads
    float inv = powf(10000.f, -(float)i / 32.f);
    float sn, c;
    sincosf((float)s * inv, &sn, &c);
    cs[s * ROPE_D + i] = c;
    cs[s * ROPE_D + 32 + i] = sn;
}

// Fused: RMSNorm(kva) -> ckvh  AND  rope+pack q -> qh, k_pe -> kpeh
__global__ void __launch_bounds__(128) norm_rope(const __half* __restrict__ qkva,
                                                 const float* __restrict__ kvs,
                                                 const float* __restrict__ cs,
                                                 __half* __restrict__ ckv,
                                                 __half* __restrict__ qh,
                                                 __half* __restrict__ kpeh) {
    int r = blockIdx.x;
    int s = r % SS;
    int tid = threadIdx.x;
    const __half* rowbase = qkva + (size_t)r * QAW;
    const __half* row = rowbase + 3072;
    const float* csr = cs + s * ROPE_D;

    // --- RMSNorm over 512 cols
    float x[4];
    float ss = 0.f;
    #pragma unroll
    for (int j = 0; j < 4; j++) {
        x[j] = __half2float(row[tid + 128 * j]);
        ss += x[j] * x[j];
    }
    #pragma unroll
    for (int o = 16; o > 0; o >>= 1)
        ss += __shfl_xor_sync(0xffffffffu, ss, o);

    __shared__ float wsum[4];
    if ((tid & 31) == 0) wsum[tid >> 5] = ss;
    __syncthreads();
    float tot = wsum[0] + wsum[1] + wsum[2] + wsum[3];
    float rms = rsqrtf(tot / (float)LORA + 1e-6f);

    __half* orow = ckv + (size_t)r * LORA;
    #pragma unroll
    for (int j = 0; j < 4; j++) {
        int c = tid + 128 * j;
        orow[c] = __float2half(x[j] * rms * kvs[c]);
    }

    // --- q nope: 2048 halves, vectorized (256 chunks of 8)
    __half* qo = qh + (size_t)r * (HH * QHD);
    #pragma unroll
    for (int p = 0; p < 2; p++) {
        int i = tid + p * 128;        // 0..255
        int head = i >> 4, d = (i & 15) * 8;
        int off = head * QHD + d;
        *(uint4*)(qo + off) = *(const uint4*)(rowbase + off);
    }
    // --- q pe: 512 pairs
    #pragma unroll
    for (int p = 0; p < 4; p++) {
        int i = tid + p * 128;
        int head = i >> 5, ii = i & 31;
        float c = csr[ii], sn = csr[ii + 32];
        int off = head * QHD + NOPE + ii;
        float x1 = __half2float(rowbase[off]), x2 = __half2float(rowbase[off + 32]);
        qo[off]      = __float2half(x1 * c - x2 * sn);
        qo[off + 32] = __float2half(x2 * c + x1 * sn);
    }
    // --- k_pe: 32 pairs
    if (tid < 32) {
        float c = csr[tid], sn = csr[tid + 32];
        const __half* kp = rowbase + 3072 + LORA;
        __half* ko = kpeh + (size_t)r * ROPE_D;
        float x1 = __half2float(kp[tid]), x2 = __half2float(kp[tid + 32]);
        ko[tid]      = __float2half(x1 * c - x2 * sn);
        ko[tid + 32] = __float2half(x2 * c + x1 * sn);
    }
}

// ---------------------------------------------------------------------------
// Flash attention (causal), FP16 mma. BM=128, BN=128, 256 thr = 8 warps.
// Q frags in registers; P packed C->A in registers (FA2 trick, no smem S).
// K/V double-buffered via cp.async.
// ---------------------------------------------------------------------------
#define FBM 128
#define FBN 128
#define KSTRH 200
#define VSTRH 136
#define SK_W (FBN * KSTRH)
#define SV_W (FBN * VSTRH)
#define FSMEM ((2*SK_W + 2*SV_W) * 2)

__global__ void __launch_bounds__(256, 1) flash_h(const __half* __restrict__ qh,
                                                  const __half* __restrict__ kvh,
                                                  const __half* __restrict__ kpeh,
                                                  __half* __restrict__ aoh) {
    extern __shared__ __half fh[];
    __half* sK = fh;                    // [2][SK_W]
    __half* sV = fh + 2 * SK_W;         // [2][SV_W]

    int qt = gridDim.x - 1 - blockIdx.x;   // heavy tiles first
    int h = blockIdx.y, b = blockIdx.z;
    int tid = threadIdx.x, wid = tid >> 5, lane = tid & 31;
    int gr = lane >> 2, tg = lane & 3;
    int qbase = qt * FBM;
    int wrow = wid * 16;

    int a_r = (lane & 7) + ((lane >> 3) & 1) * 8;
    int a_c = ((lane >> 4) & 1) * 8;
    int k_r = (lane & 7) + ((lane >> 4) & 1) * 8;  // K x4 j-pair map
    int k_c = ((lane >> 3) & 1) * 8;
    int v_r = lane & 15;                            // V x4t map
    int v_c = ((lane >> 4) & 1) * 8;

    // --- stage Q through sK[0] overlay (128 x 200 halves = SK_W)
    __half* sQ = fh;
    #pragma unroll
    for (int p = 0; p < 12; p++) {
        int idx = tid + p * 256;           // 0..3071
        int row = idx / 24, c = idx - row * 24;
        int r = b * SS + qbase + row;
        cp16(sQ + row * KSTRH + c * 8,
             qh + (size_t)r * (HH * QHD) + h * QHD + c * 8);
    }
    cp_commit();
    cp_wait<0>();
    __syncthreads();

    unsigned qf[12][4];
    #pragma unroll
    for (int ks = 0; ks < 12; ks++)
        ldm_x4(qf[ks], sQ + (wrow + a_r) * KSTRH + ks * 16 + a_c);
    __syncthreads();   // Q consumed; sK area free

    auto load_kv = [&](int kbase, int stg) {
        __half* K = sK + stg * SK_W;
        __half* V = sV + stg * SV_W;
        #pragma unroll
        for (int p = 0; p < 12; p++) {
            int idx = tid + p * 256;       // 0..3071
            int row = idx / 24, c = idx - row * 24;
            int r = b * SS + kbase + row;
            const __half* src = (c < 16)
                ? kvh  + (size_t)r * (HH * (NOPE + VD)) + h * (NOPE + VD) + c * 8
                : kpeh + (size_t)r * ROPE_D + (c - 16) * 8;
            cp16(K + row * KSTRH + c * 8, src);
        }
        #pragma unroll
        for (int p = 0; p < 8; p++) {
            int idx = tid + p * 256;       // 0..2047
            int row = idx >> 4, c = idx & 15;
            int r = b * SS + kbase + row;
            cp16(V + row * VSTRH + c * 8,
                 kvh + (size_t)r * (HH * (NOPE + VD)) + h * (NOPE + VD) + NOPE + c * 8);
        }
        cp_commit();
    };

    float o[16][4];
    #pragma unroll
    for (int n = 0; n < 16; n++)
        #pragma unroll
        for (int t = 0; t < 4; t++) o[n][t] = 0.f;
    float m0 = -1e30f, m1 = -1e30f, l0 = 0.f, l1 = 0.f;
    const float scale = 0.07216878364870323f;  // 192^-0.5

    int ktmax = qt + 1;
    load_kv(0, 0);

    for (int kt = 0; kt < ktmax; kt++) {
        int kbase = kt * FBN;
        int stg = kt & 1;
        cp_wait<0>();
        __syncthreads();
        if (kt + 1 < ktmax) load_kv(kbase + FBN, stg ^ 1);

        __half* K = sK + stg * SK_W;
        __half* V = sV + stg * SV_W;

        // ---- scores: S = Q K^T (16 rows x 128 cols per warp) ----
        float sacc[16][4];
        #pragma unroll
        for (int j = 0; j < 16; j++)
            #pragma unroll
            for (int t = 0; t < 4; t++) sacc[j][t] = 0.f;

        #pragma unroll
        for (int ks = 0; ks < 12; ks++) {
            int kk = ks * 16;
            #pragma unroll
            for (int j = 0; j < 16; j += 2) {
                unsigned bb[4];
                ldm_x4(bb, K + (j * 8 + k_r) * KSTRH + kk + k_c);
                mma16(sacc[j],     qf[ks], bb);
                mma16(sacc[j + 1], qf[ks], bb + 2);
            }
        }

        // ---- scale + (diag-only) causal mask + online softmax ----
        int qr0 = qbase + wrow + gr;
        int qr1 = qr0 + 8;
        float mx0 = -1e30f, mx1 = -1e30f;
        if (kt < qt) {
            #pragma unroll
            for (int j = 0; j < 16; j++) {
                sacc[j][0] *= scale; sacc[j][1] *= scale;
                sacc[j][2] *= scale; sacc[j][3] *= scale;
                mx0 = fmaxf(mx0, fmaxf(sacc[j][0], sacc[j][1]));
                mx1 = fmaxf(mx1, fmaxf(sacc[j][2], sacc[j][3]));
            }
        } else {
            #pragma unroll
            for (int j = 0; j < 16; j++) {
                int c0 = kbase + j * 8 + 2 * tg;
                sacc[j][0] = (c0     <= qr0) ? sacc[j][0] * scale : -1e30f;
                sacc[j][1] = (c0 + 1 <= qr0) ? sacc[j][1] * scale : -1e30f;
                sacc[j][2] = (c0     <= qr1) ? sacc[j][2] * scale : -1e30f;
                sacc[j][3] = (c0 + 1 <= qr1) ? sacc[j][3] * scale : -1e30f;
                mx0 = fmaxf(mx0, fmaxf(sacc[j][0], sacc[j][1]));
                mx1 = fmaxf(mx1, fmaxf(sacc[j][2], sacc[j][3]));
            }
        }
        mx0 = fmaxf(mx0, __shfl_xor_sync(0xffffffffu, mx0, 1));
        mx0 = fmaxf(mx0, __shfl_xor_sync(0xffffffffu, mx0, 2));
        mx1 = fmaxf(mx1, __shfl_xor_sync(0xffffffffu, mx1, 1));
        mx1 = fmaxf(mx1, __shfl_xor_sync(0xffffffffu, mx1, 2));

        float mn0 = fmaxf(m0, mx0), mn1 = fmaxf(m1, mx1);
        float f0 = __expf(m0 - mn0), f1 = __expf(m1 - mn1);
        m0 = mn0; m1 = mn1;

        // exp + pack P into A-fragments (C->A register layout identity)
        unsigned pa[8][4];
        float s0 = 0.f, s1 = 0.f;
        #pragma unroll
        for (int j2 = 0; j2 < 8; j2++) {
            float p00 = __expf(sacc[2*j2][0]   - mn0);
            float p01 = __expf(sacc[2*j2][1]   - mn0);
            float p02 = __expf(sacc[2*j2][2]   - mn1);
            float p03 = __expf(sacc[2*j2][3]   - mn1);
            float p10 = __expf(sacc[2*j2+1][0] - mn0);
            float p11 = __expf(sacc[2*j2+1][1] - mn0);
            float p12 = __expf(sacc[2*j2+1][2] - mn1);
            float p13 = __expf(sacc[2*j2+1][3] - mn1);
            s0 += p00 + p01 + p10 + p11;
            s1 += p02 + p03 + p12 + p13;
            pa[j2][0] = packh2(p00, p01);   // row gr,   cols [16j2, 16j2+8)
            pa[j2][1] = packh2(p02, p03);   // row gr+8, cols [16j2, 16j2+8)
            pa[j2][2] = packh2(p10, p11);   // row gr,   cols [16j2+8, ...)
            pa[j2][3] = packh2(p12, p13);   // row gr+8
        }
        s0 += __shfl_xor_sync(0xffffffffu, s0, 1);
        s0 += __shfl_xor_sync(0xffffffffu, s0, 2);
        s1 += __shfl_xor_sync(0xffffffffu, s1, 1);
        s1 += __shfl_xor_sync(0xffffffffu, s1, 2);
        l0 = l0 * f0 + s0;
        l1 = l1 * f1 + s1;

        #pragma unroll
        for (int n = 0; n < 16; n++) {
            o[n][0] *= f0; o[n][1] *= f0; o[n][2] *= f1; o[n][3] *= f1;
        }

        // ---- PV: O += P V (16 rows x 128 cols per warp), P from registers ----
        #pragma unroll
        for (int ks = 0; ks < 8; ks++) {
            int kk = ks * 16;
            #pragma unroll
            for (int n = 0; n < 16; n += 2) {
                unsigned bb[4];
                ldm_x4t(bb, V + (kk + v_r) * VSTRH + n * 8 + v_c);
                mma16(o[n],     pa[ks], bb);
                mma16(o[n + 1], pa[ks], bb + 2);
            }
        }
    }

    // epilogue -> half
    float inv0 = 1.f / l0, inv1 = 1.f / l1;
    size_t r0 = (size_t)(b * SS + qbase + wrow + gr) * (HH * VD);
    size_t r1 = r0 + 8 * (HH * VD);
    #pragma unroll
    for (int n = 0; n < 16; n++) {
        int cc = h * VD + n * 8 + 2 * tg;
        *(__half2*)(aoh + r0 + cc) = __floats2half2_rn(o[n][0] * inv0, o[n][1] * inv0);
        *(__half2*)(aoh + r1 + cc) = __floats2half2_rn(o[n][2] * inv1, o[n][3] * inv1);
    }
}

// ---------------------------------------------------------------------------
extern "C" void kernel_launch(void* const* d_in, const int* in_sizes, int n_in,
                              void* d_out, int out_size) {
    const float* x     = (const float*)d_in[0];
    const float* wq    = (const float*)d_in[1];
    const float* wkv_a = (const float*)d_in[2];
    const float* wkv_b = (const float*)d_in[3];
    const float* wo    = (const float*)d_in[4];
    const float* kvs   = (const float*)d_in[5];
    float* out = (float*)d_out;

    float *cs;
    __half *qkvah, *qh, *kpeh, *ckvh, *kvh, *aoh, *xh, *wqaT, *wkvbT, *woT;
    cudaGetSymbolAddress((void**)&qkvah, g_qkvah);
    cudaGetSymbolAddress((void**)&cs,    g_cs);
    cudaGetSymbolAddress((void**)&qh,    g_qh);
    cudaGetSymbolAddress((void**)&kpeh,  g_kpeh);
    cudaGetSymbolAddress((void**)&ckvh,  g_ckvh);
    cudaGetSymbolAddress((void**)&kvh,   g_kvh);
    cudaGetSymbolAddress((void**)&aoh,   g_aoh);
    cudaGetSymbolAddress((void**)&xh,    g_xh);
    cudaGetSymbolAddress((void**)&wqaT,  g_wqaT);
    cudaGetSymbolAddress((void**)&wkvbT, g_wkvbT);
    cudaGetSymbolAddress((void**)&woT,   g_woT);

    static bool attr_done = false;
    if (!attr_done) {
        cudaFuncSetAttribute(flash_h,
                             cudaFuncAttributeMaxDynamicSharedMemorySize, (int)FSMEM);
        cudaFuncSetAttribute(hgemm<float>,
                             cudaFuncAttributeMaxDynamicSharedMemorySize, (int)GSMEM);
        cudaFuncSetAttribute(hgemm<__half>,
                             cudaFuncAttributeMaxDynamicSharedMemorySize, (int)GSMEM);
        attr_done = true;
    }

    // prep
    f2h_copy<<<1024, 256>>>(x, xh, RWS * EE / 4);
    cs_table<<<SS, 32>>>(cs);
    transpose_h<<<dim3(64, 96),  dim3(32, 8)>>>(wq,    wqaT,               2048, 3072, 3072);
    transpose_h<<<dim3(64, 20),  dim3(32, 8)>>>(wkv_a, wqaT + (size_t)3072 * 2048, 2048, 576, 640);
    transpose_h<<<dim3(16, 128), dim3(32, 8)>>>(wkv_b, wkvbT, 512,  4096, 4096);
    transpose_h<<<dim3(64, 64),  dim3(32, 8)>>>(wo,    woT,   2048, 2048, 2048);

    // qkva = x @ [wq | wkv_a] : [4096, 3712] half
    hgemm<__half><<<dim3(QAW / 128, 32), 256, GSMEM>>>(xh, wqaT, qkvah, QAW, 2048);
    // fused rmsnorm + rope/pack
    norm_rope<<<RWS, 128>>>(qkvah, kvs, cs, ckvh, qh, kpeh);
    // kvh = ckv @ wkv_b : [4096, 4096] half
    hgemm<__half><<<dim3(32, 32), 256, GSMEM>>>(ckvh, wkvbT, kvh, 4096, 512);
    // attention -> aoh : [4096, 2048] half
    flash_h<<<dim3(SS / FBM, HH, BB), 256, FSMEM>>>(qh, kvh, kpeh, aoh);
    // out = ao @ wo : [4096, 2048] fp32
    hgemm<float><<<dim3(16, 32), 256, GSMEM>>>(aoh, woT, out, 2048, 2048);
}

// round 11
// speedup vs baseline: 12.9457x; 1.0105x over previous
#include <cuda_runtime.h>
#include <cuda_fp16.h>
#include <math.h>

// Problem constants
#define BB 2
#define SS 2048
#define EE 2048
#define HH 16
#define NOPE 128
#define ROPE_D 64
#define QHD 192          // NOPE + ROPE
#define LORA 512
#define VD 128
#define RWS (BB*SS)      // 4096 rows
#define QAW 3712         // fused q(3072) + kva(576->640 pad) width

// Scratch (device globals; no allocation allowed)
__device__ __half g_qkvah[(size_t)RWS * QAW];          // fused x@[wq|wkv_a], half (q roped in-place)
__device__ __half g_kpeh[(size_t)RWS * ROPE_D];        // roped k_pe, half
__device__ __half g_ckvh[(size_t)RWS * LORA];
__device__ __half g_kvh[(size_t)RWS * (HH * (NOPE + VD))];
__device__ __half g_aoh[(size_t)RWS * (HH * VD)];
__device__ __half g_xh[(size_t)RWS * EE];
__device__ __half g_wqaT[(size_t)QAW * 2048];          // [wq^T ; wkv_a^T(pad)]
__device__ __half g_wkvbT[(size_t)4096 * 512];
__device__ __half g_woT[(size_t)2048 * 2048];
__device__ float  g_cs[SS * ROPE_D];                   // cos[0..31], sin[32..63]

// ---------------- helpers ----------------
__device__ __forceinline__ void mma16(float* c, const unsigned* a, const unsigned* b) {
    asm volatile("mma.sync.aligned.m16n8k16.row.col.f32.f16.f16.f32 "
        "{%0,%1,%2,%3}, {%4,%5,%6,%7}, {%8,%9}, {%0,%1,%2,%3};"
        : "+f"(c[0]), "+f"(c[1]), "+f"(c[2]), "+f"(c[3])
        : "r"(a[0]), "r"(a[1]), "r"(a[2]), "r"(a[3]), "r"(b[0]), "r"(b[1]));
}
__device__ __forceinline__ void ldm_x4(unsigned* r, const void* p) {
    unsigned s = (unsigned)__cvta_generic_to_shared(p);
    asm volatile("ldmatrix.sync.aligned.m8n8.x4.shared.b16 {%0,%1,%2,%3}, [%4];"
        : "=r"(r[0]), "=r"(r[1]), "=r"(r[2]), "=r"(r[3]) : "r"(s));
}
__device__ __forceinline__ void ldm_x4t(unsigned* r, const void* p) {
    unsigned s = (unsigned)__cvta_generic_to_shared(p);
    asm volatile("ldmatrix.sync.aligned.m8n8.x4.trans.shared.b16 {%0,%1,%2,%3}, [%4];"
        : "=r"(r[0]), "=r"(r[1]), "=r"(r[2]), "=r"(r[3]) : "r"(s));
}
__device__ __forceinline__ void cp16(void* dst, const void* src) {
    unsigned d = (unsigned)__cvta_generic_to_shared(dst);
    asm volatile("cp.async.cg.shared.global [%0], [%1], 16;" :: "r"(d), "l"(src));
}
__device__ __forceinline__ void cp_commit() {
    asm volatile("cp.async.commit_group;");
}
template<int N> __device__ __forceinline__ void cp_wait() {
    asm volatile("cp.async.wait_group %0;" :: "n"(N));
}
__device__ __forceinline__ void st2o(float* p, float x, float y) {
    *(float2*)p = make_float2(x, y);
}
__device__ __forceinline__ void st2o(__half* p, float x, float y) {
    *(__half2*)p = __floats2half2_rn(x, y);
}
__device__ __forceinline__ unsigned packh2(float a, float b) {
    __half2 h = __floats2half2_rn(a, b);
    return *(unsigned*)&h;
}

// ---------------------------------------------------------------------------
// FP16 tensor-core GEMM: C[M,N] = A[M,K] @ BT[N,K]^T. A,BT half; C float/half.
// 128x128 tile, BK=64, 256 thr = 8 warps (2Mx4N, 64x32 each), 3-stage cp.async.
// ---------------------------------------------------------------------------
#define ASTRH 72
#define STG_H (2 * 128 * ASTRH)       // halves per stage (A + B)
#define GSMEM (3 * STG_H * 2)         // 110592 bytes

template<typename OutT>
__global__ void __launch_bounds__(256, 2) hgemm(const __half* __restrict__ A,
                                                const __half* __restrict__ BT,
                                                OutT* __restrict__ C,
                                                int N, int K) {
    extern __shared__ __half hs[];

    int tid = threadIdx.x, wid = tid >> 5, lane = tid & 31;
    int bm = blockIdx.y * 128, bn = blockIdx.x * 128;
    int wm = (wid >> 2) * 64, wn = (wid & 3) * 32;
    int gr = lane >> 2, tg = lane & 3;

    int a_r = (lane & 7) + ((lane >> 3) & 1) * 8;   // ldmatrix x4 A row map
    int a_c = ((lane >> 4) & 1) * 8;
    int b_r = (lane & 7) + ((lane >> 4) & 1) * 8;   // ldmatrix x4 B (j-pair) map
    int b_c = ((lane >> 3) & 1) * 8;

    int nkb = K >> 6;

    auto issue = [&](int kb, int slot) {
        __half* sA = hs + slot * STG_H;
        __half* sB = sA + 128 * ASTRH;
        int k0 = kb * 64;
        #pragma unroll
        for (int p = 0; p < 4; p++) {
            int idx = tid + p * 256;          // 0..1023
            int row = idx >> 3, c = idx & 7;  // 8 x 16B chunks per 64-half row
            cp16(sA + row * ASTRH + c * 8, A + (size_t)(bm + row) * K + k0 + c * 8);
        }
        #pragma unroll
        for (int p = 0; p < 4; p++) {
            int idx = tid + p * 256;
            int row = idx >> 3, c = idx & 7;
            cp16(sB + row * ASTRH + c * 8, BT + (size_t)(bn + row) * K + k0 + c * 8);
        }
        cp_commit();
    };

    issue(0, 0);
    if (nkb > 1) issue(1, 1);

    float acc[4][4][4];
    #pragma unroll
    for (int i = 0; i < 4; i++)
        #pragma unroll
        for (int j = 0; j < 4; j++)
            #pragma unroll
            for (int t = 0; t < 4; t++) acc[i][j][t] = 0.f;

    int slot = 0;
    for (int kb = 0; kb < nkb; kb++) {
        if (kb + 1 < nkb) cp_wait<1>(); else cp_wait<0>();
        __syncthreads();
        if (kb + 2 < nkb) {
            int ns = slot + 2; if (ns >= 3) ns -= 3;
            issue(kb + 2, ns);
        }

        __half* sA = hs + slot * STG_H;
        __half* sB = sA + 128 * ASTRH;

        #pragma unroll
        for (int ks = 0; ks < 4; ks++) {
            int kk = ks * 16;
            unsigned a[4][4], b[2][4];
            #pragma unroll
            for (int i = 0; i < 4; i++)
                ldm_x4(a[i], sA + (wm + i * 16 + a_r) * ASTRH + kk + a_c);
            #pragma unroll
            for (int j = 0; j < 2; j++)
                ldm_x4(b[j], sB + (wn + j * 16 + b_r) * ASTRH + kk + b_c);
            #pragma unroll
            for (int i = 0; i < 4; i++)
                #pragma unroll
                for (int j = 0; j < 2; j++) {
                    mma16(acc[i][j * 2],     a[i], b[j]);
                    mma16(acc[i][j * 2 + 1], a[i], b[j] + 2);
                }
        }
        slot++; if (slot >= 3) slot = 0;
    }

    #pragma unroll
    for (int i = 0; i < 4; i++) {
        int r0 = bm + wm + i * 16 + gr;
        #pragma unroll
        for (int j = 0; j < 4; j++) {
            int cc = bn + wn + j * 8 + 2 * tg;
            if (cc < N) {
                st2o(C + (size_t)r0 * N + cc, acc[i][j][0], acc[i][j][1]);
                st2o(C + (size_t)(r0 + 8) * N + cc, acc[i][j][2], acc[i][j][3]);
            }
        }
    }
}

// ---------------------------------------------------------------------------
// Prep kernels
// ---------------------------------------------------------------------------
__global__ void f2h_copy(const float* __restrict__ src, __half* __restrict__ dst,
                         int n4) {
    for (int i = blockIdx.x * blockDim.x + threadIdx.x; i < n4; i += gridDim.x * blockDim.x) {
        float4 v = *(const float4*)(src + i * 4);
        __half2* d = (__half2*)(dst + i * 4);
        d[0] = __floats2half2_rn(v.x, v.y);
        d[1] = __floats2half2_rn(v.z, v.w);
    }
}

// transpose + half: src[K,N] fp32 -> dst[Npad,K] half (pad rows zeroed)
__global__ void transpose_h(const float* __restrict__ src, __half* __restrict__ dst,
                            int K, int N, int Npad) {
    __shared__ float t[32][33];
    int kb = blockIdx.x * 32, nb = blockIdx.y * 32;
    int tx = threadIdx.x, ty = threadIdx.y;
    #pragma unroll
    for (int j = 0; j < 4; j++) {
        int k = kb + ty + j * 8, n = nb + tx;
        float v = 0.f;
        if (k < K && n < N) v = src[(size_t)k * N + n];
        t[ty + j * 8][tx] = v;
    }
    __syncthreads();
    #pragma unroll
    for (int j = 0; j < 4; j++) {
        int n = nb + ty + j * 8, k = kb + tx;
        if (n < Npad && k < K) dst[(size_t)n * K + k] = __float2half(t[tx][ty + j * 8]);
    }
}

// cos/sin table: g_cs[s*64 + i] = cos(s*inv_i), [s*64 + 32 + i] = sin
__global__ void cs_table(float* __restrict__ cs) {
    int s = blockIdx.x, i = threadIdx.x;   // 32 threads
    float inv = powf(10000.f, -(float)i / 32.f);
    float sn, c;
    sincosf((float)s * inv, &sn, &c);
    cs[s * ROPE_D + i] = c;
    cs[s * ROPE_D + 32 + i] = sn;
}

// Fused: RMSNorm(kva) -> ckvh; rope q_pe IN-PLACE in qkva; rope k_pe -> kpeh
__global__ void __launch_bounds__(128) norm_rope(__half* __restrict__ qkva,
                                                 const float* __restrict__ kvs,
                                                 const float* __restrict__ cs,
                                                 __half* __restrict__ ckv,
                                                 __half* __restrict__ kpeh) {
    int r = blockIdx.x;
    int s = r % SS;
    int tid = threadIdx.x;
    __half* rowbase = qkva + (size_t)r * QAW;
    const __half* row = rowbase + 3072;
    const float* csr = cs + s * ROPE_D;

    // --- RMSNorm over 512 cols
    float x[4];
    float ss = 0.f;
    #pragma unroll
    for (int j = 0; j < 4; j++) {
        x[j] = __half2float(row[tid + 128 * j]);
        ss += x[j] * x[j];
    }
    #pragma unroll
    for (int o = 16; o > 0; o >>= 1)
        ss += __shfl_xor_sync(0xffffffffu, ss, o);

    __shared__ float wsum[4];
    if ((tid & 31) == 0) wsum[tid >> 5] = ss;
    __syncthreads();
    float tot = wsum[0] + wsum[1] + wsum[2] + wsum[3];
    float rms = rsqrtf(tot / (float)LORA + 1e-6f);

    __half* orow = ckv + (size_t)r * LORA;
    #pragma unroll
    for (int j = 0; j < 4; j++) {
        int c = tid + 128 * j;
        orow[c] = __float2half(x[j] * rms * kvs[c]);
    }

    // --- q pe: 512 pairs, roped in place
    #pragma unroll
    for (int p = 0; p < 4; p++) {
        int i = tid + p * 128;
        int head = i >> 5, ii = i & 31;
        float c = csr[ii], sn = csr[ii + 32];
        int off = head * QHD + NOPE + ii;
        float x1 = __half2float(rowbase[off]), x2 = __half2float(rowbase[off + 32]);
        rowbase[off]      = __float2half(x1 * c - x2 * sn);
        rowbase[off + 32] = __float2half(x2 * c + x1 * sn);
    }
    // --- k_pe: 32 pairs
    if (tid < 32) {
        float c = csr[tid], sn = csr[tid + 32];
        const __half* kp = rowbase + 3072 + LORA;
        __half* ko = kpeh + (size_t)r * ROPE_D;
        float x1 = __half2float(kp[tid]), x2 = __half2float(kp[tid + 32]);
        ko[tid]      = __float2half(x1 * c - x2 * sn);
        ko[tid + 32] = __float2half(x2 * c + x1 * sn);
    }
}

// ---------------------------------------------------------------------------
// Flash attention (causal), FP16 mma. BM=128, BN=128, 256 thr = 8 warps.
// Q straight from qkva (roped in-place); P packed C->A in regs (FA2);
// K/V double-buffered via cp.async; exp2-domain softmax.
// ---------------------------------------------------------------------------
#define FBM 128
#define FBN 128
#define KSTRH 200
#define VSTRH 136
#define SK_W (FBN * KSTRH)
#define SV_W (FBN * VSTRH)
#define FSMEM ((2*SK_W + 2*SV_W) * 2)

__global__ void __launch_bounds__(256, 1) flash_h(const __half* __restrict__ qkva,
                                                  const __half* __restrict__ kvh,
                                                  const __half* __restrict__ kpeh,
                                                  __half* __restrict__ aoh) {
    extern __shared__ __half fh[];
    __half* sK = fh;                    // [2][SK_W]
    __half* sV = fh + 2 * SK_W;         // [2][SV_W]

    int qt = gridDim.x - 1 - blockIdx.x;   // heavy tiles first
    int h = blockIdx.y, b = blockIdx.z;
    int tid = threadIdx.x, wid = tid >> 5, lane = tid & 31;
    int gr = lane >> 2, tg = lane & 3;
    int qbase = qt * FBM;
    int wrow = wid * 16;

    int a_r = (lane & 7) + ((lane >> 3) & 1) * 8;
    int a_c = ((lane >> 4) & 1) * 8;
    int k_r = (lane & 7) + ((lane >> 4) & 1) * 8;  // K x4 j-pair map
    int k_c = ((lane >> 3) & 1) * 8;
    int v_r = lane & 15;                            // V x4t map
    int v_c = ((lane >> 4) & 1) * 8;

    // --- stage Q through sK[0] overlay (128 x 200 halves = SK_W)
    __half* sQ = fh;
    #pragma unroll
    for (int p = 0; p < 12; p++) {
        int idx = tid + p * 256;           // 0..3071
        int row = idx / 24, c = idx - row * 24;
        int r = b * SS + qbase + row;
        cp16(sQ + row * KSTRH + c * 8,
             qkva + (size_t)r * QAW + h * QHD + c * 8);
    }
    cp_commit();
    cp_wait<0>();
    __syncthreads();

    unsigned qf[12][4];
    #pragma unroll
    for (int ks = 0; ks < 12; ks++)
        ldm_x4(qf[ks], sQ + (wrow + a_r) * KSTRH + ks * 16 + a_c);
    __syncthreads();   // Q consumed; sK area free

    auto load_kv = [&](int kbase, int stg) {
        __half* K = sK + stg * SK_W;
        __half* V = sV + stg * SV_W;
        #pragma unroll
        for (int p = 0; p < 12; p++) {
            int idx = tid + p * 256;       // 0..3071
            int row = idx / 24, c = idx - row * 24;
            int r = b * SS + kbase + row;
            const __half* src = (c < 16)
                ? kvh  + (size_t)r * (HH * (NOPE + VD)) + h * (NOPE + VD) + c * 8
                : kpeh + (size_t)r * ROPE_D + (c - 16) * 8;
            cp16(K + row * KSTRH + c * 8, src);
        }
        #pragma unroll
        for (int p = 0; p < 8; p++) {
            int idx = tid + p * 256;       // 0..2047
            int row = idx >> 4, c = idx & 15;
            int r = b * SS + kbase + row;
            cp16(V + row * VSTRH + c * 8,
                 kvh + (size_t)r * (HH * (NOPE + VD)) + h * (NOPE + VD) + NOPE + c * 8);
        }
        cp_commit();
    };

    float o[16][4];
    #pragma unroll
    for (int n = 0; n < 16; n++)
        #pragma unroll
        for (int t = 0; t < 4; t++) o[n][t] = 0.f;
    float m0 = -1e30f, m1 = -1e30f, l0 = 0.f, l1 = 0.f;
    // scale * log2(e): softmax in exp2 domain
    const float scale = 0.07216878364870323f * 1.4426950408889634f;

    int ktmax = qt + 1;
    load_kv(0, 0);

    for (int kt = 0; kt < ktmax; kt++) {
        int kbase = kt * FBN;
        int stg = kt & 1;
        cp_wait<0>();
        __syncthreads();
        if (kt + 1 < ktmax) load_kv(kbase + FBN, stg ^ 1);

        __half* K = sK + stg * SK_W;
        __half* V = sV + stg * SV_W;

        // ---- scores: S = Q K^T (16 rows x 128 cols per warp) ----
        float sacc[16][4];
        #pragma unroll
        for (int j = 0; j < 16; j++)
            #pragma unroll
            for (int t = 0; t < 4; t++) sacc[j][t] = 0.f;

        #pragma unroll
        for (int ks = 0; ks < 12; ks++) {
            int kk = ks * 16;
            #pragma unroll
            for (int j = 0; j < 16; j += 2) {
                unsigned bb[4];
                ldm_x4(bb, K + (j * 8 + k_r) * KSTRH + kk + k_c);
                mma16(sacc[j],     qf[ks], bb);
                mma16(sacc[j + 1], qf[ks], bb + 2);
            }
        }

        // ---- scale + (diag-only) causal mask + online softmax (exp2 domain) ----
        int qr0 = qbase + wrow + gr;
        int qr1 = qr0 + 8;
        float mx0 = -1e30f, mx1 = -1e30f;
        if (kt < qt) {
            #pragma unroll
            for (int j = 0; j < 16; j++) {
                sacc[j][0] *= scale; sacc[j][1] *= scale;
                sacc[j][2] *= scale; sacc[j][3] *= scale;
                mx0 = fmaxf(mx0, fmaxf(sacc[j][0], sacc[j][1]));
                mx1 = fmaxf(mx1, fmaxf(sacc[j][2], sacc[j][3]));
            }
        } else {
            #pragma unroll
            for (int j = 0; j < 16; j++) {
                int c0 = kbase + j * 8 + 2 * tg;
                sacc[j][0] = (c0     <= qr0) ? sacc[j][0] * scale : -1e30f;
                sacc[j][1] = (c0 + 1 <= qr0) ? sacc[j][1] * scale : -1e30f;
                sacc[j][2] = (c0     <= qr1) ? sacc[j][2] * scale : -1e30f;
                sacc[j][3] = (c0 + 1 <= qr1) ? sacc[j][3] * scale : -1e30f;
                mx0 = fmaxf(mx0, fmaxf(sacc[j][0], sacc[j][1]));
                mx1 = fmaxf(mx1, fmaxf(sacc[j][2], sacc[j][3]));
            }
        }
        mx0 = fmaxf(mx0, __shfl_xor_sync(0xffffffffu, mx0, 1));
        mx0 = fmaxf(mx0, __shfl_xor_sync(0xffffffffu, mx0, 2));
        mx1 = fmaxf(mx1, __shfl_xor_sync(0xffffffffu, mx1, 1));
        mx1 = fmaxf(mx1, __shfl_xor_sync(0xffffffffu, mx1, 2));

        float mn0 = fmaxf(m0, mx0), mn1 = fmaxf(m1, mx1);
        float f0 = exp2f(m0 - mn0), f1 = exp2f(m1 - mn1);
        m0 = mn0; m1 = mn1;

        // exp2 + pack P into A-fragments (C->A register layout identity)
        unsigned pa[8][4];
        float s0 = 0.f, s1 = 0.f;
        #pragma unroll
        for (int j2 = 0; j2 < 8; j2++) {
            float p00 = exp2f(sacc[2*j2][0]   - mn0);
            float p01 = exp2f(sacc[2*j2][1]   - mn0);
            float p02 = exp2f(sacc[2*j2][2]   - mn1);
            float p03 = exp2f(sacc[2*j2][3]   - mn1);
            float p10 = exp2f(sacc[2*j2+1][0] - mn0);
            float p11 = exp2f(sacc[2*j2+1][1] - mn0);
            float p12 = exp2f(sacc[2*j2+1][2] - mn1);
            float p13 = exp2f(sacc[2*j2+1][3] - mn1);
            s0 += p00 + p01 + p10 + p11;
            s1 += p02 + p03 + p12 + p13;
            pa[j2][0] = packh2(p00, p01);
            pa[j2][1] = packh2(p02, p03);
            pa[j2][2] = packh2(p10, p11);
            pa[j2][3] = packh2(p12, p13);
        }
        s0 += __shfl_xor_sync(0xffffffffu, s0, 1);
        s0 += __shfl_xor_sync(0xffffffffu, s0, 2);
        s1 += __shfl_xor_sync(0xffffffffu, s1, 1);
        s1 += __shfl_xor_sync(0xffffffffu, s1, 2);
        l0 = l0 * f0 + s0;
        l1 = l1 * f1 + s1;

        #pragma unroll
        for (int n = 0; n < 16; n++) {
            o[n][0] *= f0; o[n][1] *= f0; o[n][2] *= f1; o[n][3] *= f1;
        }

        // ---- PV: O += P V (16 rows x 128 cols per warp), P from registers ----
        #pragma unroll
        for (int ks = 0; ks < 8; ks++) {
            int kk = ks * 16;
            #pragma unroll
            for (int n = 0; n < 16; n += 2) {
                unsigned bb[4];
                ldm_x4t(bb, V + (kk + v_r) * VSTRH + n * 8 + v_c);
                mma16(o[n],     pa[ks], bb);
                mma16(o[n + 1], pa[ks], bb + 2);
            }
        }
    }

    // epilogue -> half
    float inv0 = 1.f / l0, inv1 = 1.f / l1;
    size_t r0 = (size_t)(b * SS + qbase + wrow + gr) * (HH * VD);
    size_t r1 = r0 + 8 * (HH * VD);
    #pragma unroll
    for (int n = 0; n < 16; n++) {
        int cc = h * VD + n * 8 + 2 * tg;
        *(__half2*)(aoh + r0 + cc) = __floats2half2_rn(o[n][0] * inv0, o[n][1] * inv0);
        *(__half2*)(aoh + r1 + cc) = __floats2half2_rn(o[n][2] * inv1, o[n][3] * inv1);
    }
}

// ---------------------------------------------------------------------------
extern "C" void kernel_launch(void* const* d_in, const int* in_sizes, int n_in,
                              void* d_out, int out_size) {
    const float* x     = (const float*)d_in[0];
    const float* wq    = (const float*)d_in[1];
    const float* wkv_a = (const float*)d_in[2];
    const float* wkv_b = (const float*)d_in[3];
    const float* wo    = (const float*)d_in[4];
    const float* kvs   = (const float*)d_in[5];
    float* out = (float*)d_out;

    float *cs;
    __half *qkvah, *kpeh, *ckvh, *kvh, *aoh, *xh, *wqaT, *wkvbT, *woT;
    cudaGetSymbolAddress((void**)&qkvah, g_qkvah);
    cudaGetSymbolAddress((void**)&cs,    g_cs);
    cudaGetSymbolAddress((void**)&kpeh,  g_kpeh);
    cudaGetSymbolAddress((void**)&ckvh,  g_ckvh);
    cudaGetSymbolAddress((void**)&kvh,   g_kvh);
    cudaGetSymbolAddress((void**)&aoh,   g_aoh);
    cudaGetSymbolAddress((void**)&xh,    g_xh);
    cudaGetSymbolAddress((void**)&wqaT,  g_wqaT);
    cudaGetSymbolAddress((void**)&wkvbT, g_wkvbT);
    cudaGetSymbolAddress((void**)&woT,   g_woT);

    static bool attr_done = false;
    if (!attr_done) {
        cudaFuncSetAttribute(flash_h,
                             cudaFuncAttributeMaxDynamicSharedMemorySize, (int)FSMEM);
        cudaFuncSetAttribute(hgemm<float>,
                             cudaFuncAttributeMaxDynamicSharedMemorySize, (int)GSMEM);
        cudaFuncSetAttribute(hgemm<__half>,
                             cudaFuncAttributeMaxDynamicSharedMemorySize, (int)GSMEM);
        attr_done = true;
    }

    // prep
    f2h_copy<<<1024, 256>>>(x, xh, RWS * EE / 4);
    cs_table<<<SS, 32>>>(cs);
    transpose_h<<<dim3(64, 96),  dim3(32, 8)>>>(wq,    wqaT,               2048, 3072, 3072);
    transpose_h<<<dim3(64, 20),  dim3(32, 8)>>>(wkv_a, wqaT + (size_t)3072 * 2048, 2048, 576, 640);
    transpose_h<<<dim3(16, 128), dim3(32, 8)>>>(wkv_b, wkvbT, 512,  4096, 4096);
    transpose_h<<<dim3(64, 64),  dim3(32, 8)>>>(wo,    woT,   2048, 2048, 2048);

    // qkva = x @ [wq | wkv_a] : [4096, 3712] half
    hgemm<__half><<<dim3(QAW / 128, 32), 256, GSMEM>>>(xh, wqaT, qkvah, QAW, 2048);
    // fused rmsnorm + in-place q rope + k_pe rope
    norm_rope<<<RWS, 128>>>(qkvah, kvs, cs, ckvh, kpeh);
    // kvh = ckv @ wkv_b : [4096, 4096] half
    hgemm<__half><<<dim3(32, 32), 256, GSMEM>>>(ckvh, wkvbT, kvh, 4096, 512);
    // attention -> aoh : [4096, 2048] half
    flash_h<<<dim3(SS / FBM, HH, BB), 256, FSMEM>>>(qkvah, kvh, kpeh, aoh);
    // out = ao @ wo : [4096, 2048] fp32
    hgemm<float><<<dim3(16, 32), 256, GSMEM>>>(aoh, woT, out, 2048, 2048);
}